// round 11
// baseline (speedup 1.0000x reference)
#include <cuda_runtime.h>
#include <cuda_bf16.h>
#include <cstdint>

__device__ float g_l[8 * 256 * 4096];
__device__ float g_t[8 * 128 * 4096];
__device__ float g_lam[8 * 4096 * 256];
__device__ float g_avg[8 * 256];
__device__ float g_mx[8 * 256];
__device__ float g_sca[8 * 256];
__device__ float g_s2m[8 * 4096];
__device__ float g_s2x[8 * 4096];
__device__ float g_satt[8 * 4096];

__device__ __forceinline__ unsigned long long pk2(float a, float b) {
    unsigned long long r;
    asm("mov.b64 %0, {%1, %2};" : "=l"(r) : "f"(a), "f"(b));
    return r;
}
__device__ __forceinline__ void upk2(unsigned long long v, float& a, float& b) {
    asm("mov.b64 {%0, %1}, %2;" : "=f"(a), "=f"(b) : "l"(v));
}
__device__ __forceinline__ void ffma2(unsigned long long& d, unsigned long long a,
                                      unsigned long long b) {
    asm("fma.rn.f32x2 %0, %1, %2, %0;" : "+l"(d) : "l"(a), "l"(b));
}

__device__ __forceinline__ float b2f(unsigned u) {
    return __uint_as_float(u << 16);
}
__device__ __forceinline__ unsigned short f2b(float f) {
    __nv_bfloat16 h = __float2bfloat16(f);
    return *(unsigned short*)&h;
}
__device__ __forceinline__ void ldsm4(unsigned r[4], unsigned addr) {
    asm volatile("ldmatrix.sync.aligned.m8n8.x4.shared.b16 {%0,%1,%2,%3}, [%4];"
                 : "=r"(r[0]), "=r"(r[1]), "=r"(r[2]), "=r"(r[3])
                 : "r"(addr));
}
__device__ __forceinline__ void mma16816(float d[4], const unsigned a[4],
                                         unsigned b0, unsigned b1) {
    asm volatile(
        "mma.sync.aligned.m16n8k16.row.col.f32.bf16.bf16.f32 "
        "{%0,%1,%2,%3},{%4,%5,%6,%7},{%8,%9},{%0,%1,%2,%3};"
        : "+f"(d[0]), "+f"(d[1]), "+f"(d[2]), "+f"(d[3])
        : "r"(a[0]), "r"(a[1]), "r"(a[2]), "r"(a[3]), "r"(b0), "r"(b1));
}

// ---------------------------------------------------------------------------
// conv3x3 via mma.sync bf16 hi/lo split (implicit GEMM, per-tap shifts).
// CTA: 256 thr, M=128 pixels (2 rows x 64 cols), N=64 co, ci-chunks of 32.
// grid.x = batch*32 rowblocks, grid.y = CO/64.
// ---------------------------------------------------------------------------
#define CILD 40            // halfword stride per (row,col) cell (odd*16B)
#define CWTAP 2560         // 64 co * CILD
#define CONV_IH 0
#define CONV_IL 10880      // 4*68*40
#define CONV_WH 21760
#define CONV_WL 44800      // +9*64*40
#define CONV_SMEM 135680   // 67840 halfwords * 2B

template <int CI, int CO, bool RELU, bool BIAS>
__global__ __launch_bounds__(256, 1) void conv3x3_mma_k(
    const float* __restrict__ in, const float* __restrict__ wt,
    const float* __restrict__ bias, float* __restrict__ out) {
    extern __shared__ __align__(16) unsigned short cs[];
    unsigned short* ih = cs + CONV_IH;
    unsigned short* il = cs + CONV_IL;
    unsigned short* wh = cs + CONV_WH;
    unsigned short* wl = cs + CONV_WL;
    int t = threadIdx.x, w = t >> 5, lane = t & 31;
    int b = blockIdx.x >> 5, rb = blockIdx.x & 31, r0 = rb * 2;
    int coB = blockIdx.y * 64;
    int wmB = (w & 3) * 32;   // warp pixel base
    int wnB = (w >> 2) * 32;  // warp co base

    unsigned ihA = (unsigned)__cvta_generic_to_shared(ih);
    unsigned ilA = (unsigned)__cvta_generic_to_shared(il);
    unsigned whA = (unsigned)__cvta_generic_to_shared(wh);
    unsigned wlA = (unsigned)__cvta_generic_to_shared(wl);

    // zero input tiles (covers halo borders; interior rewritten each chunk)
    for (int i = t; i < 10880; i += 256) ((unsigned*)cs)[i] = 0u;

    float acc[2][16];
#pragma unroll
    for (int mb = 0; mb < 2; ++mb)
#pragma unroll
        for (int i = 0; i < 16; ++i) acc[mb][i] = 0.f;

#pragma unroll 1
    for (int cc = 0; cc < CI / 32; ++cc) {
        __syncthreads();
        // stage input chunk: [4 rows][cols 1..64][32 ci], OOB rows -> 0
#pragma unroll 1
        for (int it = 0; it < 32; ++it) {
            int i = t + it * 256;
            int col = i & 63, row = (i >> 6) & 3, ci = i >> 8;
            int imgrow = r0 - 1 + row;
            float v = 0.f;
            if ((unsigned)imgrow < 64u)
                v = in[((size_t)b * CI + cc * 32 + ci) * 4096 + imgrow * 64 + col];
            if (RELU) v = fmaxf(v, 0.f);
            unsigned short h = f2b(v);
            int idx = (row * 68 + col + 1) * CILD + ci;
            ih[idx] = h;
            il[idx] = f2b(v - b2f(h));
        }
        // stage weights chunk: wsh[tap][co][ci]
#pragma unroll 1
        for (int it = 0; it < 72; ++it) {
            int i = t + it * 256;
            int co = i / 288, g = i - co * 288;
            int ci = g / 9, tap = g - ci * 9;
            float v = wt[(size_t)(coB + co) * (CI * 9) + (cc * 32 + ci) * 9 + tap];
            unsigned short h = f2b(v);
            int idx = tap * CWTAP + co * CILD + ci;
            wh[idx] = h;
            wl[idx] = f2b(v - b2f(h));
        }
        __syncthreads();

#pragma unroll 1
        for (int tap = 0; tap < 9; ++tap) {
            int dh = tap / 3, dw = tap - dh * 3;
#pragma unroll
            for (int ks = 0; ks < 2; ++ks) {
                int k0 = ks * 16;
                unsigned ah[2][4], al[2][4], bh[2][4], bl[2][4];
#pragma unroll
                for (int mb = 0; mb < 2; ++mb) {
                    int p = wmB + mb * 16 + (lane & 15);
                    int trow = (p >> 6) + dh;
                    int tcol = (p & 63) + dw;
                    unsigned aoff =
                        (unsigned)((trow * 68 + tcol) * CILD + k0 +
                                   ((lane >> 4) << 3)) * 2;
                    ldsm4(ah[mb], ihA + aoff);
                    ldsm4(al[mb], ilA + aoff);
                }
                int brow = wnB + (lane & 7) + (((lane >> 4) & 1) << 3);
                unsigned bo0 = (unsigned)(tap * CWTAP + brow * CILD + k0 +
                                          (((lane >> 3) & 1) << 3)) * 2;
                unsigned bo1 = bo0 + 16 * CILD * 2;
                ldsm4(bh[0], whA + bo0);
                ldsm4(bh[1], whA + bo1);
                ldsm4(bl[0], wlA + bo0);
                ldsm4(bl[1], wlA + bo1);
#pragma unroll
                for (int mb = 0; mb < 2; ++mb) {
                    mma16816(&acc[mb][0], ah[mb], bh[0][0], bh[0][1]);
                    mma16816(&acc[mb][0], ah[mb], bl[0][0], bl[0][1]);
                    mma16816(&acc[mb][0], al[mb], bh[0][0], bh[0][1]);
                    mma16816(&acc[mb][4], ah[mb], bh[0][2], bh[0][3]);
                    mma16816(&acc[mb][4], ah[mb], bl[0][2], bl[0][3]);
                    mma16816(&acc[mb][4], al[mb], bh[0][2], bh[0][3]);
                    mma16816(&acc[mb][8], ah[mb], bh[1][0], bh[1][1]);
                    mma16816(&acc[mb][8], ah[mb], bl[1][0], bl[1][1]);
                    mma16816(&acc[mb][8], al[mb], bh[1][0], bh[1][1]);
                    mma16816(&acc[mb][12], ah[mb], bh[1][2], bh[1][3]);
                    mma16816(&acc[mb][12], ah[mb], bl[1][2], bl[1][3]);
                    mma16816(&acc[mb][12], al[mb], bh[1][2], bh[1][3]);
                }
            }
        }
    }

    size_t ob = (size_t)b * CO * 4096;
#pragma unroll
    for (int mb = 0; mb < 2; ++mb) {
        int p0 = wmB + mb * 16 + (lane >> 2);
#pragma unroll
        for (int nb = 0; nb < 4; ++nb) {
            int n = coB + wnB + nb * 8 + ((lane & 3) << 1);
            float bs0 = BIAS ? bias[n] : 0.f;
            float bs1 = BIAS ? bias[n + 1] : 0.f;
#pragma unroll
            for (int rr = 0; rr < 2; ++rr) {
                int p = p0 + rr * 8;
                int orow = r0 + (p >> 6), ocol = p & 63;
                out[ob + (size_t)n * 4096 + orow * 64 + ocol] =
                    acc[mb][nb * 4 + rr * 2] + bs0;
                out[ob + (size_t)(n + 1) * 4096 + orow * 64 + ocol] =
                    acc[mb][nb * 4 + rr * 2 + 1] + bs1;
            }
        }
    }
}

// 1x1 conv (relu(t)@w2) + residual add; CI=128, 16 co per block, 2 px/thread
__global__ __launch_bounds__(256) void conv1x1_add_k(const float* __restrict__ tin,
                                                     const float* __restrict__ wt,
                                                     float* __restrict__ lio) {
    __shared__ __align__(16) float wsh[128 * 16];
    int tid = threadIdx.x;
    int p0 = blockIdx.x * 512 + 2 * tid;
    int b = p0 >> 12, hw = p0 & 4095;
    int coBase = blockIdx.y * 16;
    for (int i = tid; i < 2048; i += 256) {
        int o = i >> 7, ci = i & 127;
        wsh[ci * 16 + o] = wt[(size_t)(coBase + o) * 128 + ci];
    }
    __syncthreads();
    unsigned long long acc2[16];
    size_t lb = ((size_t)b * 256 + coBase) * 4096 + hw;
#pragma unroll
    for (int q = 0; q < 8; ++q) {
        float2 v = *(const float2*)&lio[lb + (size_t)(2 * q) * 4096];
        float2 u = *(const float2*)&lio[lb + (size_t)(2 * q + 1) * 4096];
        acc2[2 * q] = pk2(v.x, u.x);
        acc2[2 * q + 1] = pk2(v.y, u.y);
    }
    const float* tb = tin + (size_t)b * 128 * 4096 + hw;
#pragma unroll 1
    for (int ci = 0; ci < 128; ci += 8) {
        float2 v[8];
#pragma unroll
        for (int j = 0; j < 8; ++j) {
            float2 u = *(const float2*)&tb[(size_t)(ci + j) * 4096];
            v[j].x = fmaxf(u.x, 0.f);
            v[j].y = fmaxf(u.y, 0.f);
        }
#pragma unroll
        for (int j = 0; j < 8; ++j) {
            unsigned long long v0 = pk2(v[j].x, v[j].x);
            unsigned long long v1 = pk2(v[j].y, v[j].y);
            const ulonglong2* wp = (const ulonglong2*)&wsh[(ci + j) * 16];
#pragma unroll
            for (int q = 0; q < 4; ++q) {
                ulonglong2 wq = wp[q];
                ffma2(acc2[4 * q], wq.x, v0);
                ffma2(acc2[4 * q + 1], wq.x, v1);
                ffma2(acc2[4 * q + 2], wq.y, v0);
                ffma2(acc2[4 * q + 3], wq.y, v1);
            }
        }
    }
#pragma unroll
    for (int q = 0; q < 8; ++q) {
        float a0, a1, b0_, b1_;
        upk2(acc2[2 * q], a0, b0_);
        upk2(acc2[2 * q + 1], a1, b1_);
        float2 o0 = {a0, a1}, o1 = {b0_, b1_};
        *(float2*)&lio[lb + (size_t)(2 * q) * 4096] = o0;
        *(float2*)&lio[lb + (size_t)(2 * q + 1) * 4096] = o1;
    }
}

__global__ __launch_bounds__(256) void pool_k(const float* __restrict__ l,
                                              float* __restrict__ avg,
                                              float* __restrict__ mx) {
    __shared__ float ss[256], sm[256];
    int bc = blockIdx.x, t = threadIdx.x;
    const float4* p = (const float4*)(l + (size_t)bc * 4096);
    float s = 0.f, m = -3.4e38f;
    for (int i = t; i < 1024; i += 256) {
        float4 v = p[i];
        s += v.x + v.y + v.z + v.w;
        m = fmaxf(m, fmaxf(fmaxf(v.x, v.y), fmaxf(v.z, v.w)));
    }
    ss[t] = s;
    sm[t] = m;
    __syncthreads();
    for (int st = 128; st > 0; st >>= 1) {
        if (t < st) {
            ss[t] += ss[t + st];
            sm[t] = fmaxf(sm[t], sm[t + st]);
        }
        __syncthreads();
    }
    if (t == 0) {
        avg[bc] = ss[0] * (1.f / 4096.f);
        mx[bc] = sm[0];
    }
}

__global__ void camlp_k(const float* __restrict__ avg, const float* __restrict__ mx,
                        const float* __restrict__ w1, const float* __restrict__ w2,
                        float* __restrict__ sca) {
    __shared__ float hsh[128];
    int t = threadIdx.x;
    if (t < 128) {
        int b = t >> 4, j = t & 15;
        float a = 0.f, m = 0.f;
        for (int c = 0; c < 256; ++c) {
            float w = w1[j * 256 + c];
            a += avg[b * 256 + c] * w;
            m += mx[b * 256 + c] * w;
        }
        hsh[b * 16 + j] = fmaxf(a, 0.f) + fmaxf(m, 0.f);
    }
    __syncthreads();
    for (int b = 0; b < 8; ++b) {
        float o = 0.f;
#pragma unroll
        for (int j = 0; j < 16; ++j) o += hsh[b * 16 + j] * w2[t * 16 + j];
        sca[b * 256 + t] = 1.f / (1.f + expf(-o));
    }
}

__global__ __launch_bounds__(256) void chan_k(float* __restrict__ l,
                                              const float* __restrict__ sca,
                                              float* __restrict__ s2m,
                                              float* __restrict__ s2x) {
    int tid = threadIdx.x;
    int p0 = blockIdx.x * 512 + 2 * tid;
    int b = p0 >> 12, hw = p0 & 4095;
    size_t base = (size_t)b * 256 * 4096 + hw;
    float s0 = 0.f, s1 = 0.f, m0 = -3.4e38f, m1 = -3.4e38f;
#pragma unroll 1
    for (int c = 0; c < 256; c += 8) {
        float2 v[8];
#pragma unroll
        for (int j = 0; j < 8; ++j) {
            float2 u = *(float2*)&l[base + (size_t)(c + j) * 4096];
            float sc = sca[b * 256 + c + j];
            v[j].x = u.x * sc;
            v[j].y = u.y * sc;
        }
#pragma unroll
        for (int j = 0; j < 8; ++j) {
            *(float2*)&l[base + (size_t)(c + j) * 4096] = v[j];
            s0 += v[j].x;
            s1 += v[j].y;
            m0 = fmaxf(m0, v[j].x);
            m1 = fmaxf(m1, v[j].y);
        }
    }
    s2m[p0] = s0 * (1.f / 256.f);
    s2m[p0 + 1] = s1 * (1.f / 256.f);
    s2x[p0] = m0;
    s2x[p0 + 1] = m1;
}

__global__ void sconv_k(const float* __restrict__ s2m, const float* __restrict__ s2x,
                        const float* __restrict__ sw, float* __restrict__ satt) {
    int p = blockIdx.x * 256 + threadIdx.x;
    int b = p >> 12, hw = p & 4095, h = hw >> 6, w = hw & 63;
    float a = 0.f;
#pragma unroll
    for (int kh = 0; kh < 3; ++kh) {
        int hh = h + kh - 1;
        if ((unsigned)hh >= 64u) continue;
#pragma unroll
        for (int kw = 0; kw < 3; ++kw) {
            int ww = w + kw - 1;
            if ((unsigned)ww >= 64u) continue;
            int q = b * 4096 + hh * 64 + ww;
            a += s2m[q] * sw[kh * 3 + kw] + s2x[q] * sw[9 + kh * 3 + kw];
        }
    }
    satt[p] = 1.f / (1.f + expf(-a));
}

__global__ void lamT_k(const float* __restrict__ l, const float* __restrict__ satt,
                       const float* __restrict__ Lp, float* __restrict__ lam) {
    __shared__ float tile[32][33];
    int pb = blockIdx.x * 32, cb = blockIdx.y * 32;
    int tx = threadIdx.x, ty = threadIdx.y;
    int b = pb >> 12, pl = pb & 4095;
#pragma unroll
    for (int k = 0; k < 4; ++k) {
        int c = cb + ty + 8 * k;
        tile[ty + 8 * k][tx] = l[((size_t)b * 256 + c) * 4096 + pl + tx];
    }
    __syncthreads();
    float invL = 1.f / Lp[0];
#pragma unroll
    for (int k = 0; k < 4; ++k) {
        int p2 = pb + ty + 8 * k;
        float sc = satt[p2] * invL;
        lam[(size_t)p2 * 256 + cb + tx] = tile[tx][ty + 8 * k] * sc;
    }
}

// ---------------------------------------------------------------------------
// LISTA via mma.sync bf16 (hi/lo split), residual form (unchanged from R10)
// ---------------------------------------------------------------------------
#define ZH_OFF 0
#define ZL_OFF 33792
#define EH_OFF 67584
#define EL_OFF 76800
#define DH_OFF 86016
#define DL_OFF 119808
#define LAM_OFF 153600
#define LISTA_SMEM 220416
#define LDZ 264
#define LDE 72
#define LDD 264
#define LDL 261

__device__ __forceinline__ void run_step1(float R[16], unsigned zhA, unsigned zlA,
                                          unsigned dhA, unsigned dlA, int mB1,
                                          int cB1, int lane) {
#pragma unroll
    for (int i = 0; i < 16; ++i) R[i] = 0.f;
    int arow = mB1 * 16 + (lane & 15);
    int acolg = (lane >> 4) << 3;
    int brow0 = cB1 + (lane & 7) + (((lane >> 4) & 1) << 3);
    int bcolg = (((lane >> 3) & 1) << 3);
#pragma unroll 2
    for (int ks = 0; ks < 16; ++ks) {
        int k0 = ks * 16;
        unsigned ah[4], al[4], bh0[4], bh1[4], bl0[4], bl1[4];
        unsigned aoff = (unsigned)((arow * LDZ + k0 + acolg) * 2);
        ldsm4(ah, zhA + aoff);
        ldsm4(al, zlA + aoff);
        unsigned boff0 = (unsigned)((brow0 * LDD + k0 + bcolg) * 2);
        unsigned boff1 = (unsigned)(((brow0 + 16) * LDD + k0 + bcolg) * 2);
        ldsm4(bh0, dhA + boff0);
        ldsm4(bl0, dlA + boff0);
        ldsm4(bh1, dhA + boff1);
        ldsm4(bl1, dlA + boff1);
        mma16816(&R[0], ah, bh0[0], bh0[1]);
        mma16816(&R[0], ah, bl0[0], bl0[1]);
        mma16816(&R[0], al, bh0[0], bh0[1]);
        mma16816(&R[4], ah, bh0[2], bh0[3]);
        mma16816(&R[4], ah, bl0[2], bl0[3]);
        mma16816(&R[4], al, bh0[2], bh0[3]);
        mma16816(&R[8], ah, bh1[0], bh1[1]);
        mma16816(&R[8], ah, bl1[0], bl1[1]);
        mma16816(&R[8], al, bh1[0], bh1[1]);
        mma16816(&R[12], ah, bh1[2], bh1[3]);
        mma16816(&R[12], ah, bl1[2], bl1[3]);
        mma16816(&R[12], al, bh1[2], bh1[3]);
    }
}

__device__ __forceinline__ void run_step2(float q[64], unsigned ehA, unsigned elA,
                                          const unsigned short* dh,
                                          const unsigned short* dl, int mB2,
                                          int aB2, int lane) {
#pragma unroll
    for (int i = 0; i < 64; ++i) q[i] = 0.f;
    int arow = mB2 * 32 + (lane & 15);
    int acolg = (lane >> 4) << 3;
    int acol_b = aB2 + (lane >> 2);
    int kr_b = (lane & 3) << 1;
#pragma unroll
    for (int ks = 0; ks < 4; ++ks) {
        int k0 = ks * 16;
        unsigned ah0[4], al0[4], ah1[4], al1[4];
        unsigned aoff0 = (unsigned)((arow * LDE + k0 + acolg) * 2);
        unsigned aoff1 = (unsigned)(((arow + 16) * LDE + k0 + acolg) * 2);
        ldsm4(ah0, ehA + aoff0);
        ldsm4(al0, elA + aoff0);
        ldsm4(ah1, ehA + aoff1);
        ldsm4(al1, elA + aoff1);
        int kr = k0 + kr_b;
#pragma unroll
        for (int nt = 0; nt < 8; ++nt) {
            int ac = acol_b + nt * 8;
            unsigned h0 = (unsigned)dh[kr * LDD + ac] |
                          ((unsigned)dh[(kr + 1) * LDD + ac] << 16);
            unsigned h1 = (unsigned)dh[(kr + 8) * LDD + ac] |
                          ((unsigned)dh[(kr + 9) * LDD + ac] << 16);
            unsigned l0 = (unsigned)dl[kr * LDD + ac] |
                          ((unsigned)dl[(kr + 1) * LDD + ac] << 16);
            unsigned l1 = (unsigned)dl[(kr + 8) * LDD + ac] |
                          ((unsigned)dl[(kr + 9) * LDD + ac] << 16);
            mma16816(&q[nt * 4], ah0, h0, h1);
            mma16816(&q[nt * 4], ah0, l0, l1);
            mma16816(&q[nt * 4], al0, h0, h1);
            mma16816(&q[32 + nt * 4], ah1, h0, h1);
            mma16816(&q[32 + nt * 4], ah1, l0, l1);
            mma16816(&q[32 + nt * 4], al1, h0, h1);
        }
    }
}

__global__ __launch_bounds__(256, 1) void lista_mma_k(
    const float* __restrict__ x, const float* __restrict__ Dict,
    const float* __restrict__ Lp, const int* __restrict__ nip,
    const float* __restrict__ lam_g, float* __restrict__ out_z,
    float* __restrict__ out_r) {
    extern __shared__ __align__(16) char smem[];
    unsigned short* zh = (unsigned short*)(smem + ZH_OFF);
    unsigned short* zl = (unsigned short*)(smem + ZL_OFF);
    unsigned short* eh = (unsigned short*)(smem + EH_OFF);
    unsigned short* el = (unsigned short*)(smem + EL_OFF);
    unsigned short* dh = (unsigned short*)(smem + DH_OFF);
    unsigned short* dl = (unsigned short*)(smem + DL_OFF);
    float* lam = (float*)(smem + LAM_OFF);
    float* xrec = (float*)(smem + EH_OFF);
    float* zfp = lam;

    int t = threadIdx.x, w = t >> 5, lane = t & 31;
    int mB1 = w & 3, cB1 = (w >> 2) * 32;
    int mB2 = w & 1, aB2 = (w >> 1) * 64;
    int pbase = blockIdx.x * 64;
    int b = pbase >> 12, pl = pbase & 4095;
    float invL = 1.f / Lp[0];
    int niters = nip[0];

    unsigned zhA = (unsigned)__cvta_generic_to_shared(zh);
    unsigned zlA = (unsigned)__cvta_generic_to_shared(zl);
    unsigned ehA = (unsigned)__cvta_generic_to_shared(eh);
    unsigned elA = (unsigned)__cvta_generic_to_shared(el);
    unsigned dhA = (unsigned)__cvta_generic_to_shared(dh);
    unsigned dlA = (unsigned)__cvta_generic_to_shared(dl);

    for (int i = t; i < 16384; i += 256) {
        int m = i >> 8, a = i & 255;
        lam[m * LDL + a] = lam_g[(size_t)(pbase + m) * 256 + a];
    }
    for (int i = t; i < 16384; i += 256) {
        int c = i >> 8, a = i & 255;
        float v = Dict[i];
        unsigned short h = f2b(v);
        dh[c * LDD + a] = h;
        dl[c * LDD + a] = f2b(v - b2f(h));
    }
    size_t xofs = (size_t)b * 64 * 4096 + pl;
    for (int i = t; i < 4096; i += 256) {
        int c = i >> 6, m = i & 63;
        float v = x[xofs + (size_t)c * 4096 + m];
        unsigned short h = f2b(v);
        eh[m * LDE + c] = h;
        el[m * LDE + c] = f2b(v - b2f(h));
    }
    __syncthreads();

    float xfrag[16];
    {
        int r0 = mB1 * 16 + (lane >> 2);
#pragma unroll
        for (int nt = 0; nt < 4; ++nt) {
            int c2 = cB1 + nt * 8 + ((lane & 3) << 1);
            xfrag[nt * 4 + 0] = x[((size_t)b * 64 + c2) * 4096 + pl + r0];
            xfrag[nt * 4 + 1] = x[((size_t)b * 64 + c2 + 1) * 4096 + pl + r0];
            xfrag[nt * 4 + 2] = x[((size_t)b * 64 + c2) * 4096 + pl + r0 + 8];
            xfrag[nt * 4 + 3] = x[((size_t)b * 64 + c2 + 1) * 4096 + pl + r0 + 8];
        }
    }

    {
        float q[64];
        run_step2(q, ehA, elA, dh, dl, mB2, aB2, lane);
        bool wz = (niters == 0);
#pragma unroll
        for (int blk = 0; blk < 2; ++blk)
#pragma unroll
            for (int nt = 0; nt < 8; ++nt) {
                int r = mB2 * 32 + blk * 16 + (lane >> 2);
                int a2 = aB2 + nt * 8 + ((lane & 3) << 1);
                const float* qq = &q[blk * 32 + nt * 4];
#pragma unroll
                for (int rr = 0; rr < 2; ++rr) {
                    int row = r + rr * 8;
                    float y0 = qq[rr * 2], y1 = qq[rr * 2 + 1];
                    float l0 = lam[row * LDL + a2], l1 = lam[row * LDL + a2 + 1];
                    float g0 = fmaxf(fabsf(y0) - l0, 0.f);
                    float g1 = fmaxf(fabsf(y1) - l1, 0.f);
                    float z0 = (y0 > 0.f) ? g0 : -g0;
                    float z1 = (y1 > 0.f) ? g1 : -g1;
                    unsigned short h0 = f2b(z0), h1 = f2b(z1);
                    *(unsigned*)&zh[row * LDZ + a2] =
                        (unsigned)h0 | ((unsigned)h1 << 16);
                    *(unsigned*)&zl[row * LDZ + a2] =
                        (unsigned)f2b(z0 - b2f(h0)) |
                        ((unsigned)f2b(z1 - b2f(h1)) << 16);
                    if (wz) {
                        zfp[row * LDL + a2] = z0;
                        zfp[row * LDL + a2 + 1] = z1;
                    }
                }
            }
    }
    __syncthreads();

    for (int it = 0; it < niters; ++it) {
        float R[16];
        run_step1(R, zhA, zlA, dhA, dlA, mB1, cB1, lane);
        {
            int r0 = mB1 * 16 + (lane >> 2);
#pragma unroll
            for (int nt = 0; nt < 4; ++nt) {
                int c2 = cB1 + nt * 8 + ((lane & 3) << 1);
#pragma unroll
                for (int rr = 0; rr < 2; ++rr) {
                    int row = r0 + rr * 8;
                    float e0 = xfrag[nt * 4 + rr * 2] - R[nt * 4 + rr * 2];
                    float e1 = xfrag[nt * 4 + rr * 2 + 1] - R[nt * 4 + rr * 2 + 1];
                    unsigned short h0 = f2b(e0), h1 = f2b(e1);
                    *(unsigned*)&eh[row * LDE + c2] =
                        (unsigned)h0 | ((unsigned)h1 << 16);
                    *(unsigned*)&el[row * LDE + c2] =
                        (unsigned)f2b(e0 - b2f(h0)) |
                        ((unsigned)f2b(e1 - b2f(h1)) << 16);
                }
            }
        }
        __syncthreads();
        float q[64];
        run_step2(q, ehA, elA, dh, dl, mB2, aB2, lane);
        bool wz = (it == niters - 1);
#pragma unroll
        for (int blk = 0; blk < 2; ++blk)
#pragma unroll
            for (int nt = 0; nt < 8; ++nt) {
                int r = mB2 * 32 + blk * 16 + (lane >> 2);
                int a2 = aB2 + nt * 8 + ((lane & 3) << 1);
                const float* qq = &q[blk * 32 + nt * 4];
#pragma unroll
                for (int rr = 0; rr < 2; ++rr) {
                    int row = r + rr * 8;
                    unsigned hz = *(unsigned*)&zh[row * LDZ + a2];
                    unsigned lz = *(unsigned*)&zl[row * LDZ + a2];
                    float zo0 = b2f(hz & 0xffffu) + b2f(lz & 0xffffu);
                    float zo1 = b2f(hz >> 16) + b2f(lz >> 16);
                    float w0 = zo0 + qq[rr * 2] * invL;
                    float w1 = zo1 + qq[rr * 2 + 1] * invL;
                    float l0 = lam[row * LDL + a2], l1 = lam[row * LDL + a2 + 1];
                    float g0 = fmaxf(fabsf(w0) - l0, 0.f);
                    float g1 = fmaxf(fabsf(w1) - l1, 0.f);
                    float z0 = (w0 > 0.f) ? g0 : -g0;
                    float z1 = (w1 > 0.f) ? g1 : -g1;
                    unsigned short h0 = f2b(z0), h1 = f2b(z1);
                    *(unsigned*)&zh[row * LDZ + a2] =
                        (unsigned)h0 | ((unsigned)h1 << 16);
                    *(unsigned*)&zl[row * LDZ + a2] =
                        (unsigned)f2b(z0 - b2f(h0)) |
                        ((unsigned)f2b(z1 - b2f(h1)) << 16);
                    if (wz) {
                        zfp[row * LDL + a2] = z0;
                        zfp[row * LDL + a2 + 1] = z1;
                    }
                }
            }
        __syncthreads();
    }

    {
        float R[16];
        run_step1(R, zhA, zlA, dhA, dlA, mB1, cB1, lane);
        __syncthreads();
        int r0 = mB1 * 16 + (lane >> 2);
#pragma unroll
        for (int nt = 0; nt < 4; ++nt) {
            int c2 = cB1 + nt * 8 + ((lane & 3) << 1);
            xrec[r0 * 65 + c2] = R[nt * 4 + 0];
            xrec[r0 * 65 + c2 + 1] = R[nt * 4 + 1];
            xrec[(r0 + 8) * 65 + c2] = R[nt * 4 + 2];
            xrec[(r0 + 8) * 65 + c2 + 1] = R[nt * 4 + 3];
        }
    }
    __syncthreads();

    size_t zofs = (size_t)b * 256 * 4096 + pl;
    for (int i = t; i < 16384; i += 256) {
        int a = i >> 6, m = i & 63;
        out_z[zofs + (size_t)a * 4096 + m] = zfp[m * LDL + a];
    }
    size_t rofs = (size_t)b * 64 * 4096 + pl;
    for (int i = t; i < 4096; i += 256) {
        int c = i >> 6, m = i & 63;
        out_r[rofs + (size_t)c * 4096 + m] = xrec[m * 65 + c];
    }
}

__global__ void copy_k(const float* __restrict__ s, float* __restrict__ d, int n) {
    int i = blockIdx.x * blockDim.x + threadIdx.x;
    if (i < n) d[i] = s[i];
}

extern "C" void kernel_launch(void* const* d_in, const int* in_sizes, int n_in,
                              void* d_out, int out_size) {
    const float* x = (const float*)d_in[0];
    const float* conv_w = (const float*)d_in[1];
    const float* conv_b = (const float*)d_in[2];
    const float* r1w1 = (const float*)d_in[3];
    const float* r1w2 = (const float*)d_in[4];
    const float* r2w1 = (const float*)d_in[5];
    const float* r2w2 = (const float*)d_in[6];
    const float* caw1 = (const float*)d_in[7];
    const float* caw2 = (const float*)d_in[8];
    const float* saw = (const float*)d_in[9];
    const float* Dict = (const float*)d_in[10];
    const float* Lp = (const float*)d_in[11];
    const int* nip = (const int*)d_in[12];
    float* out = (float*)d_out;

    float *l, *tb, *avg, *mx, *sca, *s2m, *s2x, *satt, *lam;
    cudaGetSymbolAddress((void**)&l, g_l);
    cudaGetSymbolAddress((void**)&tb, g_t);
    cudaGetSymbolAddress((void**)&avg, g_avg);
    cudaGetSymbolAddress((void**)&mx, g_mx);
    cudaGetSymbolAddress((void**)&sca, g_sca);
    cudaGetSymbolAddress((void**)&s2m, g_s2m);
    cudaGetSymbolAddress((void**)&s2x, g_s2x);
    cudaGetSymbolAddress((void**)&satt, g_satt);
    cudaGetSymbolAddress((void**)&lam, g_lam);

    cudaFuncSetAttribute(conv3x3_mma_k<64, 256, false, true>,
                         cudaFuncAttributeMaxDynamicSharedMemorySize, CONV_SMEM);
    cudaFuncSetAttribute(conv3x3_mma_k<256, 128, true, false>,
                         cudaFuncAttributeMaxDynamicSharedMemorySize, CONV_SMEM);

    conv3x3_mma_k<64, 256, false, true>
        <<<dim3(256, 4), 256, CONV_SMEM>>>(x, conv_w, conv_b, l);
    conv3x3_mma_k<256, 128, true, false>
        <<<dim3(256, 2), 256, CONV_SMEM>>>(l, r1w1, nullptr, tb);
    conv1x1_add_k<<<dim3(64, 16), 256>>>(tb, r1w2, l);
    conv3x3_mma_k<256, 128, true, false>
        <<<dim3(256, 2), 256, CONV_SMEM>>>(l, r2w1, nullptr, tb);
    conv1x1_add_k<<<dim3(64, 16), 256>>>(tb, r2w2, l);
    pool_k<<<2048, 256>>>(l, avg, mx);
    camlp_k<<<1, 256>>>(avg, mx, caw1, caw2, sca);
    chan_k<<<64, 256>>>(l, sca, s2m, s2x);
    sconv_k<<<128, 256>>>(s2m, s2x, saw, satt);
    lamT_k<<<dim3(1024, 8), dim3(32, 8)>>>(l, satt, Lp, lam);

    cudaFuncSetAttribute(lista_mma_k, cudaFuncAttributeMaxDynamicSharedMemorySize,
                         LISTA_SMEM);
    lista_mma_k<<<512, 256, LISTA_SMEM>>>(x, Dict, Lp, nip, lam,
                                          out, out + 8 * 256 * 4096);
    copy_k<<<64, 256>>>(Dict, out + 8 * 256 * 4096 + 8 * 64 * 4096, 64 * 256);
}

// round 12
// speedup vs baseline: 1.9296x; 1.9296x over previous
#include <cuda_runtime.h>
#include <cuda_bf16.h>
#include <cstdint>

__device__ float g_l[8 * 256 * 4096];
__device__ float g_t[8 * 128 * 4096];
__device__ float g_lam[8 * 4096 * 256];
__device__ float g_avg[8 * 256];
__device__ float g_mx[8 * 256];
__device__ float g_sca[8 * 256];
__device__ float g_s2m[8 * 4096];
__device__ float g_s2x[8 * 4096];
__device__ float g_satt[8 * 4096];

__device__ __forceinline__ unsigned long long pk2(float a, float b) {
    unsigned long long r;
    asm("mov.b64 %0, {%1, %2};" : "=l"(r) : "f"(a), "f"(b));
    return r;
}
__device__ __forceinline__ void upk2(unsigned long long v, float& a, float& b) {
    asm("mov.b64 {%0, %1}, %2;" : "=f"(a), "=f"(b) : "l"(v));
}
__device__ __forceinline__ void ffma2(unsigned long long& d, unsigned long long a,
                                      unsigned long long b) {
    asm("fma.rn.f32x2 %0, %1, %2, %0;" : "+l"(d) : "l"(a), "l"(b));
}

__device__ __forceinline__ float b2f(unsigned u) {
    return __uint_as_float(u << 16);
}
__device__ __forceinline__ unsigned short f2b(float f) {
    __nv_bfloat16 h = __float2bfloat16(f);
    return *(unsigned short*)&h;
}
__device__ __forceinline__ void ldsm4(unsigned r[4], unsigned addr) {
    asm volatile("ldmatrix.sync.aligned.m8n8.x4.shared.b16 {%0,%1,%2,%3}, [%4];"
                 : "=r"(r[0]), "=r"(r[1]), "=r"(r[2]), "=r"(r[3])
                 : "r"(addr));
}
__device__ __forceinline__ void mma16816(float d[4], const unsigned a[4],
                                         unsigned b0, unsigned b1) {
    asm volatile(
        "mma.sync.aligned.m16n8k16.row.col.f32.bf16.bf16.f32 "
        "{%0,%1,%2,%3},{%4,%5,%6,%7},{%8,%9},{%0,%1,%2,%3};"
        : "+f"(d[0]), "+f"(d[1]), "+f"(d[2]), "+f"(d[3])
        : "r"(a[0]), "r"(a[1]), "r"(a[2]), "r"(a[3]), "r"(b0), "r"(b1));
}

// ---------------------------------------------------------------------------
// conv3x3 via mma.sync bf16 hi/lo split (implicit GEMM, per-tap shifts).
// CTA: 256 thr, M=128 pixels (2 rows x 64 cols), N=64 co, ci-chunks of 32.
// grid.x = batch*32 rowblocks, grid.y = CO/64.  Staging hoisted (MLP=8).
// ---------------------------------------------------------------------------
#define CILD 40
#define CWTAP 2560
#define CONV_IH 0
#define CONV_IL 10880
#define CONV_WH 21760
#define CONV_WL 44800
#define CONV_SMEM 135680

template <int CI, int CO, bool RELU, bool BIAS>
__global__ __launch_bounds__(256, 1) void conv3x3_mma_k(
    const float* __restrict__ in, const float* __restrict__ wt,
    const float* __restrict__ bias, float* __restrict__ out) {
    extern __shared__ __align__(16) unsigned short cs[];
    unsigned short* ih = cs + CONV_IH;
    unsigned short* il = cs + CONV_IL;
    unsigned short* wh = cs + CONV_WH;
    unsigned short* wl = cs + CONV_WL;
    int t = threadIdx.x, w = t >> 5, lane = t & 31;
    int b = blockIdx.x >> 5, rb = blockIdx.x & 31, r0 = rb * 2;
    int coB = blockIdx.y * 64;
    int wmB = (w & 3) * 32;
    int wnB = (w >> 2) * 32;

    unsigned ihA = (unsigned)__cvta_generic_to_shared(ih);
    unsigned ilA = (unsigned)__cvta_generic_to_shared(il);
    unsigned whA = (unsigned)__cvta_generic_to_shared(wh);
    unsigned wlA = (unsigned)__cvta_generic_to_shared(wl);

    for (int i = t; i < 10880; i += 256) ((unsigned*)cs)[i] = 0u;

    float acc[2][16];
#pragma unroll
    for (int mb = 0; mb < 2; ++mb)
#pragma unroll
        for (int i = 0; i < 16; ++i) acc[mb][i] = 0.f;

#pragma unroll 1
    for (int cc = 0; cc < CI / 32; ++cc) {
        __syncthreads();
        // stage input chunk (hoisted loads, MLP=8)
#pragma unroll 1
        for (int it = 0; it < 32; it += 8) {
            float v[8];
            int idx[8];
#pragma unroll
            for (int j = 0; j < 8; ++j) {
                int i = t + (it + j) * 256;
                int col = i & 63, row = (i >> 6) & 3, ci = i >> 8;
                int imgrow = r0 - 1 + row;
                float u = 0.f;
                if ((unsigned)imgrow < 64u)
                    u = in[((size_t)b * CI + cc * 32 + ci) * 4096 + imgrow * 64 +
                           col];
                v[j] = RELU ? fmaxf(u, 0.f) : u;
                idx[j] = (row * 68 + col + 1) * CILD + ci;
            }
#pragma unroll
            for (int j = 0; j < 8; ++j) {
                unsigned short h = f2b(v[j]);
                ih[idx[j]] = h;
                il[idx[j]] = f2b(v[j] - b2f(h));
            }
        }
        // stage weights chunk (hoisted loads, MLP=8)
#pragma unroll 1
        for (int it = 0; it < 72; it += 8) {
            float v[8];
            int idx[8];
#pragma unroll
            for (int j = 0; j < 8; ++j) {
                int i = t + (it + j) * 256;
                int co = i / 288, g = i - co * 288;
                int ci = g / 9, tap = g - ci * 9;
                v[j] = wt[(size_t)(coB + co) * (CI * 9) + (cc * 32 + ci) * 9 + tap];
                idx[j] = tap * CWTAP + co * CILD + ci;
            }
#pragma unroll
            for (int j = 0; j < 8; ++j) {
                unsigned short h = f2b(v[j]);
                wh[idx[j]] = h;
                wl[idx[j]] = f2b(v[j] - b2f(h));
            }
        }
        __syncthreads();

#pragma unroll 1
        for (int tap = 0; tap < 9; ++tap) {
            int dh = tap / 3, dw = tap - dh * 3;
#pragma unroll
            for (int ks = 0; ks < 2; ++ks) {
                int k0 = ks * 16;
                unsigned ah[2][4], al[2][4], bh[2][4], bl[2][4];
#pragma unroll
                for (int mb = 0; mb < 2; ++mb) {
                    int p = wmB + mb * 16 + (lane & 15);
                    int trow = (p >> 6) + dh;
                    int tcol = (p & 63) + dw;
                    unsigned aoff = (unsigned)((trow * 68 + tcol) * CILD + k0 +
                                               ((lane >> 4) << 3)) *
                                    2;
                    ldsm4(ah[mb], ihA + aoff);
                    ldsm4(al[mb], ilA + aoff);
                }
                int brow = wnB + (lane & 7) + (((lane >> 4) & 1) << 3);
                unsigned bo0 = (unsigned)(tap * CWTAP + brow * CILD + k0 +
                                          (((lane >> 3) & 1) << 3)) *
                               2;
                unsigned bo1 = bo0 + 16 * CILD * 2;
                ldsm4(bh[0], whA + bo0);
                ldsm4(bh[1], whA + bo1);
                ldsm4(bl[0], wlA + bo0);
                ldsm4(bl[1], wlA + bo1);
#pragma unroll
                for (int mb = 0; mb < 2; ++mb) {
                    mma16816(&acc[mb][0], ah[mb], bh[0][0], bh[0][1]);
                    mma16816(&acc[mb][0], ah[mb], bl[0][0], bl[0][1]);
                    mma16816(&acc[mb][0], al[mb], bh[0][0], bh[0][1]);
                    mma16816(&acc[mb][4], ah[mb], bh[0][2], bh[0][3]);
                    mma16816(&acc[mb][4], ah[mb], bl[0][2], bl[0][3]);
                    mma16816(&acc[mb][4], al[mb], bh[0][2], bh[0][3]);
                    mma16816(&acc[mb][8], ah[mb], bh[1][0], bh[1][1]);
                    mma16816(&acc[mb][8], ah[mb], bl[1][0], bl[1][1]);
                    mma16816(&acc[mb][8], al[mb], bh[1][0], bh[1][1]);
                    mma16816(&acc[mb][12], ah[mb], bh[1][2], bh[1][3]);
                    mma16816(&acc[mb][12], ah[mb], bl[1][2], bl[1][3]);
                    mma16816(&acc[mb][12], al[mb], bh[1][2], bh[1][3]);
                }
            }
        }
    }

    size_t ob = (size_t)b * CO * 4096;
#pragma unroll
    for (int mb = 0; mb < 2; ++mb) {
        int p0 = wmB + mb * 16 + (lane >> 2);
#pragma unroll
        for (int nb = 0; nb < 4; ++nb) {
            int n = coB + wnB + nb * 8 + ((lane & 3) << 1);
            float bs0 = BIAS ? bias[n] : 0.f;
            float bs1 = BIAS ? bias[n + 1] : 0.f;
#pragma unroll
            for (int rr = 0; rr < 2; ++rr) {
                int p = p0 + rr * 8;
                int orow = r0 + (p >> 6), ocol = p & 63;
                out[ob + (size_t)n * 4096 + orow * 64 + ocol] =
                    acc[mb][nb * 4 + rr * 2] + bs0;
                out[ob + (size_t)(n + 1) * 4096 + orow * 64 + ocol] =
                    acc[mb][nb * 4 + rr * 2 + 1] + bs1;
            }
        }
    }
}

// 1x1 conv (relu(t)@w2) + residual add; CI=128, 16 co per block, 2 px/thread
__global__ __launch_bounds__(256) void conv1x1_add_k(const float* __restrict__ tin,
                                                     const float* __restrict__ wt,
                                                     float* __restrict__ lio) {
    __shared__ __align__(16) float wsh[128 * 16];
    int tid = threadIdx.x;
    int p0 = blockIdx.x * 512 + 2 * tid;
    int b = p0 >> 12, hw = p0 & 4095;
    int coBase = blockIdx.y * 16;
    for (int i = tid; i < 2048; i += 256) {
        int o = i >> 7, ci = i & 127;
        wsh[ci * 16 + o] = wt[(size_t)(coBase + o) * 128 + ci];
    }
    __syncthreads();
    unsigned long long acc2[16];
    size_t lb = ((size_t)b * 256 + coBase) * 4096 + hw;
#pragma unroll
    for (int q = 0; q < 8; ++q) {
        float2 v = *(const float2*)&lio[lb + (size_t)(2 * q) * 4096];
        float2 u = *(const float2*)&lio[lb + (size_t)(2 * q + 1) * 4096];
        acc2[2 * q] = pk2(v.x, u.x);
        acc2[2 * q + 1] = pk2(v.y, u.y);
    }
    const float* tb = tin + (size_t)b * 128 * 4096 + hw;
#pragma unroll 1
    for (int ci = 0; ci < 128; ci += 8) {
        float2 v[8];
#pragma unroll
        for (int j = 0; j < 8; ++j) {
            float2 u = *(const float2*)&tb[(size_t)(ci + j) * 4096];
            v[j].x = fmaxf(u.x, 0.f);
            v[j].y = fmaxf(u.y, 0.f);
        }
#pragma unroll
        for (int j = 0; j < 8; ++j) {
            unsigned long long v0 = pk2(v[j].x, v[j].x);
            unsigned long long v1 = pk2(v[j].y, v[j].y);
            const ulonglong2* wp = (const ulonglong2*)&wsh[(ci + j) * 16];
#pragma unroll
            for (int q = 0; q < 4; ++q) {
                ulonglong2 wq = wp[q];
                ffma2(acc2[4 * q], wq.x, v0);
                ffma2(acc2[4 * q + 1], wq.x, v1);
                ffma2(acc2[4 * q + 2], wq.y, v0);
                ffma2(acc2[4 * q + 3], wq.y, v1);
            }
        }
    }
#pragma unroll
    for (int q = 0; q < 8; ++q) {
        float a0, a1, b0_, b1_;
        upk2(acc2[2 * q], a0, b0_);
        upk2(acc2[2 * q + 1], a1, b1_);
        float2 o0 = {a0, a1}, o1 = {b0_, b1_};
        *(float2*)&lio[lb + (size_t)(2 * q) * 4096] = o0;
        *(float2*)&lio[lb + (size_t)(2 * q + 1) * 4096] = o1;
    }
}

__global__ __launch_bounds__(256) void pool_k(const float* __restrict__ l,
                                              float* __restrict__ avg,
                                              float* __restrict__ mx) {
    __shared__ float ss[256], sm[256];
    int bc = blockIdx.x, t = threadIdx.x;
    const float4* p = (const float4*)(l + (size_t)bc * 4096);
    float s = 0.f, m = -3.4e38f;
    for (int i = t; i < 1024; i += 256) {
        float4 v = p[i];
        s += v.x + v.y + v.z + v.w;
        m = fmaxf(m, fmaxf(fmaxf(v.x, v.y), fmaxf(v.z, v.w)));
    }
    ss[t] = s;
    sm[t] = m;
    __syncthreads();
    for (int st = 128; st > 0; st >>= 1) {
        if (t < st) {
            ss[t] += ss[t + st];
            sm[t] = fmaxf(sm[t], sm[t + st]);
        }
        __syncthreads();
    }
    if (t == 0) {
        avg[bc] = ss[0] * (1.f / 4096.f);
        mx[bc] = sm[0];
    }
}

__global__ void camlp_k(const float* __restrict__ avg, const float* __restrict__ mx,
                        const float* __restrict__ w1, const float* __restrict__ w2,
                        float* __restrict__ sca) {
    __shared__ float hsh[128];
    int t = threadIdx.x;
    if (t < 128) {
        int b = t >> 4, j = t & 15;
        float a = 0.f, m = 0.f;
        for (int c = 0; c < 256; ++c) {
            float w = w1[j * 256 + c];
            a += avg[b * 256 + c] * w;
            m += mx[b * 256 + c] * w;
        }
        hsh[b * 16 + j] = fmaxf(a, 0.f) + fmaxf(m, 0.f);
    }
    __syncthreads();
    for (int b = 0; b < 8; ++b) {
        float o = 0.f;
#pragma unroll
        for (int j = 0; j < 16; ++j) o += hsh[b * 16 + j] * w2[t * 16 + j];
        sca[b * 256 + t] = 1.f / (1.f + expf(-o));
    }
}

__global__ __launch_bounds__(256) void chan_k(float* __restrict__ l,
                                              const float* __restrict__ sca,
                                              float* __restrict__ s2m,
                                              float* __restrict__ s2x) {
    int tid = threadIdx.x;
    int p0 = blockIdx.x * 512 + 2 * tid;
    int b = p0 >> 12, hw = p0 & 4095;
    size_t base = (size_t)b * 256 * 4096 + hw;
    float s0 = 0.f, s1 = 0.f, m0 = -3.4e38f, m1 = -3.4e38f;
#pragma unroll 1
    for (int c = 0; c < 256; c += 8) {
        float2 v[8];
#pragma unroll
        for (int j = 0; j < 8; ++j) {
            float2 u = *(float2*)&l[base + (size_t)(c + j) * 4096];
            float sc = sca[b * 256 + c + j];
            v[j].x = u.x * sc;
            v[j].y = u.y * sc;
        }
#pragma unroll
        for (int j = 0; j < 8; ++j) {
            *(float2*)&l[base + (size_t)(c + j) * 4096] = v[j];
            s0 += v[j].x;
            s1 += v[j].y;
            m0 = fmaxf(m0, v[j].x);
            m1 = fmaxf(m1, v[j].y);
        }
    }
    s2m[p0] = s0 * (1.f / 256.f);
    s2m[p0 + 1] = s1 * (1.f / 256.f);
    s2x[p0] = m0;
    s2x[p0 + 1] = m1;
}

__global__ void sconv_k(const float* __restrict__ s2m, const float* __restrict__ s2x,
                        const float* __restrict__ sw, float* __restrict__ satt) {
    int p = blockIdx.x * 256 + threadIdx.x;
    int b = p >> 12, hw = p & 4095, h = hw >> 6, w = hw & 63;
    float a = 0.f;
#pragma unroll
    for (int kh = 0; kh < 3; ++kh) {
        int hh = h + kh - 1;
        if ((unsigned)hh >= 64u) continue;
#pragma unroll
        for (int kw = 0; kw < 3; ++kw) {
            int ww = w + kw - 1;
            if ((unsigned)ww >= 64u) continue;
            int q = b * 4096 + hh * 64 + ww;
            a += s2m[q] * sw[kh * 3 + kw] + s2x[q] * sw[9 + kh * 3 + kw];
        }
    }
    satt[p] = 1.f / (1.f + expf(-a));
}

__global__ void lamT_k(const float* __restrict__ l, const float* __restrict__ satt,
                       const float* __restrict__ Lp, float* __restrict__ lam) {
    __shared__ float tile[32][33];
    int pb = blockIdx.x * 32, cb = blockIdx.y * 32;
    int tx = threadIdx.x, ty = threadIdx.y;
    int b = pb >> 12, pl = pb & 4095;
#pragma unroll
    for (int k = 0; k < 4; ++k) {
        int c = cb + ty + 8 * k;
        tile[ty + 8 * k][tx] = l[((size_t)b * 256 + c) * 4096 + pl + tx];
    }
    __syncthreads();
    float invL = 1.f / Lp[0];
#pragma unroll
    for (int k = 0; k < 4; ++k) {
        int p2 = pb + ty + 8 * k;
        float sc = satt[p2] * invL;
        lam[(size_t)p2 * 256 + cb + tx] = tile[tx][ty + 8 * k] * sc;
    }
}

// ---------------------------------------------------------------------------
// LISTA via mma.sync bf16 (hi/lo split), residual form (unchanged from R10)
// ---------------------------------------------------------------------------
#define ZH_OFF 0
#define ZL_OFF 33792
#define EH_OFF 67584
#define EL_OFF 76800
#define DH_OFF 86016
#define DL_OFF 119808
#define LAM_OFF 153600
#define LISTA_SMEM 220416
#define LDZ 264
#define LDE 72
#define LDD 264
#define LDL 261

__device__ __forceinline__ void run_step1(float R[16], unsigned zhA, unsigned zlA,
                                          unsigned dhA, unsigned dlA, int mB1,
                                          int cB1, int lane) {
#pragma unroll
    for (int i = 0; i < 16; ++i) R[i] = 0.f;
    int arow = mB1 * 16 + (lane & 15);
    int acolg = (lane >> 4) << 3;
    int brow0 = cB1 + (lane & 7) + (((lane >> 4) & 1) << 3);
    int bcolg = (((lane >> 3) & 1) << 3);
#pragma unroll 2
    for (int ks = 0; ks < 16; ++ks) {
        int k0 = ks * 16;
        unsigned ah[4], al[4], bh0[4], bh1[4], bl0[4], bl1[4];
        unsigned aoff = (unsigned)((arow * LDZ + k0 + acolg) * 2);
        ldsm4(ah, zhA + aoff);
        ldsm4(al, zlA + aoff);
        unsigned boff0 = (unsigned)((brow0 * LDD + k0 + bcolg) * 2);
        unsigned boff1 = (unsigned)(((brow0 + 16) * LDD + k0 + bcolg) * 2);
        ldsm4(bh0, dhA + boff0);
        ldsm4(bl0, dlA + boff0);
        ldsm4(bh1, dhA + boff1);
        ldsm4(bl1, dlA + boff1);
        mma16816(&R[0], ah, bh0[0], bh0[1]);
        mma16816(&R[0], ah, bl0[0], bl0[1]);
        mma16816(&R[0], al, bh0[0], bh0[1]);
        mma16816(&R[4], ah, bh0[2], bh0[3]);
        mma16816(&R[4], ah, bl0[2], bl0[3]);
        mma16816(&R[4], al, bh0[2], bh0[3]);
        mma16816(&R[8], ah, bh1[0], bh1[1]);
        mma16816(&R[8], ah, bl1[0], bl1[1]);
        mma16816(&R[8], al, bh1[0], bh1[1]);
        mma16816(&R[12], ah, bh1[2], bh1[3]);
        mma16816(&R[12], ah, bl1[2], bl1[3]);
        mma16816(&R[12], al, bh1[2], bh1[3]);
    }
}

__device__ __forceinline__ void run_step2(float q[64], unsigned ehA, unsigned elA,
                                          const unsigned short* dh,
                                          const unsigned short* dl, int mB2,
                                          int aB2, int lane) {
#pragma unroll
    for (int i = 0; i < 64; ++i) q[i] = 0.f;
    int arow = mB2 * 32 + (lane & 15);
    int acolg = (lane >> 4) << 3;
    int acol_b = aB2 + (lane >> 2);
    int kr_b = (lane & 3) << 1;
#pragma unroll
    for (int ks = 0; ks < 4; ++ks) {
        int k0 = ks * 16;
        unsigned ah0[4], al0[4], ah1[4], al1[4];
        unsigned aoff0 = (unsigned)((arow * LDE + k0 + acolg) * 2);
        unsigned aoff1 = (unsigned)(((arow + 16) * LDE + k0 + acolg) * 2);
        ldsm4(ah0, ehA + aoff0);
        ldsm4(al0, elA + aoff0);
        ldsm4(ah1, ehA + aoff1);
        ldsm4(al1, elA + aoff1);
        int kr = k0 + kr_b;
#pragma unroll
        for (int nt = 0; nt < 8; ++nt) {
            int ac = acol_b + nt * 8;
            unsigned h0 = (unsigned)dh[kr * LDD + ac] |
                          ((unsigned)dh[(kr + 1) * LDD + ac] << 16);
            unsigned h1 = (unsigned)dh[(kr + 8) * LDD + ac] |
                          ((unsigned)dh[(kr + 9) * LDD + ac] << 16);
            unsigned l0 = (unsigned)dl[kr * LDD + ac] |
                          ((unsigned)dl[(kr + 1) * LDD + ac] << 16);
            unsigned l1 = (unsigned)dl[(kr + 8) * LDD + ac] |
                          ((unsigned)dl[(kr + 9) * LDD + ac] << 16);
            mma16816(&q[nt * 4], ah0, h0, h1);
            mma16816(&q[nt * 4], ah0, l0, l1);
            mma16816(&q[nt * 4], al0, h0, h1);
            mma16816(&q[32 + nt * 4], ah1, h0, h1);
            mma16816(&q[32 + nt * 4], ah1, l0, l1);
            mma16816(&q[32 + nt * 4], al1, h0, h1);
        }
    }
}

__global__ __launch_bounds__(256, 1) void lista_mma_k(
    const float* __restrict__ x, const float* __restrict__ Dict,
    const float* __restrict__ Lp, const int* __restrict__ nip,
    const float* __restrict__ lam_g, float* __restrict__ out_z,
    float* __restrict__ out_r) {
    extern __shared__ __align__(16) char smem[];
    unsigned short* zh = (unsigned short*)(smem + ZH_OFF);
    unsigned short* zl = (unsigned short*)(smem + ZL_OFF);
    unsigned short* eh = (unsigned short*)(smem + EH_OFF);
    unsigned short* el = (unsigned short*)(smem + EL_OFF);
    unsigned short* dh = (unsigned short*)(smem + DH_OFF);
    unsigned short* dl = (unsigned short*)(smem + DL_OFF);
    float* lam = (float*)(smem + LAM_OFF);
    float* xrec = (float*)(smem + EH_OFF);
    float* zfp = lam;

    int t = threadIdx.x, w = t >> 5, lane = t & 31;
    int mB1 = w & 3, cB1 = (w >> 2) * 32;
    int mB2 = w & 1, aB2 = (w >> 1) * 64;
    int pbase = blockIdx.x * 64;
    int b = pbase >> 12, pl = pbase & 4095;
    float invL = 1.f / Lp[0];
    int niters = nip[0];

    unsigned zhA = (unsigned)__cvta_generic_to_shared(zh);
    unsigned zlA = (unsigned)__cvta_generic_to_shared(zl);
    unsigned ehA = (unsigned)__cvta_generic_to_shared(eh);
    unsigned elA = (unsigned)__cvta_generic_to_shared(el);
    unsigned dhA = (unsigned)__cvta_generic_to_shared(dh);
    unsigned dlA = (unsigned)__cvta_generic_to_shared(dl);

    for (int i = t; i < 16384; i += 256) {
        int m = i >> 8, a = i & 255;
        lam[m * LDL + a] = lam_g[(size_t)(pbase + m) * 256 + a];
    }
    for (int i = t; i < 16384; i += 256) {
        int c = i >> 8, a = i & 255;
        float v = Dict[i];
        unsigned short h = f2b(v);
        dh[c * LDD + a] = h;
        dl[c * LDD + a] = f2b(v - b2f(h));
    }
    size_t xofs = (size_t)b * 64 * 4096 + pl;
    for (int i = t; i < 4096; i += 256) {
        int c = i >> 6, m = i & 63;
        float v = x[xofs + (size_t)c * 4096 + m];
        unsigned short h = f2b(v);
        eh[m * LDE + c] = h;
        el[m * LDE + c] = f2b(v - b2f(h));
    }
    __syncthreads();

    float xfrag[16];
    {
        int r0 = mB1 * 16 + (lane >> 2);
#pragma unroll
        for (int nt = 0; nt < 4; ++nt) {
            int c2 = cB1 + nt * 8 + ((lane & 3) << 1);
            xfrag[nt * 4 + 0] = x[((size_t)b * 64 + c2) * 4096 + pl + r0];
            xfrag[nt * 4 + 1] = x[((size_t)b * 64 + c2 + 1) * 4096 + pl + r0];
            xfrag[nt * 4 + 2] = x[((size_t)b * 64 + c2) * 4096 + pl + r0 + 8];
            xfrag[nt * 4 + 3] = x[((size_t)b * 64 + c2 + 1) * 4096 + pl + r0 + 8];
        }
    }

    {
        float q[64];
        run_step2(q, ehA, elA, dh, dl, mB2, aB2, lane);
        bool wz = (niters == 0);
#pragma unroll
        for (int blk = 0; blk < 2; ++blk)
#pragma unroll
            for (int nt = 0; nt < 8; ++nt) {
                int r = mB2 * 32 + blk * 16 + (lane >> 2);
                int a2 = aB2 + nt * 8 + ((lane & 3) << 1);
                const float* qq = &q[blk * 32 + nt * 4];
#pragma unroll
                for (int rr = 0; rr < 2; ++rr) {
                    int row = r + rr * 8;
                    float y0 = qq[rr * 2], y1 = qq[rr * 2 + 1];
                    float l0 = lam[row * LDL + a2], l1 = lam[row * LDL + a2 + 1];
                    float g0 = fmaxf(fabsf(y0) - l0, 0.f);
                    float g1 = fmaxf(fabsf(y1) - l1, 0.f);
                    float z0 = (y0 > 0.f) ? g0 : -g0;
                    float z1 = (y1 > 0.f) ? g1 : -g1;
                    unsigned short h0 = f2b(z0), h1 = f2b(z1);
                    *(unsigned*)&zh[row * LDZ + a2] =
                        (unsigned)h0 | ((unsigned)h1 << 16);
                    *(unsigned*)&zl[row * LDZ + a2] =
                        (unsigned)f2b(z0 - b2f(h0)) |
                        ((unsigned)f2b(z1 - b2f(h1)) << 16);
                    if (wz) {
                        zfp[row * LDL + a2] = z0;
                        zfp[row * LDL + a2 + 1] = z1;
                    }
                }
            }
    }
    __syncthreads();

    for (int it = 0; it < niters; ++it) {
        float R[16];
        run_step1(R, zhA, zlA, dhA, dlA, mB1, cB1, lane);
        {
            int r0 = mB1 * 16 + (lane >> 2);
#pragma unroll
            for (int nt = 0; nt < 4; ++nt) {
                int c2 = cB1 + nt * 8 + ((lane & 3) << 1);
#pragma unroll
                for (int rr = 0; rr < 2; ++rr) {
                    int row = r0 + rr * 8;
                    float e0 = xfrag[nt * 4 + rr * 2] - R[nt * 4 + rr * 2];
                    float e1 = xfrag[nt * 4 + rr * 2 + 1] - R[nt * 4 + rr * 2 + 1];
                    unsigned short h0 = f2b(e0), h1 = f2b(e1);
                    *(unsigned*)&eh[row * LDE + c2] =
                        (unsigned)h0 | ((unsigned)h1 << 16);
                    *(unsigned*)&el[row * LDE + c2] =
                        (unsigned)f2b(e0 - b2f(h0)) |
                        ((unsigned)f2b(e1 - b2f(h1)) << 16);
                }
            }
        }
        __syncthreads();
        float q[64];
        run_step2(q, ehA, elA, dh, dl, mB2, aB2, lane);
        bool wz = (it == niters - 1);
#pragma unroll
        for (int blk = 0; blk < 2; ++blk)
#pragma unroll
            for (int nt = 0; nt < 8; ++nt) {
                int r = mB2 * 32 + blk * 16 + (lane >> 2);
                int a2 = aB2 + nt * 8 + ((lane & 3) << 1);
                const float* qq = &q[blk * 32 + nt * 4];
#pragma unroll
                for (int rr = 0; rr < 2; ++rr) {
                    int row = r + rr * 8;
                    unsigned hz = *(unsigned*)&zh[row * LDZ + a2];
                    unsigned lz = *(unsigned*)&zl[row * LDZ + a2];
                    float zo0 = b2f(hz & 0xffffu) + b2f(lz & 0xffffu);
                    float zo1 = b2f(hz >> 16) + b2f(lz >> 16);
                    float w0 = zo0 + qq[rr * 2] * invL;
                    float w1 = zo1 + qq[rr * 2 + 1] * invL;
                    float l0 = lam[row * LDL + a2], l1 = lam[row * LDL + a2 + 1];
                    float g0 = fmaxf(fabsf(w0) - l0, 0.f);
                    float g1 = fmaxf(fabsf(w1) - l1, 0.f);
                    float z0 = (w0 > 0.f) ? g0 : -g0;
                    float z1 = (w1 > 0.f) ? g1 : -g1;
                    unsigned short h0 = f2b(z0), h1 = f2b(z1);
                    *(unsigned*)&zh[row * LDZ + a2] =
                        (unsigned)h0 | ((unsigned)h1 << 16);
                    *(unsigned*)&zl[row * LDZ + a2] =
                        (unsigned)f2b(z0 - b2f(h0)) |
                        ((unsigned)f2b(z1 - b2f(h1)) << 16);
                    if (wz) {
                        zfp[row * LDL + a2] = z0;
                        zfp[row * LDL + a2 + 1] = z1;
                    }
                }
            }
        __syncthreads();
    }

    {
        float R[16];
        run_step1(R, zhA, zlA, dhA, dlA, mB1, cB1, lane);
        __syncthreads();
        int r0 = mB1 * 16 + (lane >> 2);
#pragma unroll
        for (int nt = 0; nt < 4; ++nt) {
            int c2 = cB1 + nt * 8 + ((lane & 3) << 1);
            xrec[r0 * 65 + c2] = R[nt * 4 + 0];
            xrec[r0 * 65 + c2 + 1] = R[nt * 4 + 1];
            xrec[(r0 + 8) * 65 + c2] = R[nt * 4 + 2];
            xrec[(r0 + 8) * 65 + c2 + 1] = R[nt * 4 + 3];
        }
    }
    __syncthreads();

    size_t zofs = (size_t)b * 256 * 4096 + pl;
    for (int i = t; i < 16384; i += 256) {
        int a = i >> 6, m = i & 63;
        out_z[zofs + (size_t)a * 4096 + m] = zfp[m * LDL + a];
    }
    size_t rofs = (size_t)b * 64 * 4096 + pl;
    for (int i = t; i < 4096; i += 256) {
        int c = i >> 6, m = i & 63;
        out_r[rofs + (size_t)c * 4096 + m] = xrec[m * 65 + c];
    }
}

__global__ void copy_k(const float* __restrict__ s, float* __restrict__ d, int n) {
    int i = blockIdx.x * blockDim.x + threadIdx.x;
    if (i < n) d[i] = s[i];
}

extern "C" void kernel_launch(void* const* d_in, const int* in_sizes, int n_in,
                              void* d_out, int out_size) {
    const float* x = (const float*)d_in[0];
    const float* conv_w = (const float*)d_in[1];
    const float* conv_b = (const float*)d_in[2];
    const float* r1w1 = (const float*)d_in[3];
    const float* r1w2 = (const float*)d_in[4];
    const float* r2w1 = (const float*)d_in[5];
    const float* r2w2 = (const float*)d_in[6];
    const float* caw1 = (const float*)d_in[7];
    const float* caw2 = (const float*)d_in[8];
    const float* saw = (const float*)d_in[9];
    const float* Dict = (const float*)d_in[10];
    const float* Lp = (const float*)d_in[11];
    const int* nip = (const int*)d_in[12];
    float* out = (float*)d_out;

    float *l, *tb, *avg, *mx, *sca, *s2m, *s2x, *satt, *lam;
    cudaGetSymbolAddress((void**)&l, g_l);
    cudaGetSymbolAddress((void**)&tb, g_t);
    cudaGetSymbolAddress((void**)&avg, g_avg);
    cudaGetSymbolAddress((void**)&mx, g_mx);
    cudaGetSymbolAddress((void**)&sca, g_sca);
    cudaGetSymbolAddress((void**)&s2m, g_s2m);
    cudaGetSymbolAddress((void**)&s2x, g_s2x);
    cudaGetSymbolAddress((void**)&satt, g_satt);
    cudaGetSymbolAddress((void**)&lam, g_lam);

    cudaFuncSetAttribute(conv3x3_mma_k<64, 256, false, true>,
                         cudaFuncAttributeMaxDynamicSharedMemorySize, CONV_SMEM);
    cudaFuncSetAttribute(conv3x3_mma_k<256, 128, true, false>,
                         cudaFuncAttributeMaxDynamicSharedMemorySize, CONV_SMEM);

    conv3x3_mma_k<64, 256, false, true>
        <<<dim3(256, 4), 256, CONV_SMEM>>>(x, conv_w, conv_b, l);
    conv3x3_mma_k<256, 128, true, false>
        <<<dim3(256, 2), 256, CONV_SMEM>>>(l, r1w1, nullptr, tb);
    conv1x1_add_k<<<dim3(64, 16), 256>>>(tb, r1w2, l);
    conv3x3_mma_k<256, 128, true, false>
        <<<dim3(256, 2), 256, CONV_SMEM>>>(l, r2w1, nullptr, tb);
    conv1x1_add_k<<<dim3(64, 16), 256>>>(tb, r2w2, l);
    pool_k<<<2048, 256>>>(l, avg, mx);
    camlp_k<<<1, 256>>>(avg, mx, caw1, caw2, sca);
    chan_k<<<64, 256>>>(l, sca, s2m, s2x);
    sconv_k<<<128, 256>>>(s2m, s2x, saw, satt);
    lamT_k<<<dim3(1024, 8), dim3(32, 8)>>>(l, satt, Lp, lam);

    cudaFuncSetAttribute(lista_mma_k, cudaFuncAttributeMaxDynamicSharedMemorySize,
                         LISTA_SMEM);
    lista_mma_k<<<512, 256, LISTA_SMEM>>>(x, Dict, Lp, nip, lam,
                                          out, out + 8 * 256 * 4096);
    copy_k<<<64, 256>>>(Dict, out + 8 * 256 * 4096 + 8 * 64 * 4096, 64 * 256);
}

// round 13
// speedup vs baseline: 2.1737x; 1.1265x over previous
#include <cuda_runtime.h>
#include <cuda_bf16.h>
#include <cstdint>

__device__ float g_l[8 * 256 * 4096];
__device__ float g_t[8 * 128 * 4096];
__device__ float g_lam[8 * 4096 * 256];
__device__ float g_avg[8 * 256];
__device__ float g_mx[8 * 256];
__device__ float g_sca[8 * 256];
__device__ float g_s2m[8 * 4096];
__device__ float g_s2x[8 * 4096];
__device__ float g_satt[8 * 4096];

__device__ __forceinline__ unsigned long long pk2(float a, float b) {
    unsigned long long r;
    asm("mov.b64 %0, {%1, %2};" : "=l"(r) : "f"(a), "f"(b));
    return r;
}
__device__ __forceinline__ void upk2(unsigned long long v, float& a, float& b) {
    asm("mov.b64 {%0, %1}, %2;" : "=f"(a), "=f"(b) : "l"(v));
}
__device__ __forceinline__ void ffma2(unsigned long long& d, unsigned long long a,
                                      unsigned long long b) {
    asm("fma.rn.f32x2 %0, %1, %2, %0;" : "+l"(d) : "l"(a), "l"(b));
}

__device__ __forceinline__ float b2f(unsigned u) {
    return __uint_as_float(u << 16);
}
__device__ __forceinline__ unsigned short f2b(float f) {
    __nv_bfloat16 h = __float2bfloat16(f);
    return *(unsigned short*)&h;
}
__device__ __forceinline__ void ldsm4(unsigned r[4], unsigned addr) {
    asm volatile("ldmatrix.sync.aligned.m8n8.x4.shared.b16 {%0,%1,%2,%3}, [%4];"
                 : "=r"(r[0]), "=r"(r[1]), "=r"(r[2]), "=r"(r[3])
                 : "r"(addr));
}
__device__ __forceinline__ void mma16816(float d[4], const unsigned a[4],
                                         unsigned b0, unsigned b1) {
    asm volatile(
        "mma.sync.aligned.m16n8k16.row.col.f32.bf16.bf16.f32 "
        "{%0,%1,%2,%3},{%4,%5,%6,%7},{%8,%9},{%0,%1,%2,%3};"
        : "+f"(d[0]), "+f"(d[1]), "+f"(d[2]), "+f"(d[3])
        : "r"(a[0]), "r"(a[1]), "r"(a[2]), "r"(a[3]), "r"(b0), "r"(b1));
}

// ---------------------------------------------------------------------------
// conv3x3 via mma.sync bf16 hi/lo split (implicit GEMM, per-tap shifts).
// CTA: 256 thr, M=128 pixels (2 rows x 64 cols), N=64 co, ci-chunks of 16.
// smem ~79.5KB -> 2 CTAs/SM (16 warps). grid.x = batch*32, grid.y = CO/64.
// ---------------------------------------------------------------------------
#define CILD 24            // halfword stride per cell (48B = 3*16B)
#define CWTAP 1536         // 64 co * CILD
#define CONV_IH 0
#define CONV_IL 6528       // 4*68*24
#define CONV_WH 13056
#define CONV_WL 26880      // +9*64*24
#define CONV_SMEM 81408    // 40704 halfwords * 2B

template <int CI, int CO, bool RELU, bool BIAS>
__global__ __launch_bounds__(256, 2) void conv3x3_mma_k(
    const float* __restrict__ in, const float* __restrict__ wt,
    const float* __restrict__ bias, float* __restrict__ out) {
    extern __shared__ __align__(16) unsigned short cs[];
    unsigned short* ih = cs + CONV_IH;
    unsigned short* il = cs + CONV_IL;
    unsigned short* wh = cs + CONV_WH;
    unsigned short* wl = cs + CONV_WL;
    int t = threadIdx.x, w = t >> 5, lane = t & 31;
    int b = blockIdx.x >> 5, rb = blockIdx.x & 31, r0 = rb * 2;
    int coB = blockIdx.y * 64;
    int wmB = (w & 3) * 32;
    int wnB = (w >> 2) * 32;

    unsigned ihA = (unsigned)__cvta_generic_to_shared(ih);
    unsigned ilA = (unsigned)__cvta_generic_to_shared(il);
    unsigned whA = (unsigned)__cvta_generic_to_shared(wh);
    unsigned wlA = (unsigned)__cvta_generic_to_shared(wl);

    // zero input hi+lo (halo cols/rows stay zero; interior rewritten per chunk)
    for (int i = t; i < 6528; i += 256) ((unsigned*)cs)[i] = 0u;

    float acc[2][16];
#pragma unroll
    for (int mb = 0; mb < 2; ++mb)
#pragma unroll
        for (int i = 0; i < 16; ++i) acc[mb][i] = 0.f;

#pragma unroll 1
    for (int cc = 0; cc < CI / 16; ++cc) {
        __syncthreads();
        // stage input chunk: 4096 elems, 16/thread, MLP=8
#pragma unroll 1
        for (int it = 0; it < 16; it += 8) {
            float v[8];
            int idx[8];
#pragma unroll
            for (int j = 0; j < 8; ++j) {
                int i = t + (it + j) * 256;
                int col = i & 63, row = (i >> 6) & 3, ci = i >> 8;
                int imgrow = r0 - 1 + row;
                float u = 0.f;
                if ((unsigned)imgrow < 64u)
                    u = in[((size_t)b * CI + cc * 16 + ci) * 4096 + imgrow * 64 +
                           col];
                v[j] = RELU ? fmaxf(u, 0.f) : u;
                idx[j] = (row * 68 + col + 1) * CILD + ci;
            }
#pragma unroll
            for (int j = 0; j < 8; ++j) {
                unsigned short h = f2b(v[j]);
                ih[idx[j]] = h;
                il[idx[j]] = f2b(v[j] - b2f(h));
            }
        }
        // stage weights chunk: 9216 elems, 36/thread, MLP=6
#pragma unroll 1
        for (int it = 0; it < 36; it += 6) {
            float v[6];
            int idx[6];
#pragma unroll
            for (int j = 0; j < 6; ++j) {
                int i = t + (it + j) * 256;
                int co = i / 144, g = i - co * 144;
                int ci = g / 9, tap = g - ci * 9;
                v[j] = wt[(size_t)(coB + co) * (CI * 9) + (cc * 16 + ci) * 9 + tap];
                idx[j] = tap * CWTAP + co * CILD + ci;
            }
#pragma unroll
            for (int j = 0; j < 6; ++j) {
                unsigned short h = f2b(v[j]);
                wh[idx[j]] = h;
                wl[idx[j]] = f2b(v[j] - b2f(h));
            }
        }
        __syncthreads();

#pragma unroll 1
        for (int tap = 0; tap < 9; ++tap) {
            int dh = tap / 3, dw = tap - dh * 3;
            unsigned ah[2][4], al[2][4], bh[2][4], bl[2][4];
#pragma unroll
            for (int mb = 0; mb < 2; ++mb) {
                int p = wmB + mb * 16 + (lane & 15);
                int trow = (p >> 6) + dh;
                int tcol = (p & 63) + dw;
                unsigned aoff =
                    (unsigned)((trow * 68 + tcol) * CILD + ((lane >> 4) << 3)) * 2;
                ldsm4(ah[mb], ihA + aoff);
                ldsm4(al[mb], ilA + aoff);
            }
            int brow = wnB + (lane & 7) + (((lane >> 4) & 1) << 3);
            unsigned bo0 =
                (unsigned)(tap * CWTAP + brow * CILD + (((lane >> 3) & 1) << 3)) * 2;
            unsigned bo1 = bo0 + 16 * CILD * 2;
            ldsm4(bh[0], whA + bo0);
            ldsm4(bh[1], whA + bo1);
            ldsm4(bl[0], wlA + bo0);
            ldsm4(bl[1], wlA + bo1);
#pragma unroll
            for (int mb = 0; mb < 2; ++mb) {
                mma16816(&acc[mb][0], ah[mb], bh[0][0], bh[0][1]);
                mma16816(&acc[mb][0], ah[mb], bl[0][0], bl[0][1]);
                mma16816(&acc[mb][0], al[mb], bh[0][0], bh[0][1]);
                mma16816(&acc[mb][4], ah[mb], bh[0][2], bh[0][3]);
                mma16816(&acc[mb][4], ah[mb], bl[0][2], bl[0][3]);
                mma16816(&acc[mb][4], al[mb], bh[0][2], bh[0][3]);
                mma16816(&acc[mb][8], ah[mb], bh[1][0], bh[1][1]);
                mma16816(&acc[mb][8], ah[mb], bl[1][0], bl[1][1]);
                mma16816(&acc[mb][8], al[mb], bh[1][0], bh[1][1]);
                mma16816(&acc[mb][12], ah[mb], bh[1][2], bh[1][3]);
                mma16816(&acc[mb][12], ah[mb], bl[1][2], bl[1][3]);
                mma16816(&acc[mb][12], al[mb], bh[1][2], bh[1][3]);
            }
        }
    }

    size_t ob = (size_t)b * CO * 4096;
#pragma unroll
    for (int mb = 0; mb < 2; ++mb) {
        int p0 = wmB + mb * 16 + (lane >> 2);
#pragma unroll
        for (int nb = 0; nb < 4; ++nb) {
            int n = coB + wnB + nb * 8 + ((lane & 3) << 1);
            float bs0 = BIAS ? bias[n] : 0.f;
            float bs1 = BIAS ? bias[n + 1] : 0.f;
#pragma unroll
            for (int rr = 0; rr < 2; ++rr) {
                int p = p0 + rr * 8;
                int orow = r0 + (p >> 6), ocol = p & 63;
                out[ob + (size_t)n * 4096 + orow * 64 + ocol] =
                    acc[mb][nb * 4 + rr * 2] + bs0;
                out[ob + (size_t)(n + 1) * 4096 + orow * 64 + ocol] =
                    acc[mb][nb * 4 + rr * 2 + 1] + bs1;
            }
        }
    }
}

// 1x1 conv (relu(t)@w2) + residual add; CI=128, 16 co per block, 2 px/thread
__global__ __launch_bounds__(256) void conv1x1_add_k(const float* __restrict__ tin,
                                                     const float* __restrict__ wt,
                                                     float* __restrict__ lio) {
    __shared__ __align__(16) float wsh[128 * 16];
    int tid = threadIdx.x;
    int p0 = blockIdx.x * 512 + 2 * tid;
    int b = p0 >> 12, hw = p0 & 4095;
    int coBase = blockIdx.y * 16;
    for (int i = tid; i < 2048; i += 256) {
        int o = i >> 7, ci = i & 127;
        wsh[ci * 16 + o] = wt[(size_t)(coBase + o) * 128 + ci];
    }
    __syncthreads();
    unsigned long long acc2[16];
    size_t lb = ((size_t)b * 256 + coBase) * 4096 + hw;
#pragma unroll
    for (int q = 0; q < 8; ++q) {
        float2 v = *(const float2*)&lio[lb + (size_t)(2 * q) * 4096];
        float2 u = *(const float2*)&lio[lb + (size_t)(2 * q + 1) * 4096];
        acc2[2 * q] = pk2(v.x, u.x);
        acc2[2 * q + 1] = pk2(v.y, u.y);
    }
    const float* tb = tin + (size_t)b * 128 * 4096 + hw;
#pragma unroll 1
    for (int ci = 0; ci < 128; ci += 8) {
        float2 v[8];
#pragma unroll
        for (int j = 0; j < 8; ++j) {
            float2 u = *(const float2*)&tb[(size_t)(ci + j) * 4096];
            v[j].x = fmaxf(u.x, 0.f);
            v[j].y = fmaxf(u.y, 0.f);
        }
#pragma unroll
        for (int j = 0; j < 8; ++j) {
            unsigned long long v0 = pk2(v[j].x, v[j].x);
            unsigned long long v1 = pk2(v[j].y, v[j].y);
            const ulonglong2* wp = (const ulonglong2*)&wsh[(ci + j) * 16];
#pragma unroll
            for (int q = 0; q < 4; ++q) {
                ulonglong2 wq = wp[q];
                ffma2(acc2[4 * q], wq.x, v0);
                ffma2(acc2[4 * q + 1], wq.x, v1);
                ffma2(acc2[4 * q + 2], wq.y, v0);
                ffma2(acc2[4 * q + 3], wq.y, v1);
            }
        }
    }
#pragma unroll
    for (int q = 0; q < 8; ++q) {
        float a0, a1, b0_, b1_;
        upk2(acc2[2 * q], a0, b0_);
        upk2(acc2[2 * q + 1], a1, b1_);
        float2 o0 = {a0, a1}, o1 = {b0_, b1_};
        *(float2*)&lio[lb + (size_t)(2 * q) * 4096] = o0;
        *(float2*)&lio[lb + (size_t)(2 * q + 1) * 4096] = o1;
    }
}

__global__ __launch_bounds__(256) void pool_k(const float* __restrict__ l,
                                              float* __restrict__ avg,
                                              float* __restrict__ mx) {
    __shared__ float ss[256], sm[256];
    int bc = blockIdx.x, t = threadIdx.x;
    const float4* p = (const float4*)(l + (size_t)bc * 4096);
    float s = 0.f, m = -3.4e38f;
    for (int i = t; i < 1024; i += 256) {
        float4 v = p[i];
        s += v.x + v.y + v.z + v.w;
        m = fmaxf(m, fmaxf(fmaxf(v.x, v.y), fmaxf(v.z, v.w)));
    }
    ss[t] = s;
    sm[t] = m;
    __syncthreads();
    for (int st = 128; st > 0; st >>= 1) {
        if (t < st) {
            ss[t] += ss[t + st];
            sm[t] = fmaxf(sm[t], sm[t + st]);
        }
        __syncthreads();
    }
    if (t == 0) {
        avg[bc] = ss[0] * (1.f / 4096.f);
        mx[bc] = sm[0];
    }
}

__global__ void camlp_k(const float* __restrict__ avg, const float* __restrict__ mx,
                        const float* __restrict__ w1, const float* __restrict__ w2,
                        float* __restrict__ sca) {
    __shared__ float hsh[128];
    int t = threadIdx.x;
    if (t < 128) {
        int b = t >> 4, j = t & 15;
        float a = 0.f, m = 0.f;
        for (int c = 0; c < 256; ++c) {
            float w = w1[j * 256 + c];
            a += avg[b * 256 + c] * w;
            m += mx[b * 256 + c] * w;
        }
        hsh[b * 16 + j] = fmaxf(a, 0.f) + fmaxf(m, 0.f);
    }
    __syncthreads();
    for (int b = 0; b < 8; ++b) {
        float o = 0.f;
#pragma unroll
        for (int j = 0; j < 16; ++j) o += hsh[b * 16 + j] * w2[t * 16 + j];
        sca[b * 256 + t] = 1.f / (1.f + expf(-o));
    }
}

__global__ __launch_bounds__(256) void chan_k(float* __restrict__ l,
                                              const float* __restrict__ sca,
                                              float* __restrict__ s2m,
                                              float* __restrict__ s2x) {
    int tid = threadIdx.x;
    int p0 = blockIdx.x * 512 + 2 * tid;
    int b = p0 >> 12, hw = p0 & 4095;
    size_t base = (size_t)b * 256 * 4096 + hw;
    float s0 = 0.f, s1 = 0.f, m0 = -3.4e38f, m1 = -3.4e38f;
#pragma unroll 1
    for (int c = 0; c < 256; c += 8) {
        float2 v[8];
#pragma unroll
        for (int j = 0; j < 8; ++j) {
            float2 u = *(float2*)&l[base + (size_t)(c + j) * 4096];
            float sc = sca[b * 256 + c + j];
            v[j].x = u.x * sc;
            v[j].y = u.y * sc;
        }
#pragma unroll
        for (int j = 0; j < 8; ++j) {
            *(float2*)&l[base + (size_t)(c + j) * 4096] = v[j];
            s0 += v[j].x;
            s1 += v[j].y;
            m0 = fmaxf(m0, v[j].x);
            m1 = fmaxf(m1, v[j].y);
        }
    }
    s2m[p0] = s0 * (1.f / 256.f);
    s2m[p0 + 1] = s1 * (1.f / 256.f);
    s2x[p0] = m0;
    s2x[p0 + 1] = m1;
}

__global__ void sconv_k(const float* __restrict__ s2m, const float* __restrict__ s2x,
                        const float* __restrict__ sw, float* __restrict__ satt) {
    int p = blockIdx.x * 256 + threadIdx.x;
    int b = p >> 12, hw = p & 4095, h = hw >> 6, w = hw & 63;
    float a = 0.f;
#pragma unroll
    for (int kh = 0; kh < 3; ++kh) {
        int hh = h + kh - 1;
        if ((unsigned)hh >= 64u) continue;
#pragma unroll
        for (int kw = 0; kw < 3; ++kw) {
            int ww = w + kw - 1;
            if ((unsigned)ww >= 64u) continue;
            int q = b * 4096 + hh * 64 + ww;
            a += s2m[q] * sw[kh * 3 + kw] + s2x[q] * sw[9 + kh * 3 + kw];
        }
    }
    satt[p] = 1.f / (1.f + expf(-a));
}

__global__ void lamT_k(const float* __restrict__ l, const float* __restrict__ satt,
                       const float* __restrict__ Lp, float* __restrict__ lam) {
    __shared__ float tile[32][33];
    int pb = blockIdx.x * 32, cb = blockIdx.y * 32;
    int tx = threadIdx.x, ty = threadIdx.y;
    int b = pb >> 12, pl = pb & 4095;
#pragma unroll
    for (int k = 0; k < 4; ++k) {
        int c = cb + ty + 8 * k;
        tile[ty + 8 * k][tx] = l[((size_t)b * 256 + c) * 4096 + pl + tx];
    }
    __syncthreads();
    float invL = 1.f / Lp[0];
#pragma unroll
    for (int k = 0; k < 4; ++k) {
        int p2 = pb + ty + 8 * k;
        float sc = satt[p2] * invL;
        lam[(size_t)p2 * 256 + cb + tx] = tile[tx][ty + 8 * k] * sc;
    }
}

// ---------------------------------------------------------------------------
// LISTA via mma.sync bf16 (hi/lo split), residual form (unchanged from R10)
// ---------------------------------------------------------------------------
#define ZH_OFF 0
#define ZL_OFF 33792
#define EH_OFF 67584
#define EL_OFF 76800
#define DH_OFF 86016
#define DL_OFF 119808
#define LAM_OFF 153600
#define LISTA_SMEM 220416
#define LDZ 264
#define LDE 72
#define LDD 264
#define LDL 261

__device__ __forceinline__ void run_step1(float R[16], unsigned zhA, unsigned zlA,
                                          unsigned dhA, unsigned dlA, int mB1,
                                          int cB1, int lane) {
#pragma unroll
    for (int i = 0; i < 16; ++i) R[i] = 0.f;
    int arow = mB1 * 16 + (lane & 15);
    int acolg = (lane >> 4) << 3;
    int brow0 = cB1 + (lane & 7) + (((lane >> 4) & 1) << 3);
    int bcolg = (((lane >> 3) & 1) << 3);
#pragma unroll 2
    for (int ks = 0; ks < 16; ++ks) {
        int k0 = ks * 16;
        unsigned ah[4], al[4], bh0[4], bh1[4], bl0[4], bl1[4];
        unsigned aoff = (unsigned)((arow * LDZ + k0 + acolg) * 2);
        ldsm4(ah, zhA + aoff);
        ldsm4(al, zlA + aoff);
        unsigned boff0 = (unsigned)((brow0 * LDD + k0 + bcolg) * 2);
        unsigned boff1 = (unsigned)(((brow0 + 16) * LDD + k0 + bcolg) * 2);
        ldsm4(bh0, dhA + boff0);
        ldsm4(bl0, dlA + boff0);
        ldsm4(bh1, dhA + boff1);
        ldsm4(bl1, dlA + boff1);
        mma16816(&R[0], ah, bh0[0], bh0[1]);
        mma16816(&R[0], ah, bl0[0], bl0[1]);
        mma16816(&R[0], al, bh0[0], bh0[1]);
        mma16816(&R[4], ah, bh0[2], bh0[3]);
        mma16816(&R[4], ah, bl0[2], bl0[3]);
        mma16816(&R[4], al, bh0[2], bh0[3]);
        mma16816(&R[8], ah, bh1[0], bh1[1]);
        mma16816(&R[8], ah, bl1[0], bl1[1]);
        mma16816(&R[8], al, bh1[0], bh1[1]);
        mma16816(&R[12], ah, bh1[2], bh1[3]);
        mma16816(&R[12], ah, bl1[2], bl1[3]);
        mma16816(&R[12], al, bh1[2], bh1[3]);
    }
}

__device__ __forceinline__ void run_step2(float q[64], unsigned ehA, unsigned elA,
                                          const unsigned short* dh,
                                          const unsigned short* dl, int mB2,
                                          int aB2, int lane) {
#pragma unroll
    for (int i = 0; i < 64; ++i) q[i] = 0.f;
    int arow = mB2 * 32 + (lane & 15);
    int acolg = (lane >> 4) << 3;
    int acol_b = aB2 + (lane >> 2);
    int kr_b = (lane & 3) << 1;
#pragma unroll
    for (int ks = 0; ks < 4; ++ks) {
        int k0 = ks * 16;
        unsigned ah0[4], al0[4], ah1[4], al1[4];
        unsigned aoff0 = (unsigned)((arow * LDE + k0 + acolg) * 2);
        unsigned aoff1 = (unsigned)(((arow + 16) * LDE + k0 + acolg) * 2);
        ldsm4(ah0, ehA + aoff0);
        ldsm4(al0, elA + aoff0);
        ldsm4(ah1, ehA + aoff1);
        ldsm4(al1, elA + aoff1);
        int kr = k0 + kr_b;
#pragma unroll
        for (int nt = 0; nt < 8; ++nt) {
            int ac = acol_b + nt * 8;
            unsigned h0 = (unsigned)dh[kr * LDD + ac] |
                          ((unsigned)dh[(kr + 1) * LDD + ac] << 16);
            unsigned h1 = (unsigned)dh[(kr + 8) * LDD + ac] |
                          ((unsigned)dh[(kr + 9) * LDD + ac] << 16);
            unsigned l0 = (unsigned)dl[kr * LDD + ac] |
                          ((unsigned)dl[(kr + 1) * LDD + ac] << 16);
            unsigned l1 = (unsigned)dl[(kr + 8) * LDD + ac] |
                          ((unsigned)dl[(kr + 9) * LDD + ac] << 16);
            mma16816(&q[nt * 4], ah0, h0, h1);
            mma16816(&q[nt * 4], ah0, l0, l1);
            mma16816(&q[nt * 4], al0, h0, h1);
            mma16816(&q[32 + nt * 4], ah1, h0, h1);
            mma16816(&q[32 + nt * 4], ah1, l0, l1);
            mma16816(&q[32 + nt * 4], al1, h0, h1);
        }
    }
}

__global__ __launch_bounds__(256, 1) void lista_mma_k(
    const float* __restrict__ x, const float* __restrict__ Dict,
    const float* __restrict__ Lp, const int* __restrict__ nip,
    const float* __restrict__ lam_g, float* __restrict__ out_z,
    float* __restrict__ out_r) {
    extern __shared__ __align__(16) char smem[];
    unsigned short* zh = (unsigned short*)(smem + ZH_OFF);
    unsigned short* zl = (unsigned short*)(smem + ZL_OFF);
    unsigned short* eh = (unsigned short*)(smem + EH_OFF);
    unsigned short* el = (unsigned short*)(smem + EL_OFF);
    unsigned short* dh = (unsigned short*)(smem + DH_OFF);
    unsigned short* dl = (unsigned short*)(smem + DL_OFF);
    float* lam = (float*)(smem + LAM_OFF);
    float* xrec = (float*)(smem + EH_OFF);
    float* zfp = lam;

    int t = threadIdx.x, w = t >> 5, lane = t & 31;
    int mB1 = w & 3, cB1 = (w >> 2) * 32;
    int mB2 = w & 1, aB2 = (w >> 1) * 64;
    int pbase = blockIdx.x * 64;
    int b = pbase >> 12, pl = pbase & 4095;
    float invL = 1.f / Lp[0];
    int niters = nip[0];

    unsigned zhA = (unsigned)__cvta_generic_to_shared(zh);
    unsigned zlA = (unsigned)__cvta_generic_to_shared(zl);
    unsigned ehA = (unsigned)__cvta_generic_to_shared(eh);
    unsigned elA = (unsigned)__cvta_generic_to_shared(el);
    unsigned dhA = (unsigned)__cvta_generic_to_shared(dh);
    unsigned dlA = (unsigned)__cvta_generic_to_shared(dl);

    for (int i = t; i < 16384; i += 256) {
        int m = i >> 8, a = i & 255;
        lam[m * LDL + a] = lam_g[(size_t)(pbase + m) * 256 + a];
    }
    for (int i = t; i < 16384; i += 256) {
        int c = i >> 8, a = i & 255;
        float v = Dict[i];
        unsigned short h = f2b(v);
        dh[c * LDD + a] = h;
        dl[c * LDD + a] = f2b(v - b2f(h));
    }
    size_t xofs = (size_t)b * 64 * 4096 + pl;
    for (int i = t; i < 4096; i += 256) {
        int c = i >> 6, m = i & 63;
        float v = x[xofs + (size_t)c * 4096 + m];
        unsigned short h = f2b(v);
        eh[m * LDE + c] = h;
        el[m * LDE + c] = f2b(v - b2f(h));
    }
    __syncthreads();

    float xfrag[16];
    {
        int r0 = mB1 * 16 + (lane >> 2);
#pragma unroll
        for (int nt = 0; nt < 4; ++nt) {
            int c2 = cB1 + nt * 8 + ((lane & 3) << 1);
            xfrag[nt * 4 + 0] = x[((size_t)b * 64 + c2) * 4096 + pl + r0];
            xfrag[nt * 4 + 1] = x[((size_t)b * 64 + c2 + 1) * 4096 + pl + r0];
            xfrag[nt * 4 + 2] = x[((size_t)b * 64 + c2) * 4096 + pl + r0 + 8];
            xfrag[nt * 4 + 3] = x[((size_t)b * 64 + c2 + 1) * 4096 + pl + r0 + 8];
        }
    }

    {
        float q[64];
        run_step2(q, ehA, elA, dh, dl, mB2, aB2, lane);
        bool wz = (niters == 0);
#pragma unroll
        for (int blk = 0; blk < 2; ++blk)
#pragma unroll
            for (int nt = 0; nt < 8; ++nt) {
                int r = mB2 * 32 + blk * 16 + (lane >> 2);
                int a2 = aB2 + nt * 8 + ((lane & 3) << 1);
                const float* qq = &q[blk * 32 + nt * 4];
#pragma unroll
                for (int rr = 0; rr < 2; ++rr) {
                    int row = r + rr * 8;
                    float y0 = qq[rr * 2], y1 = qq[rr * 2 + 1];
                    float l0 = lam[row * LDL + a2], l1 = lam[row * LDL + a2 + 1];
                    float g0 = fmaxf(fabsf(y0) - l0, 0.f);
                    float g1 = fmaxf(fabsf(y1) - l1, 0.f);
                    float z0 = (y0 > 0.f) ? g0 : -g0;
                    float z1 = (y1 > 0.f) ? g1 : -g1;
                    unsigned short h0 = f2b(z0), h1 = f2b(z1);
                    *(unsigned*)&zh[row * LDZ + a2] =
                        (unsigned)h0 | ((unsigned)h1 << 16);
                    *(unsigned*)&zl[row * LDZ + a2] =
                        (unsigned)f2b(z0 - b2f(h0)) |
                        ((unsigned)f2b(z1 - b2f(h1)) << 16);
                    if (wz) {
                        zfp[row * LDL + a2] = z0;
                        zfp[row * LDL + a2 + 1] = z1;
                    }
                }
            }
    }
    __syncthreads();

    for (int it = 0; it < niters; ++it) {
        float R[16];
        run_step1(R, zhA, zlA, dhA, dlA, mB1, cB1, lane);
        {
            int r0 = mB1 * 16 + (lane >> 2);
#pragma unroll
            for (int nt = 0; nt < 4; ++nt) {
                int c2 = cB1 + nt * 8 + ((lane & 3) << 1);
#pragma unroll
                for (int rr = 0; rr < 2; ++rr) {
                    int row = r0 + rr * 8;
                    float e0 = xfrag[nt * 4 + rr * 2] - R[nt * 4 + rr * 2];
                    float e1 = xfrag[nt * 4 + rr * 2 + 1] - R[nt * 4 + rr * 2 + 1];
                    unsigned short h0 = f2b(e0), h1 = f2b(e1);
                    *(unsigned*)&eh[row * LDE + c2] =
                        (unsigned)h0 | ((unsigned)h1 << 16);
                    *(unsigned*)&el[row * LDE + c2] =
                        (unsigned)f2b(e0 - b2f(h0)) |
                        ((unsigned)f2b(e1 - b2f(h1)) << 16);
                }
            }
        }
        __syncthreads();
        float q[64];
        run_step2(q, ehA, elA, dh, dl, mB2, aB2, lane);
        bool wz = (it == niters - 1);
#pragma unroll
        for (int blk = 0; blk < 2; ++blk)
#pragma unroll
            for (int nt = 0; nt < 8; ++nt) {
                int r = mB2 * 32 + blk * 16 + (lane >> 2);
                int a2 = aB2 + nt * 8 + ((lane & 3) << 1);
                const float* qq = &q[blk * 32 + nt * 4];
#pragma unroll
                for (int rr = 0; rr < 2; ++rr) {
                    int row = r + rr * 8;
                    unsigned hz = *(unsigned*)&zh[row * LDZ + a2];
                    unsigned lz = *(unsigned*)&zl[row * LDZ + a2];
                    float zo0 = b2f(hz & 0xffffu) + b2f(lz & 0xffffu);
                    float zo1 = b2f(hz >> 16) + b2f(lz >> 16);
                    float w0 = zo0 + qq[rr * 2] * invL;
                    float w1 = zo1 + qq[rr * 2 + 1] * invL;
                    float l0 = lam[row * LDL + a2], l1 = lam[row * LDL + a2 + 1];
                    float g0 = fmaxf(fabsf(w0) - l0, 0.f);
                    float g1 = fmaxf(fabsf(w1) - l1, 0.f);
                    float z0 = (w0 > 0.f) ? g0 : -g0;
                    float z1 = (w1 > 0.f) ? g1 : -g1;
                    unsigned short h0 = f2b(z0), h1 = f2b(z1);
                    *(unsigned*)&zh[row * LDZ + a2] =
                        (unsigned)h0 | ((unsigned)h1 << 16);
                    *(unsigned*)&zl[row * LDZ + a2] =
                        (unsigned)f2b(z0 - b2f(h0)) |
                        ((unsigned)f2b(z1 - b2f(h1)) << 16);
                    if (wz) {
                        zfp[row * LDL + a2] = z0;
                        zfp[row * LDL + a2 + 1] = z1;
                    }
                }
            }
        __syncthreads();
    }

    {
        float R[16];
        run_step1(R, zhA, zlA, dhA, dlA, mB1, cB1, lane);
        __syncthreads();
        int r0 = mB1 * 16 + (lane >> 2);
#pragma unroll
        for (int nt = 0; nt < 4; ++nt) {
            int c2 = cB1 + nt * 8 + ((lane & 3) << 1);
            xrec[r0 * 65 + c2] = R[nt * 4 + 0];
            xrec[r0 * 65 + c2 + 1] = R[nt * 4 + 1];
            xrec[(r0 + 8) * 65 + c2] = R[nt * 4 + 2];
            xrec[(r0 + 8) * 65 + c2 + 1] = R[nt * 4 + 3];
        }
    }
    __syncthreads();

    size_t zofs = (size_t)b * 256 * 4096 + pl;
    for (int i = t; i < 16384; i += 256) {
        int a = i >> 6, m = i & 63;
        out_z[zofs + (size_t)a * 4096 + m] = zfp[m * LDL + a];
    }
    size_t rofs = (size_t)b * 64 * 4096 + pl;
    for (int i = t; i < 4096; i += 256) {
        int c = i >> 6, m = i & 63;
        out_r[rofs + (size_t)c * 4096 + m] = xrec[m * 65 + c];
    }
}

__global__ void copy_k(const float* __restrict__ s, float* __restrict__ d, int n) {
    int i = blockIdx.x * blockDim.x + threadIdx.x;
    if (i < n) d[i] = s[i];
}

extern "C" void kernel_launch(void* const* d_in, const int* in_sizes, int n_in,
                              void* d_out, int out_size) {
    const float* x = (const float*)d_in[0];
    const float* conv_w = (const float*)d_in[1];
    const float* conv_b = (const float*)d_in[2];
    const float* r1w1 = (const float*)d_in[3];
    const float* r1w2 = (const float*)d_in[4];
    const float* r2w1 = (const float*)d_in[5];
    const float* r2w2 = (const float*)d_in[6];
    const float* caw1 = (const float*)d_in[7];
    const float* caw2 = (const float*)d_in[8];
    const float* saw = (const float*)d_in[9];
    const float* Dict = (const float*)d_in[10];
    const float* Lp = (const float*)d_in[11];
    const int* nip = (const int*)d_in[12];
    float* out = (float*)d_out;

    float *l, *tb, *avg, *mx, *sca, *s2m, *s2x, *satt, *lam;
    cudaGetSymbolAddress((void**)&l, g_l);
    cudaGetSymbolAddress((void**)&tb, g_t);
    cudaGetSymbolAddress((void**)&avg, g_avg);
    cudaGetSymbolAddress((void**)&mx, g_mx);
    cudaGetSymbolAddress((void**)&sca, g_sca);
    cudaGetSymbolAddress((void**)&s2m, g_s2m);
    cudaGetSymbolAddress((void**)&s2x, g_s2x);
    cudaGetSymbolAddress((void**)&satt, g_satt);
    cudaGetSymbolAddress((void**)&lam, g_lam);

    cudaFuncSetAttribute(conv3x3_mma_k<64, 256, false, true>,
                         cudaFuncAttributeMaxDynamicSharedMemorySize, CONV_SMEM);
    cudaFuncSetAttribute(conv3x3_mma_k<256, 128, true, false>,
                         cudaFuncAttributeMaxDynamicSharedMemorySize, CONV_SMEM);

    conv3x3_mma_k<64, 256, false, true>
        <<<dim3(256, 4), 256, CONV_SMEM>>>(x, conv_w, conv_b, l);
    conv3x3_mma_k<256, 128, true, false>
        <<<dim3(256, 2), 256, CONV_SMEM>>>(l, r1w1, nullptr, tb);
    conv1x1_add_k<<<dim3(64, 16), 256>>>(tb, r1w2, l);
    conv3x3_mma_k<256, 128, true, false>
        <<<dim3(256, 2), 256, CONV_SMEM>>>(l, r2w1, nullptr, tb);
    conv1x1_add_k<<<dim3(64, 16), 256>>>(tb, r2w2, l);
    pool_k<<<2048, 256>>>(l, avg, mx);
    camlp_k<<<1, 256>>>(avg, mx, caw1, caw2, sca);
    chan_k<<<64, 256>>>(l, sca, s2m, s2x);
    sconv_k<<<128, 256>>>(s2m, s2x, saw, satt);
    lamT_k<<<dim3(1024, 8), dim3(32, 8)>>>(l, satt, Lp, lam);

    cudaFuncSetAttribute(lista_mma_k, cudaFuncAttributeMaxDynamicSharedMemorySize,
                         LISTA_SMEM);
    lista_mma_k<<<512, 256, LISTA_SMEM>>>(x, Dict, Lp, nip, lam,
                                          out, out + 8 * 256 * 4096);
    copy_k<<<64, 256>>>(Dict, out + 8 * 256 * 4096 + 8 * 64 * 4096, 64 * 256);
}

// round 14
// speedup vs baseline: 2.4578x; 1.1307x over previous
#include <cuda_runtime.h>
#include <cuda_bf16.h>
#include <cstdint>

__device__ float g_l[8 * 256 * 4096];
__device__ float g_t[8 * 128 * 4096];
__device__ float g_lam[8 * 4096 * 256];
__device__ float g_avg[8 * 256];
__device__ float g_mx[8 * 256];
__device__ float g_sca[8 * 256];
__device__ float g_s2m[8 * 4096];
__device__ float g_s2x[8 * 4096];
__device__ float g_satt[8 * 4096];

__device__ __forceinline__ unsigned long long pk2(float a, float b) {
    unsigned long long r;
    asm("mov.b64 %0, {%1, %2};" : "=l"(r) : "f"(a), "f"(b));
    return r;
}
__device__ __forceinline__ void upk2(unsigned long long v, float& a, float& b) {
    asm("mov.b64 {%0, %1}, %2;" : "=f"(a), "=f"(b) : "l"(v));
}
__device__ __forceinline__ void ffma2(unsigned long long& d, unsigned long long a,
                                      unsigned long long b) {
    asm("fma.rn.f32x2 %0, %1, %2, %0;" : "+l"(d) : "l"(a), "l"(b));
}

__device__ __forceinline__ float b2f(unsigned u) {
    return __uint_as_float(u << 16);
}
__device__ __forceinline__ unsigned short f2b(float f) {
    __nv_bfloat16 h = __float2bfloat16(f);
    return *(unsigned short*)&h;
}
__device__ __forceinline__ void ldsm4(unsigned r[4], unsigned addr) {
    asm volatile("ldmatrix.sync.aligned.m8n8.x4.shared.b16 {%0,%1,%2,%3}, [%4];"
                 : "=r"(r[0]), "=r"(r[1]), "=r"(r[2]), "=r"(r[3])
                 : "r"(addr));
}
__device__ __forceinline__ void mma16816(float d[4], const unsigned a[4],
                                         unsigned b0, unsigned b1) {
    asm volatile(
        "mma.sync.aligned.m16n8k16.row.col.f32.bf16.bf16.f32 "
        "{%0,%1,%2,%3},{%4,%5,%6,%7},{%8,%9},{%0,%1,%2,%3};"
        : "+f"(d[0]), "+f"(d[1]), "+f"(d[2]), "+f"(d[3])
        : "r"(a[0]), "r"(a[1]), "r"(a[2]), "r"(a[3]), "r"(b0), "r"(b1));
}

// ---------------------------------------------------------------------------
// conv3x3 via mma.sync bf16 hi/lo split (implicit GEMM, per-tap shifts).
// CTA: 256 thr, M=256 pixels (4 rows x 64 cols), N=64 co, ci-chunks of 16.
// Warp tile 32x64 (ratio 4 MMA/ldsm). smem 94.5KB -> 2 CTAs/SM.
// grid.x = batch*16 rowblocks, grid.y = CO/64.
// ---------------------------------------------------------------------------
#define CILD 24            // halfword stride per cell (48B)
#define CWTAP 1536         // 64 co * CILD
#define CONV_IH 0
#define CONV_IL 9792       // 6*68*24
#define CONV_WH 19584
#define CONV_WL 33408      // +9*64*24
#define CONV_SMEM 94464    // 47232 halfwords * 2B

template <int CI, int CO, bool RELU, bool BIAS>
__global__ __launch_bounds__(256, 2) void conv3x3_mma_k(
    const float* __restrict__ in, const float* __restrict__ wt,
    const float* __restrict__ bias, float* __restrict__ out) {
    extern __shared__ __align__(16) unsigned short cs[];
    unsigned short* ih = cs + CONV_IH;
    unsigned short* il = cs + CONV_IL;
    unsigned short* wh = cs + CONV_WH;
    unsigned short* wl = cs + CONV_WL;
    int t = threadIdx.x, w = t >> 5, lane = t & 31;
    int b = blockIdx.x >> 4, rb = blockIdx.x & 15, r0 = rb * 4;
    int coB = blockIdx.y * 64;
    int wmB = w * 32;  // warp pixel base (8 m-groups of 32)

    unsigned ihA = (unsigned)__cvta_generic_to_shared(ih);
    unsigned ilA = (unsigned)__cvta_generic_to_shared(il);
    unsigned whA = (unsigned)__cvta_generic_to_shared(wh);
    unsigned wlA = (unsigned)__cvta_generic_to_shared(wl);

    // zero input hi+lo (halo cols/OOB rows stay zero)
    for (int i = t; i < 9792; i += 256) ((unsigned*)cs)[i] = 0u;

    float acc[2][32];  // [mb][nt*4 + frag]
#pragma unroll
    for (int mb = 0; mb < 2; ++mb)
#pragma unroll
        for (int i = 0; i < 32; ++i) acc[mb][i] = 0.f;

#pragma unroll 1
    for (int cc = 0; cc < CI / 16; ++cc) {
        __syncthreads();
        // stage input chunk: 6 rows x 64 cols x 16 ci = 6144 elems, MLP=8
#pragma unroll 1
        for (int it = 0; it < 24; it += 8) {
            float v[8];
            int idx[8];
#pragma unroll
            for (int j = 0; j < 8; ++j) {
                int i = t + (it + j) * 256;
                int ci = i / 384, rem = i - ci * 384;
                int row = rem >> 6, col = rem & 63;
                int imgrow = r0 - 1 + row;
                float u = 0.f;
                if ((unsigned)imgrow < 64u)
                    u = in[((size_t)b * CI + cc * 16 + ci) * 4096 + imgrow * 64 +
                           col];
                v[j] = RELU ? fmaxf(u, 0.f) : u;
                idx[j] = (row * 68 + col + 1) * CILD + ci;
            }
#pragma unroll
            for (int j = 0; j < 8; ++j) {
                unsigned short h = f2b(v[j]);
                ih[idx[j]] = h;
                il[idx[j]] = f2b(v[j] - b2f(h));
            }
        }
        // stage weights chunk: 9216 elems, 36/thread, MLP=6
#pragma unroll 1
        for (int it = 0; it < 36; it += 6) {
            float v[6];
            int idx[6];
#pragma unroll
            for (int j = 0; j < 6; ++j) {
                int i = t + (it + j) * 256;
                int co = i / 144, g = i - co * 144;
                int ci = g / 9, tap = g - ci * 9;
                v[j] = wt[(size_t)(coB + co) * (CI * 9) + (cc * 16 + ci) * 9 + tap];
                idx[j] = tap * CWTAP + co * CILD + ci;
            }
#pragma unroll
            for (int j = 0; j < 6; ++j) {
                unsigned short h = f2b(v[j]);
                wh[idx[j]] = h;
                wl[idx[j]] = f2b(v[j] - b2f(h));
            }
        }
        __syncthreads();

#pragma unroll 1
        for (int tap = 0; tap < 9; ++tap) {
            int dh = tap / 3, dw = tap - dh * 3;
            unsigned ah[2][4], al[2][4];
#pragma unroll
            for (int mb = 0; mb < 2; ++mb) {
                int p = wmB + mb * 16 + (lane & 15);
                int trow = (p >> 6) + dh;
                int tcol = (p & 63) + dw;
                unsigned aoff =
                    (unsigned)((trow * 68 + tcol) * CILD + ((lane >> 4) << 3)) * 2;
                ldsm4(ah[mb], ihA + aoff);
                ldsm4(al[mb], ilA + aoff);
            }
            int brow_b = (lane & 7) + (((lane >> 4) & 1) << 3);
            unsigned bbase =
                (unsigned)(tap * CWTAP + brow_b * CILD + (((lane >> 3) & 1) << 3)) *
                2;
#pragma unroll
            for (int nt2 = 0; nt2 < 4; ++nt2) {
                unsigned bh[4], bl[4];
                unsigned bo = bbase + (unsigned)(nt2 * 16 * CILD * 2);
                ldsm4(bh, whA + bo);
                ldsm4(bl, wlA + bo);
#pragma unroll
                for (int mb = 0; mb < 2; ++mb) {
                    float* a0 = &acc[mb][nt2 * 8];
                    mma16816(&a0[0], ah[mb], bh[0], bh[1]);
                    mma16816(&a0[0], ah[mb], bl[0], bl[1]);
                    mma16816(&a0[0], al[mb], bh[0], bh[1]);
                    mma16816(&a0[4], ah[mb], bh[2], bh[3]);
                    mma16816(&a0[4], ah[mb], bl[2], bl[3]);
                    mma16816(&a0[4], al[mb], bh[2], bh[3]);
                }
            }
        }
    }

    size_t ob = (size_t)b * CO * 4096;
#pragma unroll
    for (int mb = 0; mb < 2; ++mb) {
        int p0 = wmB + mb * 16 + (lane >> 2);
#pragma unroll
        for (int nt = 0; nt < 8; ++nt) {
            int n = coB + nt * 8 + ((lane & 3) << 1);
            float bs0 = BIAS ? bias[n] : 0.f;
            float bs1 = BIAS ? bias[n + 1] : 0.f;
#pragma unroll
            for (int rr = 0; rr < 2; ++rr) {
                int p = p0 + rr * 8;
                int orow = r0 + (p >> 6), ocol = p & 63;
                out[ob + (size_t)n * 4096 + orow * 64 + ocol] =
                    acc[mb][nt * 4 + rr * 2] + bs0;
                out[ob + (size_t)(n + 1) * 4096 + orow * 64 + ocol] =
                    acc[mb][nt * 4 + rr * 2 + 1] + bs1;
            }
        }
    }
}

// 1x1 conv (relu(t)@w2) + residual add; CI=128, 16 co per block, 2 px/thread
__global__ __launch_bounds__(256) void conv1x1_add_k(const float* __restrict__ tin,
                                                     const float* __restrict__ wt,
                                                     float* __restrict__ lio) {
    __shared__ __align__(16) float wsh[128 * 16];
    int tid = threadIdx.x;
    int p0 = blockIdx.x * 512 + 2 * tid;
    int b = p0 >> 12, hw = p0 & 4095;
    int coBase = blockIdx.y * 16;
    for (int i = tid; i < 2048; i += 256) {
        int o = i >> 7, ci = i & 127;
        wsh[ci * 16 + o] = wt[(size_t)(coBase + o) * 128 + ci];
    }
    __syncthreads();
    unsigned long long acc2[16];
    size_t lb = ((size_t)b * 256 + coBase) * 4096 + hw;
#pragma unroll
    for (int q = 0; q < 8; ++q) {
        float2 v = *(const float2*)&lio[lb + (size_t)(2 * q) * 4096];
        float2 u = *(const float2*)&lio[lb + (size_t)(2 * q + 1) * 4096];
        acc2[2 * q] = pk2(v.x, u.x);
        acc2[2 * q + 1] = pk2(v.y, u.y);
    }
    const float* tb = tin + (size_t)b * 128 * 4096 + hw;
#pragma unroll 1
    for (int ci = 0; ci < 128; ci += 8) {
        float2 v[8];
#pragma unroll
        for (int j = 0; j < 8; ++j) {
            float2 u = *(const float2*)&tb[(size_t)(ci + j) * 4096];
            v[j].x = fmaxf(u.x, 0.f);
            v[j].y = fmaxf(u.y, 0.f);
        }
#pragma unroll
        for (int j = 0; j < 8; ++j) {
            unsigned long long v0 = pk2(v[j].x, v[j].x);
            unsigned long long v1 = pk2(v[j].y, v[j].y);
            const ulonglong2* wp = (const ulonglong2*)&wsh[(ci + j) * 16];
#pragma unroll
            for (int q = 0; q < 4; ++q) {
                ulonglong2 wq = wp[q];
                ffma2(acc2[4 * q], wq.x, v0);
                ffma2(acc2[4 * q + 1], wq.x, v1);
                ffma2(acc2[4 * q + 2], wq.y, v0);
                ffma2(acc2[4 * q + 3], wq.y, v1);
            }
        }
    }
#pragma unroll
    for (int q = 0; q < 8; ++q) {
        float a0, a1, b0_, b1_;
        upk2(acc2[2 * q], a0, b0_);
        upk2(acc2[2 * q + 1], a1, b1_);
        float2 o0 = {a0, a1}, o1 = {b0_, b1_};
        *(float2*)&lio[lb + (size_t)(2 * q) * 4096] = o0;
        *(float2*)&lio[lb + (size_t)(2 * q + 1) * 4096] = o1;
    }
}

__global__ __launch_bounds__(256) void pool_k(const float* __restrict__ l,
                                              float* __restrict__ avg,
                                              float* __restrict__ mx) {
    __shared__ float ss[256], sm[256];
    int bc = blockIdx.x, t = threadIdx.x;
    const float4* p = (const float4*)(l + (size_t)bc * 4096);
    float s = 0.f, m = -3.4e38f;
    for (int i = t; i < 1024; i += 256) {
        float4 v = p[i];
        s += v.x + v.y + v.z + v.w;
        m = fmaxf(m, fmaxf(fmaxf(v.x, v.y), fmaxf(v.z, v.w)));
    }
    ss[t] = s;
    sm[t] = m;
    __syncthreads();
    for (int st = 128; st > 0; st >>= 1) {
        if (t < st) {
            ss[t] += ss[t + st];
            sm[t] = fmaxf(sm[t], sm[t + st]);
        }
        __syncthreads();
    }
    if (t == 0) {
        avg[bc] = ss[0] * (1.f / 4096.f);
        mx[bc] = sm[0];
    }
}

__global__ void camlp_k(const float* __restrict__ avg, const float* __restrict__ mx,
                        const float* __restrict__ w1, const float* __restrict__ w2,
                        float* __restrict__ sca) {
    __shared__ float hsh[128];
    int t = threadIdx.x;
    if (t < 128) {
        int b = t >> 4, j = t & 15;
        float a = 0.f, m = 0.f;
        for (int c = 0; c < 256; ++c) {
            float w = w1[j * 256 + c];
            a += avg[b * 256 + c] * w;
            m += mx[b * 256 + c] * w;
        }
        hsh[b * 16 + j] = fmaxf(a, 0.f) + fmaxf(m, 0.f);
    }
    __syncthreads();
    for (int b = 0; b < 8; ++b) {
        float o = 0.f;
#pragma unroll
        for (int j = 0; j < 16; ++j) o += hsh[b * 16 + j] * w2[t * 16 + j];
        sca[b * 256 + t] = 1.f / (1.f + expf(-o));
    }
}

__global__ __launch_bounds__(256) void chan_k(float* __restrict__ l,
                                              const float* __restrict__ sca,
                                              float* __restrict__ s2m,
                                              float* __restrict__ s2x) {
    int tid = threadIdx.x;
    int p0 = blockIdx.x * 512 + 2 * tid;
    int b = p0 >> 12, hw = p0 & 4095;
    size_t base = (size_t)b * 256 * 4096 + hw;
    float s0 = 0.f, s1 = 0.f, m0 = -3.4e38f, m1 = -3.4e38f;
#pragma unroll 1
    for (int c = 0; c < 256; c += 8) {
        float2 v[8];
#pragma unroll
        for (int j = 0; j < 8; ++j) {
            float2 u = *(float2*)&l[base + (size_t)(c + j) * 4096];
            float sc = sca[b * 256 + c + j];
            v[j].x = u.x * sc;
            v[j].y = u.y * sc;
        }
#pragma unroll
        for (int j = 0; j < 8; ++j) {
            *(float2*)&l[base + (size_t)(c + j) * 4096] = v[j];
            s0 += v[j].x;
            s1 += v[j].y;
            m0 = fmaxf(m0, v[j].x);
            m1 = fmaxf(m1, v[j].y);
        }
    }
    s2m[p0] = s0 * (1.f / 256.f);
    s2m[p0 + 1] = s1 * (1.f / 256.f);
    s2x[p0] = m0;
    s2x[p0 + 1] = m1;
}

__global__ void sconv_k(const float* __restrict__ s2m, const float* __restrict__ s2x,
                        const float* __restrict__ sw, float* __restrict__ satt) {
    int p = blockIdx.x * 256 + threadIdx.x;
    int b = p >> 12, hw = p & 4095, h = hw >> 6, w = hw & 63;
    float a = 0.f;
#pragma unroll
    for (int kh = 0; kh < 3; ++kh) {
        int hh = h + kh - 1;
        if ((unsigned)hh >= 64u) continue;
#pragma unroll
        for (int kw = 0; kw < 3; ++kw) {
            int ww = w + kw - 1;
            if ((unsigned)ww >= 64u) continue;
            int q = b * 4096 + hh * 64 + ww;
            a += s2m[q] * sw[kh * 3 + kw] + s2x[q] * sw[9 + kh * 3 + kw];
        }
    }
    satt[p] = 1.f / (1.f + expf(-a));
}

__global__ void lamT_k(const float* __restrict__ l, const float* __restrict__ satt,
                       const float* __restrict__ Lp, float* __restrict__ lam) {
    __shared__ float tile[32][33];
    int pb = blockIdx.x * 32, cb = blockIdx.y * 32;
    int tx = threadIdx.x, ty = threadIdx.y;
    int b = pb >> 12, pl = pb & 4095;
#pragma unroll
    for (int k = 0; k < 4; ++k) {
        int c = cb + ty + 8 * k;
        tile[ty + 8 * k][tx] = l[((size_t)b * 256 + c) * 4096 + pl + tx];
    }
    __syncthreads();
    float invL = 1.f / Lp[0];
#pragma unroll
    for (int k = 0; k < 4; ++k) {
        int p2 = pb + ty + 8 * k;
        float sc = satt[p2] * invL;
        lam[(size_t)p2 * 256 + cb + tx] = tile[tx][ty + 8 * k] * sc;
    }
}

// ---------------------------------------------------------------------------
// LISTA via mma.sync bf16 (hi/lo split), residual form (unchanged from R10)
// ---------------------------------------------------------------------------
#define ZH_OFF 0
#define ZL_OFF 33792
#define EH_OFF 67584
#define EL_OFF 76800
#define DH_OFF 86016
#define DL_OFF 119808
#define LAM_OFF 153600
#define LISTA_SMEM 220416
#define LDZ 264
#define LDE 72
#define LDD 264
#define LDL 261

__device__ __forceinline__ void run_step1(float R[16], unsigned zhA, unsigned zlA,
                                          unsigned dhA, unsigned dlA, int mB1,
                                          int cB1, int lane) {
#pragma unroll
    for (int i = 0; i < 16; ++i) R[i] = 0.f;
    int arow = mB1 * 16 + (lane & 15);
    int acolg = (lane >> 4) << 3;
    int brow0 = cB1 + (lane & 7) + (((lane >> 4) & 1) << 3);
    int bcolg = (((lane >> 3) & 1) << 3);
#pragma unroll 2
    for (int ks = 0; ks < 16; ++ks) {
        int k0 = ks * 16;
        unsigned ah[4], al[4], bh0[4], bh1[4], bl0[4], bl1[4];
        unsigned aoff = (unsigned)((arow * LDZ + k0 + acolg) * 2);
        ldsm4(ah, zhA + aoff);
        ldsm4(al, zlA + aoff);
        unsigned boff0 = (unsigned)((brow0 * LDD + k0 + bcolg) * 2);
        unsigned boff1 = (unsigned)(((brow0 + 16) * LDD + k0 + bcolg) * 2);
        ldsm4(bh0, dhA + boff0);
        ldsm4(bl0, dlA + boff0);
        ldsm4(bh1, dhA + boff1);
        ldsm4(bl1, dlA + boff1);
        mma16816(&R[0], ah, bh0[0], bh0[1]);
        mma16816(&R[0], ah, bl0[0], bl0[1]);
        mma16816(&R[0], al, bh0[0], bh0[1]);
        mma16816(&R[4], ah, bh0[2], bh0[3]);
        mma16816(&R[4], ah, bl0[2], bl0[3]);
        mma16816(&R[4], al, bh0[2], bh0[3]);
        mma16816(&R[8], ah, bh1[0], bh1[1]);
        mma16816(&R[8], ah, bl1[0], bl1[1]);
        mma16816(&R[8], al, bh1[0], bh1[1]);
        mma16816(&R[12], ah, bh1[2], bh1[3]);
        mma16816(&R[12], ah, bl1[2], bl1[3]);
        mma16816(&R[12], al, bh1[2], bh1[3]);
    }
}

__device__ __forceinline__ void run_step2(float q[64], unsigned ehA, unsigned elA,
                                          const unsigned short* dh,
                                          const unsigned short* dl, int mB2,
                                          int aB2, int lane) {
#pragma unroll
    for (int i = 0; i < 64; ++i) q[i] = 0.f;
    int arow = mB2 * 32 + (lane & 15);
    int acolg = (lane >> 4) << 3;
    int acol_b = aB2 + (lane >> 2);
    int kr_b = (lane & 3) << 1;
#pragma unroll
    for (int ks = 0; ks < 4; ++ks) {
        int k0 = ks * 16;
        unsigned ah0[4], al0[4], ah1[4], al1[4];
        unsigned aoff0 = (unsigned)((arow * LDE + k0 + acolg) * 2);
        unsigned aoff1 = (unsigned)(((arow + 16) * LDE + k0 + acolg) * 2);
        ldsm4(ah0, ehA + aoff0);
        ldsm4(al0, elA + aoff0);
        ldsm4(ah1, ehA + aoff1);
        ldsm4(al1, elA + aoff1);
        int kr = k0 + kr_b;
#pragma unroll
        for (int nt = 0; nt < 8; ++nt) {
            int ac = acol_b + nt * 8;
            unsigned h0 = (unsigned)dh[kr * LDD + ac] |
                          ((unsigned)dh[(kr + 1) * LDD + ac] << 16);
            unsigned h1 = (unsigned)dh[(kr + 8) * LDD + ac] |
                          ((unsigned)dh[(kr + 9) * LDD + ac] << 16);
            unsigned l0 = (unsigned)dl[kr * LDD + ac] |
                          ((unsigned)dl[(kr + 1) * LDD + ac] << 16);
            unsigned l1 = (unsigned)dl[(kr + 8) * LDD + ac] |
                          ((unsigned)dl[(kr + 9) * LDD + ac] << 16);
            mma16816(&q[nt * 4], ah0, h0, h1);
            mma16816(&q[nt * 4], ah0, l0, l1);
            mma16816(&q[nt * 4], al0, h0, h1);
            mma16816(&q[32 + nt * 4], ah1, h0, h1);
            mma16816(&q[32 + nt * 4], ah1, l0, l1);
            mma16816(&q[32 + nt * 4], al1, h0, h1);
        }
    }
}

__global__ __launch_bounds__(256, 1) void lista_mma_k(
    const float* __restrict__ x, const float* __restrict__ Dict,
    const float* __restrict__ Lp, const int* __restrict__ nip,
    const float* __restrict__ lam_g, float* __restrict__ out_z,
    float* __restrict__ out_r) {
    extern __shared__ __align__(16) char smem[];
    unsigned short* zh = (unsigned short*)(smem + ZH_OFF);
    unsigned short* zl = (unsigned short*)(smem + ZL_OFF);
    unsigned short* eh = (unsigned short*)(smem + EH_OFF);
    unsigned short* el = (unsigned short*)(smem + EL_OFF);
    unsigned short* dh = (unsigned short*)(smem + DH_OFF);
    unsigned short* dl = (unsigned short*)(smem + DL_OFF);
    float* lam = (float*)(smem + LAM_OFF);
    float* xrec = (float*)(smem + EH_OFF);
    float* zfp = lam;

    int t = threadIdx.x, w = t >> 5, lane = t & 31;
    int mB1 = w & 3, cB1 = (w >> 2) * 32;
    int mB2 = w & 1, aB2 = (w >> 1) * 64;
    int pbase = blockIdx.x * 64;
    int b = pbase >> 12, pl = pbase & 4095;
    float invL = 1.f / Lp[0];
    int niters = nip[0];

    unsigned zhA = (unsigned)__cvta_generic_to_shared(zh);
    unsigned zlA = (unsigned)__cvta_generic_to_shared(zl);
    unsigned ehA = (unsigned)__cvta_generic_to_shared(eh);
    unsigned elA = (unsigned)__cvta_generic_to_shared(el);
    unsigned dhA = (unsigned)__cvta_generic_to_shared(dh);
    unsigned dlA = (unsigned)__cvta_generic_to_shared(dl);

    for (int i = t; i < 16384; i += 256) {
        int m = i >> 8, a = i & 255;
        lam[m * LDL + a] = lam_g[(size_t)(pbase + m) * 256 + a];
    }
    for (int i = t; i < 16384; i += 256) {
        int c = i >> 8, a = i & 255;
        float v = Dict[i];
        unsigned short h = f2b(v);
        dh[c * LDD + a] = h;
        dl[c * LDD + a] = f2b(v - b2f(h));
    }
    size_t xofs = (size_t)b * 64 * 4096 + pl;
    for (int i = t; i < 4096; i += 256) {
        int c = i >> 6, m = i & 63;
        float v = x[xofs + (size_t)c * 4096 + m];
        unsigned short h = f2b(v);
        eh[m * LDE + c] = h;
        el[m * LDE + c] = f2b(v - b2f(h));
    }
    __syncthreads();

    float xfrag[16];
    {
        int r0 = mB1 * 16 + (lane >> 2);
#pragma unroll
        for (int nt = 0; nt < 4; ++nt) {
            int c2 = cB1 + nt * 8 + ((lane & 3) << 1);
            xfrag[nt * 4 + 0] = x[((size_t)b * 64 + c2) * 4096 + pl + r0];
            xfrag[nt * 4 + 1] = x[((size_t)b * 64 + c2 + 1) * 4096 + pl + r0];
            xfrag[nt * 4 + 2] = x[((size_t)b * 64 + c2) * 4096 + pl + r0 + 8];
            xfrag[nt * 4 + 3] = x[((size_t)b * 64 + c2 + 1) * 4096 + pl + r0 + 8];
        }
    }

    {
        float q[64];
        run_step2(q, ehA, elA, dh, dl, mB2, aB2, lane);
        bool wz = (niters == 0);
#pragma unroll
        for (int blk = 0; blk < 2; ++blk)
#pragma unroll
            for (int nt = 0; nt < 8; ++nt) {
                int r = mB2 * 32 + blk * 16 + (lane >> 2);
                int a2 = aB2 + nt * 8 + ((lane & 3) << 1);
                const float* qq = &q[blk * 32 + nt * 4];
#pragma unroll
                for (int rr = 0; rr < 2; ++rr) {
                    int row = r + rr * 8;
                    float y0 = qq[rr * 2], y1 = qq[rr * 2 + 1];
                    float l0 = lam[row * LDL + a2], l1 = lam[row * LDL + a2 + 1];
                    float g0 = fmaxf(fabsf(y0) - l0, 0.f);
                    float g1 = fmaxf(fabsf(y1) - l1, 0.f);
                    float z0 = (y0 > 0.f) ? g0 : -g0;
                    float z1 = (y1 > 0.f) ? g1 : -g1;
                    unsigned short h0 = f2b(z0), h1 = f2b(z1);
                    *(unsigned*)&zh[row * LDZ + a2] =
                        (unsigned)h0 | ((unsigned)h1 << 16);
                    *(unsigned*)&zl[row * LDZ + a2] =
                        (unsigned)f2b(z0 - b2f(h0)) |
                        ((unsigned)f2b(z1 - b2f(h1)) << 16);
                    if (wz) {
                        zfp[row * LDL + a2] = z0;
                        zfp[row * LDL + a2 + 1] = z1;
                    }
                }
            }
    }
    __syncthreads();

    for (int it = 0; it < niters; ++it) {
        float R[16];
        run_step1(R, zhA, zlA, dhA, dlA, mB1, cB1, lane);
        {
            int r0 = mB1 * 16 + (lane >> 2);
#pragma unroll
            for (int nt = 0; nt < 4; ++nt) {
                int c2 = cB1 + nt * 8 + ((lane & 3) << 1);
#pragma unroll
                for (int rr = 0; rr < 2; ++rr) {
                    int row = r0 + rr * 8;
                    float e0 = xfrag[nt * 4 + rr * 2] - R[nt * 4 + rr * 2];
                    float e1 = xfrag[nt * 4 + rr * 2 + 1] - R[nt * 4 + rr * 2 + 1];
                    unsigned short h0 = f2b(e0), h1 = f2b(e1);
                    *(unsigned*)&eh[row * LDE + c2] =
                        (unsigned)h0 | ((unsigned)h1 << 16);
                    *(unsigned*)&el[row * LDE + c2] =
                        (unsigned)f2b(e0 - b2f(h0)) |
                        ((unsigned)f2b(e1 - b2f(h1)) << 16);
                }
            }
        }
        __syncthreads();
        float q[64];
        run_step2(q, ehA, elA, dh, dl, mB2, aB2, lane);
        bool wz = (it == niters - 1);
#pragma unroll
        for (int blk = 0; blk < 2; ++blk)
#pragma unroll
            for (int nt = 0; nt < 8; ++nt) {
                int r = mB2 * 32 + blk * 16 + (lane >> 2);
                int a2 = aB2 + nt * 8 + ((lane & 3) << 1);
                const float* qq = &q[blk * 32 + nt * 4];
#pragma unroll
                for (int rr = 0; rr < 2; ++rr) {
                    int row = r + rr * 8;
                    unsigned hz = *(unsigned*)&zh[row * LDZ + a2];
                    unsigned lz = *(unsigned*)&zl[row * LDZ + a2];
                    float zo0 = b2f(hz & 0xffffu) + b2f(lz & 0xffffu);
                    float zo1 = b2f(hz >> 16) + b2f(lz >> 16);
                    float w0 = zo0 + qq[rr * 2] * invL;
                    float w1 = zo1 + qq[rr * 2 + 1] * invL;
                    float l0 = lam[row * LDL + a2], l1 = lam[row * LDL + a2 + 1];
                    float g0 = fmaxf(fabsf(w0) - l0, 0.f);
                    float g1 = fmaxf(fabsf(w1) - l1, 0.f);
                    float z0 = (w0 > 0.f) ? g0 : -g0;
                    float z1 = (w1 > 0.f) ? g1 : -g1;
                    unsigned short h0 = f2b(z0), h1 = f2b(z1);
                    *(unsigned*)&zh[row * LDZ + a2] =
                        (unsigned)h0 | ((unsigned)h1 << 16);
                    *(unsigned*)&zl[row * LDZ + a2] =
                        (unsigned)f2b(z0 - b2f(h0)) |
                        ((unsigned)f2b(z1 - b2f(h1)) << 16);
                    if (wz) {
                        zfp[row * LDL + a2] = z0;
                        zfp[row * LDL + a2 + 1] = z1;
                    }
                }
            }
        __syncthreads();
    }

    {
        float R[16];
        run_step1(R, zhA, zlA, dhA, dlA, mB1, cB1, lane);
        __syncthreads();
        int r0 = mB1 * 16 + (lane >> 2);
#pragma unroll
        for (int nt = 0; nt < 4; ++nt) {
            int c2 = cB1 + nt * 8 + ((lane & 3) << 1);
            xrec[r0 * 65 + c2] = R[nt * 4 + 0];
            xrec[r0 * 65 + c2 + 1] = R[nt * 4 + 1];
            xrec[(r0 + 8) * 65 + c2] = R[nt * 4 + 2];
            xrec[(r0 + 8) * 65 + c2 + 1] = R[nt * 4 + 3];
        }
    }
    __syncthreads();

    size_t zofs = (size_t)b * 256 * 4096 + pl;
    for (int i = t; i < 16384; i += 256) {
        int a = i >> 6, m = i & 63;
        out_z[zofs + (size_t)a * 4096 + m] = zfp[m * LDL + a];
    }
    size_t rofs = (size_t)b * 64 * 4096 + pl;
    for (int i = t; i < 4096; i += 256) {
        int c = i >> 6, m = i & 63;
        out_r[rofs + (size_t)c * 4096 + m] = xrec[m * 65 + c];
    }
}

__global__ void copy_k(const float* __restrict__ s, float* __restrict__ d, int n) {
    int i = blockIdx.x * blockDim.x + threadIdx.x;
    if (i < n) d[i] = s[i];
}

extern "C" void kernel_launch(void* const* d_in, const int* in_sizes, int n_in,
                              void* d_out, int out_size) {
    const float* x = (const float*)d_in[0];
    const float* conv_w = (const float*)d_in[1];
    const float* conv_b = (const float*)d_in[2];
    const float* r1w1 = (const float*)d_in[3];
    const float* r1w2 = (const float*)d_in[4];
    const float* r2w1 = (const float*)d_in[5];
    const float* r2w2 = (const float*)d_in[6];
    const float* caw1 = (const float*)d_in[7];
    const float* caw2 = (const float*)d_in[8];
    const float* saw = (const float*)d_in[9];
    const float* Dict = (const float*)d_in[10];
    const float* Lp = (const float*)d_in[11];
    const int* nip = (const int*)d_in[12];
    float* out = (float*)d_out;

    float *l, *tb, *avg, *mx, *sca, *s2m, *s2x, *satt, *lam;
    cudaGetSymbolAddress((void**)&l, g_l);
    cudaGetSymbolAddress((void**)&tb, g_t);
    cudaGetSymbolAddress((void**)&avg, g_avg);
    cudaGetSymbolAddress((void**)&mx, g_mx);
    cudaGetSymbolAddress((void**)&sca, g_sca);
    cudaGetSymbolAddress((void**)&s2m, g_s2m);
    cudaGetSymbolAddress((void**)&s2x, g_s2x);
    cudaGetSymbolAddress((void**)&satt, g_satt);
    cudaGetSymbolAddress((void**)&lam, g_lam);

    cudaFuncSetAttribute(conv3x3_mma_k<64, 256, false, true>,
                         cudaFuncAttributeMaxDynamicSharedMemorySize, CONV_SMEM);
    cudaFuncSetAttribute(conv3x3_mma_k<256, 128, true, false>,
                         cudaFuncAttributeMaxDynamicSharedMemorySize, CONV_SMEM);

    conv3x3_mma_k<64, 256, false, true>
        <<<dim3(128, 4), 256, CONV_SMEM>>>(x, conv_w, conv_b, l);
    conv3x3_mma_k<256, 128, true, false>
        <<<dim3(128, 2), 256, CONV_SMEM>>>(l, r1w1, nullptr, tb);
    conv1x1_add_k<<<dim3(64, 16), 256>>>(tb, r1w2, l);
    conv3x3_mma_k<256, 128, true, false>
        <<<dim3(128, 2), 256, CONV_SMEM>>>(l, r2w1, nullptr, tb);
    conv1x1_add_k<<<dim3(64, 16), 256>>>(tb, r2w2, l);
    pool_k<<<2048, 256>>>(l, avg, mx);
    camlp_k<<<1, 256>>>(avg, mx, caw1, caw2, sca);
    chan_k<<<64, 256>>>(l, sca, s2m, s2x);
    sconv_k<<<128, 256>>>(s2m, s2x, saw, satt);
    lamT_k<<<dim3(1024, 8), dim3(32, 8)>>>(l, satt, Lp, lam);

    cudaFuncSetAttribute(lista_mma_k, cudaFuncAttributeMaxDynamicSharedMemorySize,
                         LISTA_SMEM);
    lista_mma_k<<<512, 256, LISTA_SMEM>>>(x, Dict, Lp, nip, lam,
                                          out, out + 8 * 256 * 4096);
    copy_k<<<64, 256>>>(Dict, out + 8 * 256 * 4096 + 8 * 64 * 4096, 64 * 256);
}

// round 15
// speedup vs baseline: 2.7161x; 1.1051x over previous
#include <cuda_runtime.h>
#include <cuda_bf16.h>
#include <cstdint>

__device__ float g_l[8 * 256 * 4096];
__device__ float g_t[8 * 128 * 4096];
__device__ float g_lam[8 * 4096 * 256];
__device__ float g_avg[8 * 256];
__device__ float g_mx[8 * 256];
__device__ float g_sca[8 * 256];
__device__ float g_s2m[8 * 4096];
__device__ float g_s2x[8 * 4096];
__device__ float g_satt[8 * 4096];

__device__ __forceinline__ unsigned long long pk2(float a, float b) {
    unsigned long long r;
    asm("mov.b64 %0, {%1, %2};" : "=l"(r) : "f"(a), "f"(b));
    return r;
}
__device__ __forceinline__ void upk2(unsigned long long v, float& a, float& b) {
    asm("mov.b64 {%0, %1}, %2;" : "=f"(a), "=f"(b) : "l"(v));
}
__device__ __forceinline__ void ffma2(unsigned long long& d, unsigned long long a,
                                      unsigned long long b) {
    asm("fma.rn.f32x2 %0, %1, %2, %0;" : "+l"(d) : "l"(a), "l"(b));
}

__device__ __forceinline__ float b2f(unsigned u) {
    return __uint_as_float(u << 16);
}
__device__ __forceinline__ unsigned short f2b(float f) {
    __nv_bfloat16 h = __float2bfloat16(f);
    return *(unsigned short*)&h;
}
__device__ __forceinline__ void ldsm4(unsigned r[4], unsigned addr) {
    asm volatile("ldmatrix.sync.aligned.m8n8.x4.shared.b16 {%0,%1,%2,%3}, [%4];"
                 : "=r"(r[0]), "=r"(r[1]), "=r"(r[2]), "=r"(r[3])
                 : "r"(addr));
}
__device__ __forceinline__ void mma16816(float d[4], const unsigned a[4],
                                         unsigned b0, unsigned b1) {
    asm volatile(
        "mma.sync.aligned.m16n8k16.row.col.f32.bf16.bf16.f32 "
        "{%0,%1,%2,%3},{%4,%5,%6,%7},{%8,%9},{%0,%1,%2,%3};"
        : "+f"(d[0]), "+f"(d[1]), "+f"(d[2]), "+f"(d[3])
        : "r"(a[0]), "r"(a[1]), "r"(a[2]), "r"(a[3]), "r"(b0), "r"(b1));
}

// ---------------------------------------------------------------------------
// conv3x3 via mma.sync bf16 hi/lo split (implicit GEMM, per-tap shifts).
// CTA: 256 thr, M=256 pixels (4 rows x 64 cols), N=64 co, ci-chunks of 16.
// Warp tile 32x64. smem 94.5KB -> 2 CTAs/SM. Staging uses 32-bit packed STS.
// grid.x = batch*16 rowblocks, grid.y = CO/64.
// ---------------------------------------------------------------------------
#define CILD 24            // halfword stride per cell (48B)
#define CWTAP 1536         // 64 co * CILD
#define CONV_IH 0
#define CONV_IL 9792       // 6*68*24
#define CONV_WH 19584
#define CONV_WL 33408      // +9*64*24
#define CONV_SMEM 94464    // 47232 halfwords * 2B

template <int CI, int CO, bool RELU, bool BIAS>
__global__ __launch_bounds__(256, 2) void conv3x3_mma_k(
    const float* __restrict__ in, const float* __restrict__ wt,
    const float* __restrict__ bias, float* __restrict__ out) {
    extern __shared__ __align__(16) unsigned short cs[];
    unsigned short* ih = cs + CONV_IH;
    unsigned short* il = cs + CONV_IL;
    unsigned short* wh = cs + CONV_WH;
    unsigned short* wl = cs + CONV_WL;
    int t = threadIdx.x, w = t >> 5, lane = t & 31;
    int b = blockIdx.x >> 4, rb = blockIdx.x & 15, r0 = rb * 4;
    int coB = blockIdx.y * 64;
    int wmB = w * 32;

    unsigned ihA = (unsigned)__cvta_generic_to_shared(ih);
    unsigned ilA = (unsigned)__cvta_generic_to_shared(il);
    unsigned whA = (unsigned)__cvta_generic_to_shared(wh);
    unsigned wlA = (unsigned)__cvta_generic_to_shared(wl);

    for (int i = t; i < 9792; i += 256) ((unsigned*)cs)[i] = 0u;

    float acc[2][32];
#pragma unroll
    for (int mb = 0; mb < 2; ++mb)
#pragma unroll
        for (int i = 0; i < 32; ++i) acc[mb][i] = 0.f;

#pragma unroll 1
    for (int cc = 0; cc < CI / 16; ++cc) {
        __syncthreads();
        // stage input chunk: 3072 ci-pairs (6r x 64c x 8), 12/thread, MLP=6,
        // packed 32-bit STS
#pragma unroll 1
        for (int it = 0; it < 12; it += 6) {
            float u0[6], u1[6];
            int idx[6];
#pragma unroll
            for (int j = 0; j < 6; ++j) {
                int p = t + (it + j) * 256;
                int cell = p >> 3, cp = p & 7;
                int row = cell >> 6, col = cell & 63;
                int ci0 = cp * 2;
                int imgrow = r0 - 1 + row;
                float a = 0.f, bb = 0.f;
                if ((unsigned)imgrow < 64u) {
                    const float* ip = in + ((size_t)b * CI + cc * 16 + ci0) * 4096 +
                                      imgrow * 64 + col;
                    a = ip[0];
                    bb = ip[4096];
                }
                u0[j] = RELU ? fmaxf(a, 0.f) : a;
                u1[j] = RELU ? fmaxf(bb, 0.f) : bb;
                idx[j] = (row * 68 + col + 1) * CILD + ci0;
            }
#pragma unroll
            for (int j = 0; j < 6; ++j) {
                unsigned short h0 = f2b(u0[j]), h1 = f2b(u1[j]);
                *(unsigned*)&ih[idx[j]] = (unsigned)h0 | ((unsigned)h1 << 16);
                unsigned short l0 = f2b(u0[j] - b2f(h0));
                unsigned short l1 = f2b(u1[j] - b2f(h1));
                *(unsigned*)&il[idx[j]] = (unsigned)l0 | ((unsigned)l1 << 16);
            }
        }
        // stage weights: 4608 ci-pairs, 18/thread, MLP=6, packed 32-bit STS
#pragma unroll 1
        for (int it = 0; it < 18; it += 6) {
            float u0[6], u1[6];
            int idx[6];
#pragma unroll
            for (int j = 0; j < 6; ++j) {
                int p = t + (it + j) * 256;
                int co = p / 72, rem = p - co * 72;
                int tap = rem >> 3, cp = rem & 7;
                int ci0 = cp * 2;
                const float* wp = wt + (size_t)(coB + co) * (CI * 9) +
                                  (size_t)(cc * 16 + ci0) * 9 + tap;
                u0[j] = wp[0];
                u1[j] = wp[9];
                idx[j] = tap * CWTAP + co * CILD + ci0;
            }
#pragma unroll
            for (int j = 0; j < 6; ++j) {
                unsigned short h0 = f2b(u0[j]), h1 = f2b(u1[j]);
                *(unsigned*)&wh[idx[j]] = (unsigned)h0 | ((unsigned)h1 << 16);
                unsigned short l0 = f2b(u0[j] - b2f(h0));
                unsigned short l1 = f2b(u1[j] - b2f(h1));
                *(unsigned*)&wl[idx[j]] = (unsigned)l0 | ((unsigned)l1 << 16);
            }
        }
        __syncthreads();

#pragma unroll 1
        for (int tap = 0; tap < 9; ++tap) {
            int dh = tap / 3, dw = tap - dh * 3;
            unsigned ah[2][4], al[2][4];
#pragma unroll
            for (int mb = 0; mb < 2; ++mb) {
                int p = wmB + mb * 16 + (lane & 15);
                int trow = (p >> 6) + dh;
                int tcol = (p & 63) + dw;
                unsigned aoff =
                    (unsigned)((trow * 68 + tcol) * CILD + ((lane >> 4) << 3)) * 2;
                ldsm4(ah[mb], ihA + aoff);
                ldsm4(al[mb], ilA + aoff);
            }
            int brow_b = (lane & 7) + (((lane >> 4) & 1) << 3);
            unsigned bbase =
                (unsigned)(tap * CWTAP + brow_b * CILD + (((lane >> 3) & 1) << 3)) *
                2;
#pragma unroll
            for (int nt2 = 0; nt2 < 4; ++nt2) {
                unsigned bh[4], bl[4];
                unsigned bo = bbase + (unsigned)(nt2 * 16 * CILD * 2);
                ldsm4(bh, whA + bo);
                ldsm4(bl, wlA + bo);
#pragma unroll
                for (int mb = 0; mb < 2; ++mb) {
                    float* a0 = &acc[mb][nt2 * 8];
                    mma16816(&a0[0], ah[mb], bh[0], bh[1]);
                    mma16816(&a0[0], ah[mb], bl[0], bl[1]);
                    mma16816(&a0[0], al[mb], bh[0], bh[1]);
                    mma16816(&a0[4], ah[mb], bh[2], bh[3]);
                    mma16816(&a0[4], ah[mb], bl[2], bl[3]);
                    mma16816(&a0[4], al[mb], bh[2], bh[3]);
                }
            }
        }
    }

    size_t ob = (size_t)b * CO * 4096;
#pragma unroll
    for (int mb = 0; mb < 2; ++mb) {
        int p0 = wmB + mb * 16 + (lane >> 2);
#pragma unroll
        for (int nt = 0; nt < 8; ++nt) {
            int n = coB + nt * 8 + ((lane & 3) << 1);
            float bs0 = BIAS ? bias[n] : 0.f;
            float bs1 = BIAS ? bias[n + 1] : 0.f;
#pragma unroll
            for (int rr = 0; rr < 2; ++rr) {
                int p = p0 + rr * 8;
                int orow = r0 + (p >> 6), ocol = p & 63;
                out[ob + (size_t)n * 4096 + orow * 64 + ocol] =
                    acc[mb][nt * 4 + rr * 2] + bs0;
                out[ob + (size_t)(n + 1) * 4096 + orow * 64 + ocol] =
                    acc[mb][nt * 4 + rr * 2 + 1] + bs1;
            }
        }
    }
}

// 1x1 conv (relu(t)@w2) + residual add; CI=128, 16 co per block, 2 px/thread
__global__ __launch_bounds__(256) void conv1x1_add_k(const float* __restrict__ tin,
                                                     const float* __restrict__ wt,
                                                     float* __restrict__ lio) {
    __shared__ __align__(16) float wsh[128 * 16];
    int tid = threadIdx.x;
    int p0 = blockIdx.x * 512 + 2 * tid;
    int b = p0 >> 12, hw = p0 & 4095;
    int coBase = blockIdx.y * 16;
    for (int i = tid; i < 2048; i += 256) {
        int o = i >> 7, ci = i & 127;
        wsh[ci * 16 + o] = wt[(size_t)(coBase + o) * 128 + ci];
    }
    __syncthreads();
    unsigned long long acc2[16];
    size_t lb = ((size_t)b * 256 + coBase) * 4096 + hw;
#pragma unroll
    for (int q = 0; q < 8; ++q) {
        float2 v = *(const float2*)&lio[lb + (size_t)(2 * q) * 4096];
        float2 u = *(const float2*)&lio[lb + (size_t)(2 * q + 1) * 4096];
        acc2[2 * q] = pk2(v.x, u.x);
        acc2[2 * q + 1] = pk2(v.y, u.y);
    }
    const float* tb = tin + (size_t)b * 128 * 4096 + hw;
#pragma unroll 1
    for (int ci = 0; ci < 128; ci += 8) {
        float2 v[8];
#pragma unroll
        for (int j = 0; j < 8; ++j) {
            float2 u = *(const float2*)&tb[(size_t)(ci + j) * 4096];
            v[j].x = fmaxf(u.x, 0.f);
            v[j].y = fmaxf(u.y, 0.f);
        }
#pragma unroll
        for (int j = 0; j < 8; ++j) {
            unsigned long long v0 = pk2(v[j].x, v[j].x);
            unsigned long long v1 = pk2(v[j].y, v[j].y);
            const ulonglong2* wp = (const ulonglong2*)&wsh[(ci + j) * 16];
#pragma unroll
            for (int q = 0; q < 4; ++q) {
                ulonglong2 wq = wp[q];
                ffma2(acc2[4 * q], wq.x, v0);
                ffma2(acc2[4 * q + 1], wq.x, v1);
                ffma2(acc2[4 * q + 2], wq.y, v0);
                ffma2(acc2[4 * q + 3], wq.y, v1);
            }
        }
    }
#pragma unroll
    for (int q = 0; q < 8; ++q) {
        float a0, a1, b0_, b1_;
        upk2(acc2[2 * q], a0, b0_);
        upk2(acc2[2 * q + 1], a1, b1_);
        float2 o0 = {a0, a1}, o1 = {b0_, b1_};
        *(float2*)&lio[lb + (size_t)(2 * q) * 4096] = o0;
        *(float2*)&lio[lb + (size_t)(2 * q + 1) * 4096] = o1;
    }
}

__global__ __launch_bounds__(256) void pool_k(const float* __restrict__ l,
                                              float* __restrict__ avg,
                                              float* __restrict__ mx) {
    __shared__ float ss[256], sm[256];
    int bc = blockIdx.x, t = threadIdx.x;
    const float4* p = (const float4*)(l + (size_t)bc * 4096);
    float s = 0.f, m = -3.4e38f;
    for (int i = t; i < 1024; i += 256) {
        float4 v = p[i];
        s += v.x + v.y + v.z + v.w;
        m = fmaxf(m, fmaxf(fmaxf(v.x, v.y), fmaxf(v.z, v.w)));
    }
    ss[t] = s;
    sm[t] = m;
    __syncthreads();
    for (int st = 128; st > 0; st >>= 1) {
        if (t < st) {
            ss[t] += ss[t + st];
            sm[t] = fmaxf(sm[t], sm[t + st]);
        }
        __syncthreads();
    }
    if (t == 0) {
        avg[bc] = ss[0] * (1.f / 4096.f);
        mx[bc] = sm[0];
    }
}

__global__ void camlp_k(const float* __restrict__ avg, const float* __restrict__ mx,
                        const float* __restrict__ w1, const float* __restrict__ w2,
                        float* __restrict__ sca) {
    __shared__ float hsh[128];
    int t = threadIdx.x;
    if (t < 128) {
        int b = t >> 4, j = t & 15;
        float a = 0.f, m = 0.f;
        for (int c = 0; c < 256; ++c) {
            float w = w1[j * 256 + c];
            a += avg[b * 256 + c] * w;
            m += mx[b * 256 + c] * w;
        }
        hsh[b * 16 + j] = fmaxf(a, 0.f) + fmaxf(m, 0.f);
    }
    __syncthreads();
    for (int b = 0; b < 8; ++b) {
        float o = 0.f;
#pragma unroll
        for (int j = 0; j < 16; ++j) o += hsh[b * 16 + j] * w2[t * 16 + j];
        sca[b * 256 + t] = 1.f / (1.f + expf(-o));
    }
}

__global__ __launch_bounds__(256) void chan_k(float* __restrict__ l,
                                              const float* __restrict__ sca,
                                              float* __restrict__ s2m,
                                              float* __restrict__ s2x) {
    int tid = threadIdx.x;
    int p0 = blockIdx.x * 512 + 2 * tid;
    int b = p0 >> 12, hw = p0 & 4095;
    size_t base = (size_t)b * 256 * 4096 + hw;
    float s0 = 0.f, s1 = 0.f, m0 = -3.4e38f, m1 = -3.4e38f;
#pragma unroll 1
    for (int c = 0; c < 256; c += 8) {
        float2 v[8];
#pragma unroll
        for (int j = 0; j < 8; ++j) {
            float2 u = *(float2*)&l[base + (size_t)(c + j) * 4096];
            float sc = sca[b * 256 + c + j];
            v[j].x = u.x * sc;
            v[j].y = u.y * sc;
        }
#pragma unroll
        for (int j = 0; j < 8; ++j) {
            *(float2*)&l[base + (size_t)(c + j) * 4096] = v[j];
            s0 += v[j].x;
            s1 += v[j].y;
            m0 = fmaxf(m0, v[j].x);
            m1 = fmaxf(m1, v[j].y);
        }
    }
    s2m[p0] = s0 * (1.f / 256.f);
    s2m[p0 + 1] = s1 * (1.f / 256.f);
    s2x[p0] = m0;
    s2x[p0 + 1] = m1;
}

__global__ void sconv_k(const float* __restrict__ s2m, const float* __restrict__ s2x,
                        const float* __restrict__ sw, float* __restrict__ satt) {
    int p = blockIdx.x * 256 + threadIdx.x;
    int b = p >> 12, hw = p & 4095, h = hw >> 6, w = hw & 63;
    float a = 0.f;
#pragma unroll
    for (int kh = 0; kh < 3; ++kh) {
        int hh = h + kh - 1;
        if ((unsigned)hh >= 64u) continue;
#pragma unroll
        for (int kw = 0; kw < 3; ++kw) {
            int ww = w + kw - 1;
            if ((unsigned)ww >= 64u) continue;
            int q = b * 4096 + hh * 64 + ww;
            a += s2m[q] * sw[kh * 3 + kw] + s2x[q] * sw[9 + kh * 3 + kw];
        }
    }
    satt[p] = 1.f / (1.f + expf(-a));
}

__global__ void lamT_k(const float* __restrict__ l, const float* __restrict__ satt,
                       const float* __restrict__ Lp, float* __restrict__ lam) {
    __shared__ float tile[32][33];
    int pb = blockIdx.x * 32, cb = blockIdx.y * 32;
    int tx = threadIdx.x, ty = threadIdx.y;
    int b = pb >> 12, pl = pb & 4095;
#pragma unroll
    for (int k = 0; k < 4; ++k) {
        int c = cb + ty + 8 * k;
        tile[ty + 8 * k][tx] = l[((size_t)b * 256 + c) * 4096 + pl + tx];
    }
    __syncthreads();
    float invL = 1.f / Lp[0];
#pragma unroll
    for (int k = 0; k < 4; ++k) {
        int p2 = pb + ty + 8 * k;
        float sc = satt[p2] * invL;
        lam[(size_t)p2 * 256 + cb + tx] = tile[tx][ty + 8 * k] * sc;
    }
}

// ---------------------------------------------------------------------------
// LISTA via mma.sync bf16 (hi/lo split), residual form (unchanged)
// ---------------------------------------------------------------------------
#define ZH_OFF 0
#define ZL_OFF 33792
#define EH_OFF 67584
#define EL_OFF 76800
#define DH_OFF 86016
#define DL_OFF 119808
#define LAM_OFF 153600
#define LISTA_SMEM 220416
#define LDZ 264
#define LDE 72
#define LDD 264
#define LDL 261

__device__ __forceinline__ void run_step1(float R[16], unsigned zhA, unsigned zlA,
                                          unsigned dhA, unsigned dlA, int mB1,
                                          int cB1, int lane) {
#pragma unroll
    for (int i = 0; i < 16; ++i) R[i] = 0.f;
    int arow = mB1 * 16 + (lane & 15);
    int acolg = (lane >> 4) << 3;
    int brow0 = cB1 + (lane & 7) + (((lane >> 4) & 1) << 3);
    int bcolg = (((lane >> 3) & 1) << 3);
#pragma unroll 2
    for (int ks = 0; ks < 16; ++ks) {
        int k0 = ks * 16;
        unsigned ah[4], al[4], bh0[4], bh1[4], bl0[4], bl1[4];
        unsigned aoff = (unsigned)((arow * LDZ + k0 + acolg) * 2);
        ldsm4(ah, zhA + aoff);
        ldsm4(al, zlA + aoff);
        unsigned boff0 = (unsigned)((brow0 * LDD + k0 + bcolg) * 2);
        unsigned boff1 = (unsigned)(((brow0 + 16) * LDD + k0 + bcolg) * 2);
        ldsm4(bh0, dhA + boff0);
        ldsm4(bl0, dlA + boff0);
        ldsm4(bh1, dhA + boff1);
        ldsm4(bl1, dlA + boff1);
        mma16816(&R[0], ah, bh0[0], bh0[1]);
        mma16816(&R[0], ah, bl0[0], bl0[1]);
        mma16816(&R[0], al, bh0[0], bh0[1]);
        mma16816(&R[4], ah, bh0[2], bh0[3]);
        mma16816(&R[4], ah, bl0[2], bl0[3]);
        mma16816(&R[4], al, bh0[2], bh0[3]);
        mma16816(&R[8], ah, bh1[0], bh1[1]);
        mma16816(&R[8], ah, bl1[0], bl1[1]);
        mma16816(&R[8], al, bh1[0], bh1[1]);
        mma16816(&R[12], ah, bh1[2], bh1[3]);
        mma16816(&R[12], ah, bl1[2], bl1[3]);
        mma16816(&R[12], al, bh1[2], bh1[3]);
    }
}

__device__ __forceinline__ void run_step2(float q[64], unsigned ehA, unsigned elA,
                                          const unsigned short* dh,
                                          const unsigned short* dl, int mB2,
                                          int aB2, int lane) {
#pragma unroll
    for (int i = 0; i < 64; ++i) q[i] = 0.f;
    int arow = mB2 * 32 + (lane & 15);
    int acolg = (lane >> 4) << 3;
    int acol_b = aB2 + (lane >> 2);
    int kr_b = (lane & 3) << 1;
#pragma unroll
    for (int ks = 0; ks < 4; ++ks) {
        int k0 = ks * 16;
        unsigned ah0[4], al0[4], ah1[4], al1[4];
        unsigned aoff0 = (unsigned)((arow * LDE + k0 + acolg) * 2);
        unsigned aoff1 = (unsigned)(((arow + 16) * LDE + k0 + acolg) * 2);
        ldsm4(ah0, ehA + aoff0);
        ldsm4(al0, elA + aoff0);
        ldsm4(ah1, ehA + aoff1);
        ldsm4(al1, elA + aoff1);
        int kr = k0 + kr_b;
#pragma unroll
        for (int nt = 0; nt < 8; ++nt) {
            int ac = acol_b + nt * 8;
            unsigned h0 = (unsigned)dh[kr * LDD + ac] |
                          ((unsigned)dh[(kr + 1) * LDD + ac] << 16);
            unsigned h1 = (unsigned)dh[(kr + 8) * LDD + ac] |
                          ((unsigned)dh[(kr + 9) * LDD + ac] << 16);
            unsigned l0 = (unsigned)dl[kr * LDD + ac] |
                          ((unsigned)dl[(kr + 1) * LDD + ac] << 16);
            unsigned l1 = (unsigned)dl[(kr + 8) * LDD + ac] |
                          ((unsigned)dl[(kr + 9) * LDD + ac] << 16);
            mma16816(&q[nt * 4], ah0, h0, h1);
            mma16816(&q[nt * 4], ah0, l0, l1);
            mma16816(&q[nt * 4], al0, h0, h1);
            mma16816(&q[32 + nt * 4], ah1, h0, h1);
            mma16816(&q[32 + nt * 4], ah1, l0, l1);
            mma16816(&q[32 + nt * 4], al1, h0, h1);
        }
    }
}

__global__ __launch_bounds__(256, 1) void lista_mma_k(
    const float* __restrict__ x, const float* __restrict__ Dict,
    const float* __restrict__ Lp, const int* __restrict__ nip,
    const float* __restrict__ lam_g, float* __restrict__ out_z,
    float* __restrict__ out_r) {
    extern __shared__ __align__(16) char smem[];
    unsigned short* zh = (unsigned short*)(smem + ZH_OFF);
    unsigned short* zl = (unsigned short*)(smem + ZL_OFF);
    unsigned short* eh = (unsigned short*)(smem + EH_OFF);
    unsigned short* el = (unsigned short*)(smem + EL_OFF);
    unsigned short* dh = (unsigned short*)(smem + DH_OFF);
    unsigned short* dl = (unsigned short*)(smem + DL_OFF);
    float* lam = (float*)(smem + LAM_OFF);
    float* xrec = (float*)(smem + EH_OFF);
    float* zfp = lam;

    int t = threadIdx.x, w = t >> 5, lane = t & 31;
    int mB1 = w & 3, cB1 = (w >> 2) * 32;
    int mB2 = w & 1, aB2 = (w >> 1) * 64;
    int pbase = blockIdx.x * 64;
    int b = pbase >> 12, pl = pbase & 4095;
    float invL = 1.f / Lp[0];
    int niters = nip[0];

    unsigned zhA = (unsigned)__cvta_generic_to_shared(zh);
    unsigned zlA = (unsigned)__cvta_generic_to_shared(zl);
    unsigned ehA = (unsigned)__cvta_generic_to_shared(eh);
    unsigned elA = (unsigned)__cvta_generic_to_shared(el);
    unsigned dhA = (unsigned)__cvta_generic_to_shared(dh);
    unsigned dlA = (unsigned)__cvta_generic_to_shared(dl);

    for (int i = t; i < 16384; i += 256) {
        int m = i >> 8, a = i & 255;
        lam[m * LDL + a] = lam_g[(size_t)(pbase + m) * 256 + a];
    }
    for (int i = t; i < 16384; i += 256) {
        int c = i >> 8, a = i & 255;
        float v = Dict[i];
        unsigned short h = f2b(v);
        dh[c * LDD + a] = h;
        dl[c * LDD + a] = f2b(v - b2f(h));
    }
    size_t xofs = (size_t)b * 64 * 4096 + pl;
    for (int i = t; i < 4096; i += 256) {
        int c = i >> 6, m = i & 63;
        float v = x[xofs + (size_t)c * 4096 + m];
        unsigned short h = f2b(v);
        eh[m * LDE + c] = h;
        el[m * LDE + c] = f2b(v - b2f(h));
    }
    __syncthreads();

    float xfrag[16];
    {
        int r0 = mB1 * 16 + (lane >> 2);
#pragma unroll
        for (int nt = 0; nt < 4; ++nt) {
            int c2 = cB1 + nt * 8 + ((lane & 3) << 1);
            xfrag[nt * 4 + 0] = x[((size_t)b * 64 + c2) * 4096 + pl + r0];
            xfrag[nt * 4 + 1] = x[((size_t)b * 64 + c2 + 1) * 4096 + pl + r0];
            xfrag[nt * 4 + 2] = x[((size_t)b * 64 + c2) * 4096 + pl + r0 + 8];
            xfrag[nt * 4 + 3] = x[((size_t)b * 64 + c2 + 1) * 4096 + pl + r0 + 8];
        }
    }

    {
        float q[64];
        run_step2(q, ehA, elA, dh, dl, mB2, aB2, lane);
        bool wz = (niters == 0);
#pragma unroll
        for (int blk = 0; blk < 2; ++blk)
#pragma unroll
            for (int nt = 0; nt < 8; ++nt) {
                int r = mB2 * 32 + blk * 16 + (lane >> 2);
                int a2 = aB2 + nt * 8 + ((lane & 3) << 1);
                const float* qq = &q[blk * 32 + nt * 4];
#pragma unroll
                for (int rr = 0; rr < 2; ++rr) {
                    int row = r + rr * 8;
                    float y0 = qq[rr * 2], y1 = qq[rr * 2 + 1];
                    float l0 = lam[row * LDL + a2], l1 = lam[row * LDL + a2 + 1];
                    float g0 = fmaxf(fabsf(y0) - l0, 0.f);
                    float g1 = fmaxf(fabsf(y1) - l1, 0.f);
                    float z0 = (y0 > 0.f) ? g0 : -g0;
                    float z1 = (y1 > 0.f) ? g1 : -g1;
                    unsigned short h0 = f2b(z0), h1 = f2b(z1);
                    *(unsigned*)&zh[row * LDZ + a2] =
                        (unsigned)h0 | ((unsigned)h1 << 16);
                    *(unsigned*)&zl[row * LDZ + a2] =
                        (unsigned)f2b(z0 - b2f(h0)) |
                        ((unsigned)f2b(z1 - b2f(h1)) << 16);
                    if (wz) {
                        zfp[row * LDL + a2] = z0;
                        zfp[row * LDL + a2 + 1] = z1;
                    }
                }
            }
    }
    __syncthreads();

    for (int it = 0; it < niters; ++it) {
        float R[16];
        run_step1(R, zhA, zlA, dhA, dlA, mB1, cB1, lane);
        {
            int r0 = mB1 * 16 + (lane >> 2);
#pragma unroll
            for (int nt = 0; nt < 4; ++nt) {
                int c2 = cB1 + nt * 8 + ((lane & 3) << 1);
#pragma unroll
                for (int rr = 0; rr < 2; ++rr) {
                    int row = r0 + rr * 8;
                    float e0 = xfrag[nt * 4 + rr * 2] - R[nt * 4 + rr * 2];
                    float e1 = xfrag[nt * 4 + rr * 2 + 1] - R[nt * 4 + rr * 2 + 1];
                    unsigned short h0 = f2b(e0), h1 = f2b(e1);
                    *(unsigned*)&eh[row * LDE + c2] =
                        (unsigned)h0 | ((unsigned)h1 << 16);
                    *(unsigned*)&el[row * LDE + c2] =
                        (unsigned)f2b(e0 - b2f(h0)) |
                        ((unsigned)f2b(e1 - b2f(h1)) << 16);
                }
            }
        }
        __syncthreads();
        float q[64];
        run_step2(q, ehA, elA, dh, dl, mB2, aB2, lane);
        bool wz = (it == niters - 1);
#pragma unroll
        for (int blk = 0; blk < 2; ++blk)
#pragma unroll
            for (int nt = 0; nt < 8; ++nt) {
                int r = mB2 * 32 + blk * 16 + (lane >> 2);
                int a2 = aB2 + nt * 8 + ((lane & 3) << 1);
                const float* qq = &q[blk * 32 + nt * 4];
#pragma unroll
                for (int rr = 0; rr < 2; ++rr) {
                    int row = r + rr * 8;
                    unsigned hz = *(unsigned*)&zh[row * LDZ + a2];
                    unsigned lz = *(unsigned*)&zl[row * LDZ + a2];
                    float zo0 = b2f(hz & 0xffffu) + b2f(lz & 0xffffu);
                    float zo1 = b2f(hz >> 16) + b2f(lz >> 16);
                    float w0 = zo0 + qq[rr * 2] * invL;
                    float w1 = zo1 + qq[rr * 2 + 1] * invL;
                    float l0 = lam[row * LDL + a2], l1 = lam[row * LDL + a2 + 1];
                    float g0 = fmaxf(fabsf(w0) - l0, 0.f);
                    float g1 = fmaxf(fabsf(w1) - l1, 0.f);
                    float z0 = (w0 > 0.f) ? g0 : -g0;
                    float z1 = (w1 > 0.f) ? g1 : -g1;
                    unsigned short h0 = f2b(z0), h1 = f2b(z1);
                    *(unsigned*)&zh[row * LDZ + a2] =
                        (unsigned)h0 | ((unsigned)h1 << 16);
                    *(unsigned*)&zl[row * LDZ + a2] =
                        (unsigned)f2b(z0 - b2f(h0)) |
                        ((unsigned)f2b(z1 - b2f(h1)) << 16);
                    if (wz) {
                        zfp[row * LDL + a2] = z0;
                        zfp[row * LDL + a2 + 1] = z1;
                    }
                }
            }
        __syncthreads();
    }

    {
        float R[16];
        run_step1(R, zhA, zlA, dhA, dlA, mB1, cB1, lane);
        __syncthreads();
        int r0 = mB1 * 16 + (lane >> 2);
#pragma unroll
        for (int nt = 0; nt < 4; ++nt) {
            int c2 = cB1 + nt * 8 + ((lane & 3) << 1);
            xrec[r0 * 65 + c2] = R[nt * 4 + 0];
            xrec[r0 * 65 + c2 + 1] = R[nt * 4 + 1];
            xrec[(r0 + 8) * 65 + c2] = R[nt * 4 + 2];
            xrec[(r0 + 8) * 65 + c2 + 1] = R[nt * 4 + 3];
        }
    }
    __syncthreads();

    size_t zofs = (size_t)b * 256 * 4096 + pl;
    for (int i = t; i < 16384; i += 256) {
        int a = i >> 6, m = i & 63;
        out_z[zofs + (size_t)a * 4096 + m] = zfp[m * LDL + a];
    }
    size_t rofs = (size_t)b * 64 * 4096 + pl;
    for (int i = t; i < 4096; i += 256) {
        int c = i >> 6, m = i & 63;
        out_r[rofs + (size_t)c * 4096 + m] = xrec[m * 65 + c];
    }
}

__global__ void copy_k(const float* __restrict__ s, float* __restrict__ d, int n) {
    int i = blockIdx.x * blockDim.x + threadIdx.x;
    if (i < n) d[i] = s[i];
}

extern "C" void kernel_launch(void* const* d_in, const int* in_sizes, int n_in,
                              void* d_out, int out_size) {
    const float* x = (const float*)d_in[0];
    const float* conv_w = (const float*)d_in[1];
    const float* conv_b = (const float*)d_in[2];
    const float* r1w1 = (const float*)d_in[3];
    const float* r1w2 = (const float*)d_in[4];
    const float* r2w1 = (const float*)d_in[5];
    const float* r2w2 = (const float*)d_in[6];
    const float* caw1 = (const float*)d_in[7];
    const float* caw2 = (const float*)d_in[8];
    const float* saw = (const float*)d_in[9];
    const float* Dict = (const float*)d_in[10];
    const float* Lp = (const float*)d_in[11];
    const int* nip = (const int*)d_in[12];
    float* out = (float*)d_out;

    float *l, *tb, *avg, *mx, *sca, *s2m, *s2x, *satt, *lam;
    cudaGetSymbolAddress((void**)&l, g_l);
    cudaGetSymbolAddress((void**)&tb, g_t);
    cudaGetSymbolAddress((void**)&avg, g_avg);
    cudaGetSymbolAddress((void**)&mx, g_mx);
    cudaGetSymbolAddress((void**)&sca, g_sca);
    cudaGetSymbolAddress((void**)&s2m, g_s2m);
    cudaGetSymbolAddress((void**)&s2x, g_s2x);
    cudaGetSymbolAddress((void**)&satt, g_satt);
    cudaGetSymbolAddress((void**)&lam, g_lam);

    cudaFuncSetAttribute(conv3x3_mma_k<64, 256, false, true>,
                         cudaFuncAttributeMaxDynamicSharedMemorySize, CONV_SMEM);
    cudaFuncSetAttribute(conv3x3_mma_k<256, 128, true, false>,
                         cudaFuncAttributeMaxDynamicSharedMemorySize, CONV_SMEM);

    conv3x3_mma_k<64, 256, false, true>
        <<<dim3(128, 4), 256, CONV_SMEM>>>(x, conv_w, conv_b, l);
    conv3x3_mma_k<256, 128, true, false>
        <<<dim3(128, 2), 256, CONV_SMEM>>>(l, r1w1, nullptr, tb);
    conv1x1_add_k<<<dim3(64, 16), 256>>>(tb, r1w2, l);
    conv3x3_mma_k<256, 128, true, false>
        <<<dim3(128, 2), 256, CONV_SMEM>>>(l, r2w1, nullptr, tb);
    conv1x1_add_k<<<dim3(64, 16), 256>>>(tb, r2w2, l);
    pool_k<<<2048, 256>>>(l, avg, mx);
    camlp_k<<<1, 256>>>(avg, mx, caw1, caw2, sca);
    chan_k<<<64, 256>>>(l, sca, s2m, s2x);
    sconv_k<<<128, 256>>>(s2m, s2x, saw, satt);
    lamT_k<<<dim3(1024, 8), dim3(32, 8)>>>(l, satt, Lp, lam);

    cudaFuncSetAttribute(lista_mma_k, cudaFuncAttributeMaxDynamicSharedMemorySize,
                         LISTA_SMEM);
    lista_mma_k<<<512, 256, LISTA_SMEM>>>(x, Dict, Lp, nip, lam,
                                          out, out + 8 * 256 * 4096);
    copy_k<<<64, 256>>>(Dict, out + 8 * 256 * 4096 + 8 * 64 * 4096, 64 * 256);
}

// round 16
// speedup vs baseline: 2.7652x; 1.0181x over previous
#include <cuda_runtime.h>
#include <cuda_bf16.h>
#include <cstdint>

__device__ float g_l[8 * 256 * 4096];
__device__ float g_t[8 * 128 * 4096];
__device__ float g_lam[8 * 4096 * 256];
__device__ float g_avg[8 * 256];
__device__ float g_mx[8 * 256];
__device__ float g_sca[8 * 256];
__device__ float g_s2m[8 * 4096];
__device__ float g_s2x[8 * 4096];

__device__ __forceinline__ unsigned long long pk2(float a, float b) {
    unsigned long long r;
    asm("mov.b64 %0, {%1, %2};" : "=l"(r) : "f"(a), "f"(b));
    return r;
}
__device__ __forceinline__ void upk2(unsigned long long v, float& a, float& b) {
    asm("mov.b64 {%0, %1}, %2;" : "=f"(a), "=f"(b) : "l"(v));
}
__device__ __forceinline__ void ffma2(unsigned long long& d, unsigned long long a,
                                      unsigned long long b) {
    asm("fma.rn.f32x2 %0, %1, %2, %0;" : "+l"(d) : "l"(a), "l"(b));
}

__device__ __forceinline__ float b2f(unsigned u) {
    return __uint_as_float(u << 16);
}
__device__ __forceinline__ unsigned short f2b(float f) {
    __nv_bfloat16 h = __float2bfloat16(f);
    return *(unsigned short*)&h;
}
__device__ __forceinline__ void ldsm4(unsigned r[4], unsigned addr) {
    asm volatile("ldmatrix.sync.aligned.m8n8.x4.shared.b16 {%0,%1,%2,%3}, [%4];"
                 : "=r"(r[0]), "=r"(r[1]), "=r"(r[2]), "=r"(r[3])
                 : "r"(addr));
}
__device__ __forceinline__ void ldsm4t(unsigned r[4], unsigned addr) {
    asm volatile(
        "ldmatrix.sync.aligned.m8n8.x4.trans.shared.b16 {%0,%1,%2,%3}, [%4];"
        : "=r"(r[0]), "=r"(r[1]), "=r"(r[2]), "=r"(r[3])
        : "r"(addr));
}
__device__ __forceinline__ void mma16816(float d[4], const unsigned a[4],
                                         unsigned b0, unsigned b1) {
    asm volatile(
        "mma.sync.aligned.m16n8k16.row.col.f32.bf16.bf16.f32 "
        "{%0,%1,%2,%3},{%4,%5,%6,%7},{%8,%9},{%0,%1,%2,%3};"
        : "+f"(d[0]), "+f"(d[1]), "+f"(d[2]), "+f"(d[3])
        : "r"(a[0]), "r"(a[1]), "r"(a[2]), "r"(a[3]), "r"(b0), "r"(b1));
}

// ---------------------------------------------------------------------------
// conv3x3 via mma.sync bf16 hi/lo split (unchanged from R15)
// ---------------------------------------------------------------------------
#define CILD 24
#define CWTAP 1536
#define CONV_IH 0
#define CONV_IL 9792
#define CONV_WH 19584
#define CONV_WL 33408
#define CONV_SMEM 94464

template <int CI, int CO, bool RELU, bool BIAS>
__global__ __launch_bounds__(256, 2) void conv3x3_mma_k(
    const float* __restrict__ in, const float* __restrict__ wt,
    const float* __restrict__ bias, float* __restrict__ out) {
    extern __shared__ __align__(16) unsigned short cs[];
    unsigned short* ih = cs + CONV_IH;
    unsigned short* il = cs + CONV_IL;
    unsigned short* wh = cs + CONV_WH;
    unsigned short* wl = cs + CONV_WL;
    int t = threadIdx.x, w = t >> 5, lane = t & 31;
    int b = blockIdx.x >> 4, rb = blockIdx.x & 15, r0 = rb * 4;
    int coB = blockIdx.y * 64;
    int wmB = w * 32;

    unsigned ihA = (unsigned)__cvta_generic_to_shared(ih);
    unsigned ilA = (unsigned)__cvta_generic_to_shared(il);
    unsigned whA = (unsigned)__cvta_generic_to_shared(wh);
    unsigned wlA = (unsigned)__cvta_generic_to_shared(wl);

    for (int i = t; i < 9792; i += 256) ((unsigned*)cs)[i] = 0u;

    float acc[2][32];
#pragma unroll
    for (int mb = 0; mb < 2; ++mb)
#pragma unroll
        for (int i = 0; i < 32; ++i) acc[mb][i] = 0.f;

#pragma unroll 1
    for (int cc = 0; cc < CI / 16; ++cc) {
        __syncthreads();
#pragma unroll 1
        for (int it = 0; it < 12; it += 6) {
            float u0[6], u1[6];
            int idx[6];
#pragma unroll
            for (int j = 0; j < 6; ++j) {
                int p = t + (it + j) * 256;
                int cell = p >> 3, cp = p & 7;
                int row = cell >> 6, col = cell & 63;
                int ci0 = cp * 2;
                int imgrow = r0 - 1 + row;
                float a = 0.f, bb = 0.f;
                if ((unsigned)imgrow < 64u) {
                    const float* ip = in + ((size_t)b * CI + cc * 16 + ci0) * 4096 +
                                      imgrow * 64 + col;
                    a = ip[0];
                    bb = ip[4096];
                }
                u0[j] = RELU ? fmaxf(a, 0.f) : a;
                u1[j] = RELU ? fmaxf(bb, 0.f) : bb;
                idx[j] = (row * 68 + col + 1) * CILD + ci0;
            }
#pragma unroll
            for (int j = 0; j < 6; ++j) {
                unsigned short h0 = f2b(u0[j]), h1 = f2b(u1[j]);
                *(unsigned*)&ih[idx[j]] = (unsigned)h0 | ((unsigned)h1 << 16);
                unsigned short l0 = f2b(u0[j] - b2f(h0));
                unsigned short l1 = f2b(u1[j] - b2f(h1));
                *(unsigned*)&il[idx[j]] = (unsigned)l0 | ((unsigned)l1 << 16);
            }
        }
#pragma unroll 1
        for (int it = 0; it < 18; it += 6) {
            float u0[6], u1[6];
            int idx[6];
#pragma unroll
            for (int j = 0; j < 6; ++j) {
                int p = t + (it + j) * 256;
                int co = p / 72, rem = p - co * 72;
                int tap = rem >> 3, cp = rem & 7;
                int ci0 = cp * 2;
                const float* wp = wt + (size_t)(coB + co) * (CI * 9) +
                                  (size_t)(cc * 16 + ci0) * 9 + tap;
                u0[j] = wp[0];
                u1[j] = wp[9];
                idx[j] = tap * CWTAP + co * CILD + ci0;
            }
#pragma unroll
            for (int j = 0; j < 6; ++j) {
                unsigned short h0 = f2b(u0[j]), h1 = f2b(u1[j]);
                *(unsigned*)&wh[idx[j]] = (unsigned)h0 | ((unsigned)h1 << 16);
                unsigned short l0 = f2b(u0[j] - b2f(h0));
                unsigned short l1 = f2b(u1[j] - b2f(h1));
                *(unsigned*)&wl[idx[j]] = (unsigned)l0 | ((unsigned)l1 << 16);
            }
        }
        __syncthreads();

#pragma unroll 1
        for (int tap = 0; tap < 9; ++tap) {
            int dh = tap / 3, dw = tap - dh * 3;
            unsigned ah[2][4], al[2][4];
#pragma unroll
            for (int mb = 0; mb < 2; ++mb) {
                int p = wmB + mb * 16 + (lane & 15);
                int trow = (p >> 6) + dh;
                int tcol = (p & 63) + dw;
                unsigned aoff =
                    (unsigned)((trow * 68 + tcol) * CILD + ((lane >> 4) << 3)) * 2;
                ldsm4(ah[mb], ihA + aoff);
                ldsm4(al[mb], ilA + aoff);
            }
            int brow_b = (lane & 7) + (((lane >> 4) & 1) << 3);
            unsigned bbase =
                (unsigned)(tap * CWTAP + brow_b * CILD + (((lane >> 3) & 1) << 3)) *
                2;
#pragma unroll
            for (int nt2 = 0; nt2 < 4; ++nt2) {
                unsigned bh[4], bl[4];
                unsigned bo = bbase + (unsigned)(nt2 * 16 * CILD * 2);
                ldsm4(bh, whA + bo);
                ldsm4(bl, wlA + bo);
#pragma unroll
                for (int mb = 0; mb < 2; ++mb) {
                    float* a0 = &acc[mb][nt2 * 8];
                    mma16816(&a0[0], ah[mb], bh[0], bh[1]);
                    mma16816(&a0[0], ah[mb], bl[0], bl[1]);
                    mma16816(&a0[0], al[mb], bh[0], bh[1]);
                    mma16816(&a0[4], ah[mb], bh[2], bh[3]);
                    mma16816(&a0[4], ah[mb], bl[2], bl[3]);
                    mma16816(&a0[4], al[mb], bh[2], bh[3]);
                }
            }
        }
    }

    size_t ob = (size_t)b * CO * 4096;
#pragma unroll
    for (int mb = 0; mb < 2; ++mb) {
        int p0 = wmB + mb * 16 + (lane >> 2);
#pragma unroll
        for (int nt = 0; nt < 8; ++nt) {
            int n = coB + nt * 8 + ((lane & 3) << 1);
            float bs0 = BIAS ? bias[n] : 0.f;
            float bs1 = BIAS ? bias[n + 1] : 0.f;
#pragma unroll
            for (int rr = 0; rr < 2; ++rr) {
                int p = p0 + rr * 8;
                int orow = r0 + (p >> 6), ocol = p & 63;
                out[ob + (size_t)n * 4096 + orow * 64 + ocol] =
                    acc[mb][nt * 4 + rr * 2] + bs0;
                out[ob + (size_t)(n + 1) * 4096 + orow * 64 + ocol] =
                    acc[mb][nt * 4 + rr * 2 + 1] + bs1;
            }
        }
    }
}

// 1x1 conv (relu(t)@w2) + residual add (unchanged)
__global__ __launch_bounds__(256) void conv1x1_add_k(const float* __restrict__ tin,
                                                     const float* __restrict__ wt,
                                                     float* __restrict__ lio) {
    __shared__ __align__(16) float wsh[128 * 16];
    int tid = threadIdx.x;
    int p0 = blockIdx.x * 512 + 2 * tid;
    int b = p0 >> 12, hw = p0 & 4095;
    int coBase = blockIdx.y * 16;
    for (int i = tid; i < 2048; i += 256) {
        int o = i >> 7, ci = i & 127;
        wsh[ci * 16 + o] = wt[(size_t)(coBase + o) * 128 + ci];
    }
    __syncthreads();
    unsigned long long acc2[16];
    size_t lb = ((size_t)b * 256 + coBase) * 4096 + hw;
#pragma unroll
    for (int q = 0; q < 8; ++q) {
        float2 v = *(const float2*)&lio[lb + (size_t)(2 * q) * 4096];
        float2 u = *(const float2*)&lio[lb + (size_t)(2 * q + 1) * 4096];
        acc2[2 * q] = pk2(v.x, u.x);
        acc2[2 * q + 1] = pk2(v.y, u.y);
    }
    const float* tb = tin + (size_t)b * 128 * 4096 + hw;
#pragma unroll 1
    for (int ci = 0; ci < 128; ci += 8) {
        float2 v[8];
#pragma unroll
        for (int j = 0; j < 8; ++j) {
            float2 u = *(const float2*)&tb[(size_t)(ci + j) * 4096];
            v[j].x = fmaxf(u.x, 0.f);
            v[j].y = fmaxf(u.y, 0.f);
        }
#pragma unroll
        for (int j = 0; j < 8; ++j) {
            unsigned long long v0 = pk2(v[j].x, v[j].x);
            unsigned long long v1 = pk2(v[j].y, v[j].y);
            const ulonglong2* wp = (const ulonglong2*)&wsh[(ci + j) * 16];
#pragma unroll
            for (int q = 0; q < 4; ++q) {
                ulonglong2 wq = wp[q];
                ffma2(acc2[4 * q], wq.x, v0);
                ffma2(acc2[4 * q + 1], wq.x, v1);
                ffma2(acc2[4 * q + 2], wq.y, v0);
                ffma2(acc2[4 * q + 3], wq.y, v1);
            }
        }
    }
#pragma unroll
    for (int q = 0; q < 8; ++q) {
        float a0, a1, b0_, b1_;
        upk2(acc2[2 * q], a0, b0_);
        upk2(acc2[2 * q + 1], a1, b1_);
        float2 o0 = {a0, a1}, o1 = {b0_, b1_};
        *(float2*)&lio[lb + (size_t)(2 * q) * 4096] = o0;
        *(float2*)&lio[lb + (size_t)(2 * q + 1) * 4096] = o1;
    }
}

__global__ __launch_bounds__(256) void pool_k(const float* __restrict__ l,
                                              float* __restrict__ avg,
                                              float* __restrict__ mx) {
    __shared__ float ss[256], sm[256];
    int bc = blockIdx.x, t = threadIdx.x;
    const float4* p = (const float4*)(l + (size_t)bc * 4096);
    float s = 0.f, m = -3.4e38f;
    for (int i = t; i < 1024; i += 256) {
        float4 v = p[i];
        s += v.x + v.y + v.z + v.w;
        m = fmaxf(m, fmaxf(fmaxf(v.x, v.y), fmaxf(v.z, v.w)));
    }
    ss[t] = s;
    sm[t] = m;
    __syncthreads();
    for (int st = 128; st > 0; st >>= 1) {
        if (t < st) {
            ss[t] += ss[t + st];
            sm[t] = fmaxf(sm[t], sm[t + st]);
        }
        __syncthreads();
    }
    if (t == 0) {
        avg[bc] = ss[0] * (1.f / 4096.f);
        mx[bc] = sm[0];
    }
}

__global__ void camlp_k(const float* __restrict__ avg, const float* __restrict__ mx,
                        const float* __restrict__ w1, const float* __restrict__ w2,
                        float* __restrict__ sca) {
    __shared__ float hsh[128];
    int t = threadIdx.x;
    if (t < 128) {
        int b = t >> 4, j = t & 15;
        float a = 0.f, m = 0.f;
        for (int c = 0; c < 256; ++c) {
            float w = w1[j * 256 + c];
            a += avg[b * 256 + c] * w;
            m += mx[b * 256 + c] * w;
        }
        hsh[b * 16 + j] = fmaxf(a, 0.f) + fmaxf(m, 0.f);
    }
    __syncthreads();
    for (int b = 0; b < 8; ++b) {
        float o = 0.f;
#pragma unroll
        for (int j = 0; j < 16; ++j) o += hsh[b * 16 + j] * w2[t * 16 + j];
        sca[b * 256 + t] = 1.f / (1.f + expf(-o));
    }
}

// channel scale in-place + spatial mean/max; 1 px/thread, 128 CTAs
__global__ __launch_bounds__(256) void chan_k(float* __restrict__ l,
                                              const float* __restrict__ sca,
                                              float* __restrict__ s2m,
                                              float* __restrict__ s2x) {
    int p = blockIdx.x * 256 + threadIdx.x;
    int b = p >> 12, hw = p & 4095;
    size_t base = (size_t)b * 256 * 4096 + hw;
    float s = 0.f, m = -3.4e38f;
#pragma unroll 1
    for (int c = 0; c < 256; c += 8) {
        float v[8];
#pragma unroll
        for (int j = 0; j < 8; ++j)
            v[j] = l[base + (size_t)(c + j) * 4096] * sca[b * 256 + c + j];
#pragma unroll
        for (int j = 0; j < 8; ++j) {
            l[base + (size_t)(c + j) * 4096] = v[j];
            s += v[j];
            m = fmaxf(m, v[j]);
        }
    }
    s2m[p] = s * (1.f / 256.f);
    s2x[p] = m;
}

// lam NHWC = (l * sigmoid(sconv(s2))) / L, sconv fused per-block
__global__ void lamT_k(const float* __restrict__ l, const float* __restrict__ s2m,
                       const float* __restrict__ s2x, const float* __restrict__ sw,
                       const float* __restrict__ Lp, float* __restrict__ lam) {
    __shared__ float tile[32][33];
    __shared__ float satts[32];
    int pb = blockIdx.x * 32, cb = blockIdx.y * 32;
    int tx = threadIdx.x, ty = threadIdx.y;
    int b = pb >> 12, pl = pb & 4095;
#pragma unroll
    for (int k = 0; k < 4; ++k) {
        int c = cb + ty + 8 * k;
        tile[ty + 8 * k][tx] = l[((size_t)b * 256 + c) * 4096 + pl + tx];
    }
    if (ty == 0) {
        int p2 = pb + tx;
        int hw = p2 & 4095, h = hw >> 6, w2 = hw & 63;
        float a = 0.f;
#pragma unroll
        for (int kh = 0; kh < 3; ++kh) {
            int hh = h + kh - 1;
            if ((unsigned)hh >= 64u) continue;
#pragma unroll
            for (int kw = 0; kw < 3; ++kw) {
                int ww = w2 + kw - 1;
                if ((unsigned)ww >= 64u) continue;
                int q = b * 4096 + hh * 64 + ww;
                a += s2m[q] * sw[kh * 3 + kw] + s2x[q] * sw[9 + kh * 3 + kw];
            }
        }
        satts[tx] = 1.f / (1.f + expf(-a));
    }
    __syncthreads();
    float invL = 1.f / Lp[0];
#pragma unroll
    for (int k = 0; k < 4; ++k) {
        int p2 = pb + ty + 8 * k;
        float sc = satts[ty + 8 * k] * invL;
        lam[(size_t)p2 * 256 + cb + tx] = tile[tx][ty + 8 * k] * sc;
    }
}

// ---------------------------------------------------------------------------
// LISTA via mma.sync bf16 (hi/lo split); step2 B now via ldmatrix.trans
// ---------------------------------------------------------------------------
#define ZH_OFF 0
#define ZL_OFF 33792
#define EH_OFF 67584
#define EL_OFF 76800
#define DH_OFF 86016
#define DL_OFF 119808
#define LAM_OFF 153600
#define LISTA_SMEM 220416
#define LDZ 264
#define LDE 72
#define LDD 264
#define LDL 261

__device__ __forceinline__ void run_step1(float R[16], unsigned zhA, unsigned zlA,
                                          unsigned dhA, unsigned dlA, int mB1,
                                          int cB1, int lane) {
#pragma unroll
    for (int i = 0; i < 16; ++i) R[i] = 0.f;
    int arow = mB1 * 16 + (lane & 15);
    int acolg = (lane >> 4) << 3;
    int brow0 = cB1 + (lane & 7) + (((lane >> 4) & 1) << 3);
    int bcolg = (((lane >> 3) & 1) << 3);
#pragma unroll 2
    for (int ks = 0; ks < 16; ++ks) {
        int k0 = ks * 16;
        unsigned ah[4], al[4], bh0[4], bh1[4], bl0[4], bl1[4];
        unsigned aoff = (unsigned)((arow * LDZ + k0 + acolg) * 2);
        ldsm4(ah, zhA + aoff);
        ldsm4(al, zlA + aoff);
        unsigned boff0 = (unsigned)((brow0 * LDD + k0 + bcolg) * 2);
        unsigned boff1 = (unsigned)(((brow0 + 16) * LDD + k0 + bcolg) * 2);
        ldsm4(bh0, dhA + boff0);
        ldsm4(bl0, dlA + boff0);
        ldsm4(bh1, dhA + boff1);
        ldsm4(bl1, dlA + boff1);
        mma16816(&R[0], ah, bh0[0], bh0[1]);
        mma16816(&R[0], ah, bl0[0], bl0[1]);
        mma16816(&R[0], al, bh0[0], bh0[1]);
        mma16816(&R[4], ah, bh0[2], bh0[3]);
        mma16816(&R[4], ah, bl0[2], bl0[3]);
        mma16816(&R[4], al, bh0[2], bh0[3]);
        mma16816(&R[8], ah, bh1[0], bh1[1]);
        mma16816(&R[8], ah, bl1[0], bl1[1]);
        mma16816(&R[8], al, bh1[0], bh1[1]);
        mma16816(&R[12], ah, bh1[2], bh1[3]);
        mma16816(&R[12], ah, bl1[2], bl1[3]);
        mma16816(&R[12], al, bh1[2], bh1[3]);
    }
}

// step2: Q[64m x 256a] = E(split) @ Dict; B frags via ldmatrix.trans on [c][a]
__device__ __forceinline__ void run_step2(float q[64], unsigned ehA, unsigned elA,
                                          unsigned dhA, unsigned dlA, int mB2,
                                          int aB2, int lane) {
#pragma unroll
    for (int i = 0; i < 64; ++i) q[i] = 0.f;
    int arow = mB2 * 32 + (lane & 15);
    int acolg = (lane >> 4) << 3;
    int bkrow = (lane & 7) + (((lane >> 3) & 1) << 3);
    int bcol = (lane >> 4) << 3;
#pragma unroll
    for (int ks = 0; ks < 4; ++ks) {
        int k0 = ks * 16;
        unsigned ah0[4], al0[4], ah1[4], al1[4];
        unsigned aoff0 = (unsigned)((arow * LDE + k0 + acolg) * 2);
        unsigned aoff1 = (unsigned)(((arow + 16) * LDE + k0 + acolg) * 2);
        ldsm4(ah0, ehA + aoff0);
        ldsm4(al0, elA + aoff0);
        ldsm4(ah1, ehA + aoff1);
        ldsm4(al1, elA + aoff1);
#pragma unroll
        for (int ng = 0; ng < 4; ++ng) {
            unsigned bh[4], bl[4];
            unsigned bo =
                (unsigned)(((k0 + bkrow) * LDD) + aB2 + ng * 16 + bcol) * 2;
            ldsm4t(bh, dhA + bo);
            ldsm4t(bl, dlA + bo);
            float* q0 = &q[(2 * ng) * 4];
            float* q1 = &q[(2 * ng + 1) * 4];
            mma16816(q0, ah0, bh[0], bh[1]);
            mma16816(q0, ah0, bl[0], bl[1]);
            mma16816(q0, al0, bh[0], bh[1]);
            mma16816(q1, ah0, bh[2], bh[3]);
            mma16816(q1, ah0, bl[2], bl[3]);
            mma16816(q1, al0, bh[2], bh[3]);
            float* q2 = &q[32 + (2 * ng) * 4];
            float* q3 = &q[32 + (2 * ng + 1) * 4];
            mma16816(q2, ah1, bh[0], bh[1]);
            mma16816(q2, ah1, bl[0], bl[1]);
            mma16816(q2, al1, bh[0], bh[1]);
            mma16816(q3, ah1, bh[2], bh[3]);
            mma16816(q3, ah1, bl[2], bl[3]);
            mma16816(q3, al1, bh[2], bh[3]);
        }
    }
}

__global__ __launch_bounds__(256, 1) void lista_mma_k(
    const float* __restrict__ x, const float* __restrict__ Dict,
    const float* __restrict__ Lp, const int* __restrict__ nip,
    const float* __restrict__ lam_g, float* __restrict__ out_z,
    float* __restrict__ out_r) {
    extern __shared__ __align__(16) char smem[];
    unsigned short* zh = (unsigned short*)(smem + ZH_OFF);
    unsigned short* zl = (unsigned short*)(smem + ZL_OFF);
    unsigned short* eh = (unsigned short*)(smem + EH_OFF);
    unsigned short* el = (unsigned short*)(smem + EL_OFF);
    unsigned short* dh = (unsigned short*)(smem + DH_OFF);
    unsigned short* dl = (unsigned short*)(smem + DL_OFF);
    float* lam = (float*)(smem + LAM_OFF);
    float* xrec = (float*)(smem + EH_OFF);
    float* zfp = lam;

    int t = threadIdx.x, w = t >> 5, lane = t & 31;
    int mB1 = w & 3, cB1 = (w >> 2) * 32;
    int mB2 = w & 1, aB2 = (w >> 1) * 64;
    int pbase = blockIdx.x * 64;
    int b = pbase >> 12, pl = pbase & 4095;
    float invL = 1.f / Lp[0];
    int niters = nip[0];

    unsigned zhA = (unsigned)__cvta_generic_to_shared(zh);
    unsigned zlA = (unsigned)__cvta_generic_to_shared(zl);
    unsigned ehA = (unsigned)__cvta_generic_to_shared(eh);
    unsigned elA = (unsigned)__cvta_generic_to_shared(el);
    unsigned dhA = (unsigned)__cvta_generic_to_shared(dh);
    unsigned dlA = (unsigned)__cvta_generic_to_shared(dl);

    for (int i = t; i < 16384; i += 256) {
        int m = i >> 8, a = i & 255;
        lam[m * LDL + a] = lam_g[(size_t)(pbase + m) * 256 + a];
    }
    for (int i = t; i < 16384; i += 256) {
        int c = i >> 8, a = i & 255;
        float v = Dict[i];
        unsigned short h = f2b(v);
        dh[c * LDD + a] = h;
        dl[c * LDD + a] = f2b(v - b2f(h));
    }
    size_t xofs = (size_t)b * 64 * 4096 + pl;
    for (int i = t; i < 4096; i += 256) {
        int c = i >> 6, m = i & 63;
        float v = x[xofs + (size_t)c * 4096 + m];
        unsigned short h = f2b(v);
        eh[m * LDE + c] = h;
        el[m * LDE + c] = f2b(v - b2f(h));
    }
    __syncthreads();

    float xfrag[16];
    {
        int r0 = mB1 * 16 + (lane >> 2);
#pragma unroll
        for (int nt = 0; nt < 4; ++nt) {
            int c2 = cB1 + nt * 8 + ((lane & 3) << 1);
            xfrag[nt * 4 + 0] = x[((size_t)b * 64 + c2) * 4096 + pl + r0];
            xfrag[nt * 4 + 1] = x[((size_t)b * 64 + c2 + 1) * 4096 + pl + r0];
            xfrag[nt * 4 + 2] = x[((size_t)b * 64 + c2) * 4096 + pl + r0 + 8];
            xfrag[nt * 4 + 3] = x[((size_t)b * 64 + c2 + 1) * 4096 + pl + r0 + 8];
        }
    }

    {
        float q[64];
        run_step2(q, ehA, elA, dhA, dlA, mB2, aB2, lane);
        bool wz = (niters == 0);
#pragma unroll
        for (int blk = 0; blk < 2; ++blk)
#pragma unroll
            for (int nt = 0; nt < 8; ++nt) {
                int r = mB2 * 32 + blk * 16 + (lane >> 2);
                int a2 = aB2 + nt * 8 + ((lane & 3) << 1);
                const float* qq = &q[blk * 32 + nt * 4];
#pragma unroll
                for (int rr = 0; rr < 2; ++rr) {
                    int row = r + rr * 8;
                    float y0 = qq[rr * 2], y1 = qq[rr * 2 + 1];
                    float l0 = lam[row * LDL + a2], l1 = lam[row * LDL + a2 + 1];
                    float g0 = fmaxf(fabsf(y0) - l0, 0.f);
                    float g1 = fmaxf(fabsf(y1) - l1, 0.f);
                    float z0 = (y0 > 0.f) ? g0 : -g0;
                    float z1 = (y1 > 0.f) ? g1 : -g1;
                    unsigned short h0 = f2b(z0), h1 = f2b(z1);
                    *(unsigned*)&zh[row * LDZ + a2] =
                        (unsigned)h0 | ((unsigned)h1 << 16);
                    *(unsigned*)&zl[row * LDZ + a2] =
                        (unsigned)f2b(z0 - b2f(h0)) |
                        ((unsigned)f2b(z1 - b2f(h1)) << 16);
                    if (wz) {
                        zfp[row * LDL + a2] = z0;
                        zfp[row * LDL + a2 + 1] = z1;
                    }
                }
            }
    }
    __syncthreads();

    for (int it = 0; it < niters; ++it) {
        float R[16];
        run_step1(R, zhA, zlA, dhA, dlA, mB1, cB1, lane);
        {
            int r0 = mB1 * 16 + (lane >> 2);
#pragma unroll
            for (int nt = 0; nt < 4; ++nt) {
                int c2 = cB1 + nt * 8 + ((lane & 3) << 1);
#pragma unroll
                for (int rr = 0; rr < 2; ++rr) {
                    int row = r0 + rr * 8;
                    float e0 = xfrag[nt * 4 + rr * 2] - R[nt * 4 + rr * 2];
                    float e1 = xfrag[nt * 4 + rr * 2 + 1] - R[nt * 4 + rr * 2 + 1];
                    unsigned short h0 = f2b(e0), h1 = f2b(e1);
                    *(unsigned*)&eh[row * LDE + c2] =
                        (unsigned)h0 | ((unsigned)h1 << 16);
                    *(unsigned*)&el[row * LDE + c2] =
                        (unsigned)f2b(e0 - b2f(h0)) |
                        ((unsigned)f2b(e1 - b2f(h1)) << 16);
                }
            }
        }
        __syncthreads();
        float q[64];
        run_step2(q, ehA, elA, dhA, dlA, mB2, aB2, lane);
        bool wz = (it == niters - 1);
#pragma unroll
        for (int blk = 0; blk < 2; ++blk)
#pragma unroll
            for (int nt = 0; nt < 8; ++nt) {
                int r = mB2 * 32 + blk * 16 + (lane >> 2);
                int a2 = aB2 + nt * 8 + ((lane & 3) << 1);
                const float* qq = &q[blk * 32 + nt * 4];
#pragma unroll
                for (int rr = 0; rr < 2; ++rr) {
                    int row = r + rr * 8;
                    unsigned hz = *(unsigned*)&zh[row * LDZ + a2];
                    unsigned lz = *(unsigned*)&zl[row * LDZ + a2];
                    float zo0 = b2f(hz & 0xffffu) + b2f(lz & 0xffffu);
                    float zo1 = b2f(hz >> 16) + b2f(lz >> 16);
                    float w0 = zo0 + qq[rr * 2] * invL;
                    float w1 = zo1 + qq[rr * 2 + 1] * invL;
                    float l0 = lam[row * LDL + a2], l1 = lam[row * LDL + a2 + 1];
                    float g0 = fmaxf(fabsf(w0) - l0, 0.f);
                    float g1 = fmaxf(fabsf(w1) - l1, 0.f);
                    float z0 = (w0 > 0.f) ? g0 : -g0;
                    float z1 = (w1 > 0.f) ? g1 : -g1;
                    unsigned short h0 = f2b(z0), h1 = f2b(z1);
                    *(unsigned*)&zh[row * LDZ + a2] =
                        (unsigned)h0 | ((unsigned)h1 << 16);
                    *(unsigned*)&zl[row * LDZ + a2] =
                        (unsigned)f2b(z0 - b2f(h0)) |
                        ((unsigned)f2b(z1 - b2f(h1)) << 16);
                    if (wz) {
                        zfp[row * LDL + a2] = z0;
                        zfp[row * LDL + a2 + 1] = z1;
                    }
                }
            }
        __syncthreads();
    }

    {
        float R[16];
        run_step1(R, zhA, zlA, dhA, dlA, mB1, cB1, lane);
        __syncthreads();
        int r0 = mB1 * 16 + (lane >> 2);
#pragma unroll
        for (int nt = 0; nt < 4; ++nt) {
            int c2 = cB1 + nt * 8 + ((lane & 3) << 1);
            xrec[r0 * 65 + c2] = R[nt * 4 + 0];
            xrec[r0 * 65 + c2 + 1] = R[nt * 4 + 1];
            xrec[(r0 + 8) * 65 + c2] = R[nt * 4 + 2];
            xrec[(r0 + 8) * 65 + c2 + 1] = R[nt * 4 + 3];
        }
    }
    __syncthreads();

    size_t zofs = (size_t)b * 256 * 4096 + pl;
    for (int i = t; i < 16384; i += 256) {
        int a = i >> 6, m = i & 63;
        out_z[zofs + (size_t)a * 4096 + m] = zfp[m * LDL + a];
    }
    size_t rofs = (size_t)b * 64 * 4096 + pl;
    for (int i = t; i < 4096; i += 256) {
        int c = i >> 6, m = i & 63;
        out_r[rofs + (size_t)c * 4096 + m] = xrec[m * 65 + c];
    }
}

__global__ void copy_k(const float* __restrict__ s, float* __restrict__ d, int n) {
    int i = blockIdx.x * blockDim.x + threadIdx.x;
    if (i < n) d[i] = s[i];
}

extern "C" void kernel_launch(void* const* d_in, const int* in_sizes, int n_in,
                              void* d_out, int out_size) {
    const float* x = (const float*)d_in[0];
    const float* conv_w = (const float*)d_in[1];
    const float* conv_b = (const float*)d_in[2];
    const float* r1w1 = (const float*)d_in[3];
    const float* r1w2 = (const float*)d_in[4];
    const float* r2w1 = (const float*)d_in[5];
    const float* r2w2 = (const float*)d_in[6];
    const float* caw1 = (const float*)d_in[7];
    const float* caw2 = (const float*)d_in[8];
    const float* saw = (const float*)d_in[9];
    const float* Dict = (const float*)d_in[10];
    const float* Lp = (const float*)d_in[11];
    const int* nip = (const int*)d_in[12];
    float* out = (float*)d_out;

    float *l, *tb, *avg, *mx, *sca, *s2m, *s2x, *lam;
    cudaGetSymbolAddress((void**)&l, g_l);
    cudaGetSymbolAddress((void**)&tb, g_t);
    cudaGetSymbolAddress((void**)&avg, g_avg);
    cudaGetSymbolAddress((void**)&mx, g_mx);
    cudaGetSymbolAddress((void**)&sca, g_sca);
    cudaGetSymbolAddress((void**)&s2m, g_s2m);
    cudaGetSymbolAddress((void**)&s2x, g_s2x);
    cudaGetSymbolAddress((void**)&lam, g_lam);

    cudaFuncSetAttribute(conv3x3_mma_k<64, 256, false, true>,
                         cudaFuncAttributeMaxDynamicSharedMemorySize, CONV_SMEM);
    cudaFuncSetAttribute(conv3x3_mma_k<256, 128, true, false>,
                         cudaFuncAttributeMaxDynamicSharedMemorySize, CONV_SMEM);

    conv3x3_mma_k<64, 256, false, true>
        <<<dim3(128, 4), 256, CONV_SMEM>>>(x, conv_w, conv_b, l);
    conv3x3_mma_k<256, 128, true, false>
        <<<dim3(128, 2), 256, CONV_SMEM>>>(l, r1w1, nullptr, tb);
    conv1x1_add_k<<<dim3(64, 16), 256>>>(tb, r1w2, l);
    conv3x3_mma_k<256, 128, true, false>
        <<<dim3(128, 2), 256, CONV_SMEM>>>(l, r2w1, nullptr, tb);
    conv1x1_add_k<<<dim3(64, 16), 256>>>(tb, r2w2, l);
    pool_k<<<2048, 256>>>(l, avg, mx);
    camlp_k<<<1, 256>>>(avg, mx, caw1, caw2, sca);
    chan_k<<<128, 256>>>(l, sca, s2m, s2x);
    lamT_k<<<dim3(1024, 8), dim3(32, 8)>>>(l, s2m, s2x, saw, Lp, lam);

    cudaFuncSetAttribute(lista_mma_k, cudaFuncAttributeMaxDynamicSharedMemorySize,
                         LISTA_SMEM);
    lista_mma_k<<<512, 256, LISTA_SMEM>>>(x, Dict, Lp, nip, lam,
                                          out, out + 8 * 256 * 4096);
    copy_k<<<64, 256>>>(Dict, out + 8 * 256 * 4096 + 8 * 64 * 4096, 64 * 256);
}

// round 17
// speedup vs baseline: 2.8558x; 1.0328x over previous
#include <cuda_runtime.h>
#include <cuda_bf16.h>
#include <cstdint>

__device__ float g_l[8 * 256 * 4096];
__device__ float g_t[8 * 128 * 4096];
__device__ float g_lam[8 * 4096 * 256];
__device__ float g_avg[8 * 256];
__device__ float g_mx[8 * 256];
__device__ float g_sca[8 * 256];
__device__ float g_s2m[8 * 4096];
__device__ float g_s2x[8 * 4096];

__device__ __forceinline__ unsigned long long pk2(float a, float b) {
    unsigned long long r;
    asm("mov.b64 %0, {%1, %2};" : "=l"(r) : "f"(a), "f"(b));
    return r;
}
__device__ __forceinline__ void upk2(unsigned long long v, float& a, float& b) {
    asm("mov.b64 {%0, %1}, %2;" : "=f"(a), "=f"(b) : "l"(v));
}
__device__ __forceinline__ void ffma2(unsigned long long& d, unsigned long long a,
                                      unsigned long long b) {
    asm("fma.rn.f32x2 %0, %1, %2, %0;" : "+l"(d) : "l"(a), "l"(b));
}

__device__ __forceinline__ float b2f(unsigned u) {
    return __uint_as_float(u << 16);
}
__device__ __forceinline__ unsigned short f2b(float f) {
    __nv_bfloat16 h = __float2bfloat16(f);
    return *(unsigned short*)&h;
}
__device__ __forceinline__ void ldsm4(unsigned r[4], unsigned addr) {
    asm volatile("ldmatrix.sync.aligned.m8n8.x4.shared.b16 {%0,%1,%2,%3}, [%4];"
                 : "=r"(r[0]), "=r"(r[1]), "=r"(r[2]), "=r"(r[3])
                 : "r"(addr));
}
__device__ __forceinline__ void ldsm4t(unsigned r[4], unsigned addr) {
    asm volatile(
        "ldmatrix.sync.aligned.m8n8.x4.trans.shared.b16 {%0,%1,%2,%3}, [%4];"
        : "=r"(r[0]), "=r"(r[1]), "=r"(r[2]), "=r"(r[3])
        : "r"(addr));
}
__device__ __forceinline__ void mma16816(float d[4], const unsigned a[4],
                                         unsigned b0, unsigned b1) {
    asm volatile(
        "mma.sync.aligned.m16n8k16.row.col.f32.bf16.bf16.f32 "
        "{%0,%1,%2,%3},{%4,%5,%6,%7},{%8,%9},{%0,%1,%2,%3};"
        : "+f"(d[0]), "+f"(d[1]), "+f"(d[2]), "+f"(d[3])
        : "r"(a[0]), "r"(a[1]), "r"(a[2]), "r"(a[3]), "r"(b0), "r"(b1));
}

// ---------------------------------------------------------------------------
// conv3x3 via mma.sync bf16 hi/lo split (unchanged from R16)
// ---------------------------------------------------------------------------
#define CILD 24
#define CWTAP 1536
#define CONV_IH 0
#define CONV_IL 9792
#define CONV_WH 19584
#define CONV_WL 33408
#define CONV_SMEM 94464

template <int CI, int CO, bool RELU, bool BIAS>
__global__ __launch_bounds__(256, 2) void conv3x3_mma_k(
    const float* __restrict__ in, const float* __restrict__ wt,
    const float* __restrict__ bias, float* __restrict__ out) {
    extern __shared__ __align__(16) unsigned short cs[];
    unsigned short* ih = cs + CONV_IH;
    unsigned short* il = cs + CONV_IL;
    unsigned short* wh = cs + CONV_WH;
    unsigned short* wl = cs + CONV_WL;
    int t = threadIdx.x, w = t >> 5, lane = t & 31;
    int b = blockIdx.x >> 4, rb = blockIdx.x & 15, r0 = rb * 4;
    int coB = blockIdx.y * 64;
    int wmB = w * 32;

    unsigned ihA = (unsigned)__cvta_generic_to_shared(ih);
    unsigned ilA = (unsigned)__cvta_generic_to_shared(il);
    unsigned whA = (unsigned)__cvta_generic_to_shared(wh);
    unsigned wlA = (unsigned)__cvta_generic_to_shared(wl);

    for (int i = t; i < 9792; i += 256) ((unsigned*)cs)[i] = 0u;

    float acc[2][32];
#pragma unroll
    for (int mb = 0; mb < 2; ++mb)
#pragma unroll
        for (int i = 0; i < 32; ++i) acc[mb][i] = 0.f;

#pragma unroll 1
    for (int cc = 0; cc < CI / 16; ++cc) {
        __syncthreads();
#pragma unroll 1
        for (int it = 0; it < 12; it += 6) {
            float u0[6], u1[6];
            int idx[6];
#pragma unroll
            for (int j = 0; j < 6; ++j) {
                int p = t + (it + j) * 256;
                int cell = p >> 3, cp = p & 7;
                int row = cell >> 6, col = cell & 63;
                int ci0 = cp * 2;
                int imgrow = r0 - 1 + row;
                float a = 0.f, bb = 0.f;
                if ((unsigned)imgrow < 64u) {
                    const float* ip = in + ((size_t)b * CI + cc * 16 + ci0) * 4096 +
                                      imgrow * 64 + col;
                    a = ip[0];
                    bb = ip[4096];
                }
                u0[j] = RELU ? fmaxf(a, 0.f) : a;
                u1[j] = RELU ? fmaxf(bb, 0.f) : bb;
                idx[j] = (row * 68 + col + 1) * CILD + ci0;
            }
#pragma unroll
            for (int j = 0; j < 6; ++j) {
                unsigned short h0 = f2b(u0[j]), h1 = f2b(u1[j]);
                *(unsigned*)&ih[idx[j]] = (unsigned)h0 | ((unsigned)h1 << 16);
                unsigned short l0 = f2b(u0[j] - b2f(h0));
                unsigned short l1 = f2b(u1[j] - b2f(h1));
                *(unsigned*)&il[idx[j]] = (unsigned)l0 | ((unsigned)l1 << 16);
            }
        }
#pragma unroll 1
        for (int it = 0; it < 18; it += 6) {
            float u0[6], u1[6];
            int idx[6];
#pragma unroll
            for (int j = 0; j < 6; ++j) {
                int p = t + (it + j) * 256;
                int co = p / 72, rem = p - co * 72;
                int tap = rem >> 3, cp = rem & 7;
                int ci0 = cp * 2;
                const float* wp = wt + (size_t)(coB + co) * (CI * 9) +
                                  (size_t)(cc * 16 + ci0) * 9 + tap;
                u0[j] = wp[0];
                u1[j] = wp[9];
                idx[j] = tap * CWTAP + co * CILD + ci0;
            }
#pragma unroll
            for (int j = 0; j < 6; ++j) {
                unsigned short h0 = f2b(u0[j]), h1 = f2b(u1[j]);
                *(unsigned*)&wh[idx[j]] = (unsigned)h0 | ((unsigned)h1 << 16);
                unsigned short l0 = f2b(u0[j] - b2f(h0));
                unsigned short l1 = f2b(u1[j] - b2f(h1));
                *(unsigned*)&wl[idx[j]] = (unsigned)l0 | ((unsigned)l1 << 16);
            }
        }
        __syncthreads();

#pragma unroll 1
        for (int tap = 0; tap < 9; ++tap) {
            int dh = tap / 3, dw = tap - dh * 3;
            unsigned ah[2][4], al[2][4];
#pragma unroll
            for (int mb = 0; mb < 2; ++mb) {
                int p = wmB + mb * 16 + (lane & 15);
                int trow = (p >> 6) + dh;
                int tcol = (p & 63) + dw;
                unsigned aoff =
                    (unsigned)((trow * 68 + tcol) * CILD + ((lane >> 4) << 3)) * 2;
                ldsm4(ah[mb], ihA + aoff);
                ldsm4(al[mb], ilA + aoff);
            }
            int brow_b = (lane & 7) + (((lane >> 4) & 1) << 3);
            unsigned bbase =
                (unsigned)(tap * CWTAP + brow_b * CILD + (((lane >> 3) & 1) << 3)) *
                2;
#pragma unroll
            for (int nt2 = 0; nt2 < 4; ++nt2) {
                unsigned bh[4], bl[4];
                unsigned bo = bbase + (unsigned)(nt2 * 16 * CILD * 2);
                ldsm4(bh, whA + bo);
                ldsm4(bl, wlA + bo);
#pragma unroll
                for (int mb = 0; mb < 2; ++mb) {
                    float* a0 = &acc[mb][nt2 * 8];
                    mma16816(&a0[0], ah[mb], bh[0], bh[1]);
                    mma16816(&a0[0], ah[mb], bl[0], bl[1]);
                    mma16816(&a0[0], al[mb], bh[0], bh[1]);
                    mma16816(&a0[4], ah[mb], bh[2], bh[3]);
                    mma16816(&a0[4], ah[mb], bl[2], bl[3]);
                    mma16816(&a0[4], al[mb], bh[2], bh[3]);
                }
            }
        }
    }

    size_t ob = (size_t)b * CO * 4096;
#pragma unroll
    for (int mb = 0; mb < 2; ++mb) {
        int p0 = wmB + mb * 16 + (lane >> 2);
#pragma unroll
        for (int nt = 0; nt < 8; ++nt) {
            int n = coB + nt * 8 + ((lane & 3) << 1);
            float bs0 = BIAS ? bias[n] : 0.f;
            float bs1 = BIAS ? bias[n + 1] : 0.f;
#pragma unroll
            for (int rr = 0; rr < 2; ++rr) {
                int p = p0 + rr * 8;
                int orow = r0 + (p >> 6), ocol = p & 63;
                out[ob + (size_t)n * 4096 + orow * 64 + ocol] =
                    acc[mb][nt * 4 + rr * 2] + bs0;
                out[ob + (size_t)(n + 1) * 4096 + orow * 64 + ocol] =
                    acc[mb][nt * 4 + rr * 2 + 1] + bs1;
            }
        }
    }
}

// 1x1 conv (relu(t)@w2) + residual add (unchanged)
__global__ __launch_bounds__(256) void conv1x1_add_k(const float* __restrict__ tin,
                                                     const float* __restrict__ wt,
                                                     float* __restrict__ lio) {
    __shared__ __align__(16) float wsh[128 * 16];
    int tid = threadIdx.x;
    int p0 = blockIdx.x * 512 + 2 * tid;
    int b = p0 >> 12, hw = p0 & 4095;
    int coBase = blockIdx.y * 16;
    for (int i = tid; i < 2048; i += 256) {
        int o = i >> 7, ci = i & 127;
        wsh[ci * 16 + o] = wt[(size_t)(coBase + o) * 128 + ci];
    }
    __syncthreads();
    unsigned long long acc2[16];
    size_t lb = ((size_t)b * 256 + coBase) * 4096 + hw;
#pragma unroll
    for (int q = 0; q < 8; ++q) {
        float2 v = *(const float2*)&lio[lb + (size_t)(2 * q) * 4096];
        float2 u = *(const float2*)&lio[lb + (size_t)(2 * q + 1) * 4096];
        acc2[2 * q] = pk2(v.x, u.x);
        acc2[2 * q + 1] = pk2(v.y, u.y);
    }
    const float* tb = tin + (size_t)b * 128 * 4096 + hw;
#pragma unroll 1
    for (int ci = 0; ci < 128; ci += 8) {
        float2 v[8];
#pragma unroll
        for (int j = 0; j < 8; ++j) {
            float2 u = *(const float2*)&tb[(size_t)(ci + j) * 4096];
            v[j].x = fmaxf(u.x, 0.f);
            v[j].y = fmaxf(u.y, 0.f);
        }
#pragma unroll
        for (int j = 0; j < 8; ++j) {
            unsigned long long v0 = pk2(v[j].x, v[j].x);
            unsigned long long v1 = pk2(v[j].y, v[j].y);
            const ulonglong2* wp = (const ulonglong2*)&wsh[(ci + j) * 16];
#pragma unroll
            for (int q = 0; q < 4; ++q) {
                ulonglong2 wq = wp[q];
                ffma2(acc2[4 * q], wq.x, v0);
                ffma2(acc2[4 * q + 1], wq.x, v1);
                ffma2(acc2[4 * q + 2], wq.y, v0);
                ffma2(acc2[4 * q + 3], wq.y, v1);
            }
        }
    }
#pragma unroll
    for (int q = 0; q < 8; ++q) {
        float a0, a1, b0_, b1_;
        upk2(acc2[2 * q], a0, b0_);
        upk2(acc2[2 * q + 1], a1, b1_);
        float2 o0 = {a0, a1}, o1 = {b0_, b1_};
        *(float2*)&lio[lb + (size_t)(2 * q) * 4096] = o0;
        *(float2*)&lio[lb + (size_t)(2 * q + 1) * 4096] = o1;
    }
}

__global__ __launch_bounds__(256) void pool_k(const float* __restrict__ l,
                                              float* __restrict__ avg,
                                              float* __restrict__ mx) {
    __shared__ float ss[256], sm[256];
    int bc = blockIdx.x, t = threadIdx.x;
    const float4* p = (const float4*)(l + (size_t)bc * 4096);
    float s = 0.f, m = -3.4e38f;
    for (int i = t; i < 1024; i += 256) {
        float4 v = p[i];
        s += v.x + v.y + v.z + v.w;
        m = fmaxf(m, fmaxf(fmaxf(v.x, v.y), fmaxf(v.z, v.w)));
    }
    ss[t] = s;
    sm[t] = m;
    __syncthreads();
    for (int st = 128; st > 0; st >>= 1) {
        if (t < st) {
            ss[t] += ss[t + st];
            sm[t] = fmaxf(sm[t], sm[t + st]);
        }
        __syncthreads();
    }
    if (t == 0) {
        avg[bc] = ss[0] * (1.f / 4096.f);
        mx[bc] = sm[0];
    }
}

__global__ void camlp_k(const float* __restrict__ avg, const float* __restrict__ mx,
                        const float* __restrict__ w1, const float* __restrict__ w2,
                        float* __restrict__ sca) {
    __shared__ float hsh[128];
    int t = threadIdx.x;
    if (t < 128) {
        int b = t >> 4, j = t & 15;
        float a = 0.f, m = 0.f;
        for (int c = 0; c < 256; ++c) {
            float w = w1[j * 256 + c];
            a += avg[b * 256 + c] * w;
            m += mx[b * 256 + c] * w;
        }
        hsh[b * 16 + j] = fmaxf(a, 0.f) + fmaxf(m, 0.f);
    }
    __syncthreads();
    for (int b = 0; b < 8; ++b) {
        float o = 0.f;
#pragma unroll
        for (int j = 0; j < 16; ++j) o += hsh[b * 16 + j] * w2[t * 16 + j];
        sca[b * 256 + t] = 1.f / (1.f + expf(-o));
    }
}

__global__ __launch_bounds__(256) void chan_k(float* __restrict__ l,
                                              const float* __restrict__ sca,
                                              float* __restrict__ s2m,
                                              float* __restrict__ s2x) {
    int p = blockIdx.x * 256 + threadIdx.x;
    int b = p >> 12, hw = p & 4095;
    size_t base = (size_t)b * 256 * 4096 + hw;
    float s = 0.f, m = -3.4e38f;
#pragma unroll 1
    for (int c = 0; c < 256; c += 8) {
        float v[8];
#pragma unroll
        for (int j = 0; j < 8; ++j)
            v[j] = l[base + (size_t)(c + j) * 4096] * sca[b * 256 + c + j];
#pragma unroll
        for (int j = 0; j < 8; ++j) {
            l[base + (size_t)(c + j) * 4096] = v[j];
            s += v[j];
            m = fmaxf(m, v[j]);
        }
    }
    s2m[p] = s * (1.f / 256.f);
    s2x[p] = m;
}

__global__ void lamT_k(const float* __restrict__ l, const float* __restrict__ s2m,
                       const float* __restrict__ s2x, const float* __restrict__ sw,
                       const float* __restrict__ Lp, float* __restrict__ lam) {
    __shared__ float tile[32][33];
    __shared__ float satts[32];
    int pb = blockIdx.x * 32, cb = blockIdx.y * 32;
    int tx = threadIdx.x, ty = threadIdx.y;
    int b = pb >> 12, pl = pb & 4095;
#pragma unroll
    for (int k = 0; k < 4; ++k) {
        int c = cb + ty + 8 * k;
        tile[ty + 8 * k][tx] = l[((size_t)b * 256 + c) * 4096 + pl + tx];
    }
    if (ty == 0) {
        int p2 = pb + tx;
        int hw = p2 & 4095, h = hw >> 6, w2 = hw & 63;
        float a = 0.f;
#pragma unroll
        for (int kh = 0; kh < 3; ++kh) {
            int hh = h + kh - 1;
            if ((unsigned)hh >= 64u) continue;
#pragma unroll
            for (int kw = 0; kw < 3; ++kw) {
                int ww = w2 + kw - 1;
                if ((unsigned)ww >= 64u) continue;
                int q = b * 4096 + hh * 64 + ww;
                a += s2m[q] * sw[kh * 3 + kw] + s2x[q] * sw[9 + kh * 3 + kw];
            }
        }
        satts[tx] = 1.f / (1.f + expf(-a));
    }
    __syncthreads();
    float invL = 1.f / Lp[0];
#pragma unroll
    for (int k = 0; k < 4; ++k) {
        int p2 = pb + ty + 8 * k;
        float sc = satts[ty + 8 * k] * invL;
        lam[(size_t)p2 * 256 + cb + tx] = tile[tx][ty + 8 * k] * sc;
    }
}

// ---------------------------------------------------------------------------
// LISTA via mma.sync bf16 (hi/lo split); 512 threads (16 warps), 64 px/CTA
// ---------------------------------------------------------------------------
#define ZH_OFF 0
#define ZL_OFF 33792
#define EH_OFF 67584
#define EL_OFF 76800
#define DH_OFF 86016
#define DL_OFF 119808
#define LAM_OFF 153600
#define LISTA_SMEM 220416
#define LDZ 264
#define LDE 72
#define LDD 264
#define LDL 261

// step1: R[16m x 16c] per warp; warp w: mB1=(w&3)*16, cB1=(w>>2)*16
__device__ __forceinline__ void run_step1(float R[8], unsigned zhA, unsigned zlA,
                                          unsigned dhA, unsigned dlA, int mB1,
                                          int cB1, int lane) {
#pragma unroll
    for (int i = 0; i < 8; ++i) R[i] = 0.f;
    int arow = mB1 + (lane & 15);
    int acolg = (lane >> 4) << 3;
    int brow0 = cB1 + (lane & 7) + (((lane >> 4) & 1) << 3);
    int bcolg = (((lane >> 3) & 1) << 3);
#pragma unroll 4
    for (int ks = 0; ks < 16; ++ks) {
        int k0 = ks * 16;
        unsigned ah[4], al[4], bh0[4], bl0[4];
        unsigned aoff = (unsigned)((arow * LDZ + k0 + acolg) * 2);
        ldsm4(ah, zhA + aoff);
        ldsm4(al, zlA + aoff);
        unsigned boff0 = (unsigned)((brow0 * LDD + k0 + bcolg) * 2);
        ldsm4(bh0, dhA + boff0);
        ldsm4(bl0, dlA + boff0);
        mma16816(&R[0], ah, bh0[0], bh0[1]);
        mma16816(&R[0], ah, bl0[0], bl0[1]);
        mma16816(&R[0], al, bh0[0], bh0[1]);
        mma16816(&R[4], ah, bh0[2], bh0[3]);
        mma16816(&R[4], ah, bl0[2], bl0[3]);
        mma16816(&R[4], al, bh0[2], bh0[3]);
    }
}

// step2: Q[32m x 32a] per warp; warp w: mB2=(w&1)*32, aB2=(w>>1)*32
__device__ __forceinline__ void run_step2(float q[32], unsigned ehA, unsigned elA,
                                          unsigned dhA, unsigned dlA, int mB2,
                                          int aB2, int lane) {
#pragma unroll
    for (int i = 0; i < 32; ++i) q[i] = 0.f;
    int arow = mB2 + (lane & 15);
    int acolg = (lane >> 4) << 3;
    int bkrow = (lane & 7) + (((lane >> 3) & 1) << 3);
    int bcol = (lane >> 4) << 3;
#pragma unroll
    for (int ks = 0; ks < 4; ++ks) {
        int k0 = ks * 16;
        unsigned ah0[4], al0[4], ah1[4], al1[4];
        unsigned aoff0 = (unsigned)((arow * LDE + k0 + acolg) * 2);
        unsigned aoff1 = (unsigned)(((arow + 16) * LDE + k0 + acolg) * 2);
        ldsm4(ah0, ehA + aoff0);
        ldsm4(al0, elA + aoff0);
        ldsm4(ah1, ehA + aoff1);
        ldsm4(al1, elA + aoff1);
#pragma unroll
        for (int ng = 0; ng < 2; ++ng) {
            unsigned bh[4], bl[4];
            unsigned bo =
                (unsigned)(((k0 + bkrow) * LDD) + aB2 + ng * 16 + bcol) * 2;
            ldsm4t(bh, dhA + bo);
            ldsm4t(bl, dlA + bo);
            float* q0 = &q[(2 * ng) * 4];
            float* q1 = &q[(2 * ng + 1) * 4];
            mma16816(q0, ah0, bh[0], bh[1]);
            mma16816(q0, ah0, bl[0], bl[1]);
            mma16816(q0, al0, bh[0], bh[1]);
            mma16816(q1, ah0, bh[2], bh[3]);
            mma16816(q1, ah0, bl[2], bl[3]);
            mma16816(q1, al0, bh[2], bh[3]);
            float* q2 = &q[16 + (2 * ng) * 4];
            float* q3 = &q[16 + (2 * ng + 1) * 4];
            mma16816(q2, ah1, bh[0], bh[1]);
            mma16816(q2, ah1, bl[0], bl[1]);
            mma16816(q2, al1, bh[0], bh[1]);
            mma16816(q3, ah1, bh[2], bh[3]);
            mma16816(q3, ah1, bl[2], bl[3]);
            mma16816(q3, al1, bh[2], bh[3]);
        }
    }
}

__global__ __launch_bounds__(512, 1) void lista_mma_k(
    const float* __restrict__ x, const float* __restrict__ Dict,
    const float* __restrict__ Lp, const int* __restrict__ nip,
    const float* __restrict__ lam_g, float* __restrict__ out_z,
    float* __restrict__ out_r) {
    extern __shared__ __align__(16) char smem[];
    unsigned short* zh = (unsigned short*)(smem + ZH_OFF);
    unsigned short* zl = (unsigned short*)(smem + ZL_OFF);
    unsigned short* eh = (unsigned short*)(smem + EH_OFF);
    unsigned short* el = (unsigned short*)(smem + EL_OFF);
    unsigned short* dh = (unsigned short*)(smem + DH_OFF);
    unsigned short* dl = (unsigned short*)(smem + DL_OFF);
    float* lam = (float*)(smem + LAM_OFF);
    float* xrec = (float*)(smem + EH_OFF);
    float* zfp = lam;

    int t = threadIdx.x, w = t >> 5, lane = t & 31;
    int mB1 = (w & 3) * 16, cB1 = (w >> 2) * 16;
    int mB2 = (w & 1) * 32, aB2 = (w >> 1) * 32;
    int pbase = blockIdx.x * 64;
    int b = pbase >> 12, pl = pbase & 4095;
    float invL = 1.f / Lp[0];
    int niters = nip[0];

    unsigned zhA = (unsigned)__cvta_generic_to_shared(zh);
    unsigned zlA = (unsigned)__cvta_generic_to_shared(zl);
    unsigned ehA = (unsigned)__cvta_generic_to_shared(eh);
    unsigned elA = (unsigned)__cvta_generic_to_shared(el);
    unsigned dhA = (unsigned)__cvta_generic_to_shared(dh);
    unsigned dlA = (unsigned)__cvta_generic_to_shared(dl);

    for (int i = t; i < 16384; i += 512) {
        int m = i >> 8, a = i & 255;
        lam[m * LDL + a] = lam_g[(size_t)(pbase + m) * 256 + a];
    }
    for (int i = t; i < 16384; i += 512) {
        int c = i >> 8, a = i & 255;
        float v = Dict[i];
        unsigned short h = f2b(v);
        dh[c * LDD + a] = h;
        dl[c * LDD + a] = f2b(v - b2f(h));
    }
    size_t xofs = (size_t)b * 64 * 4096 + pl;
    for (int i = t; i < 4096; i += 512) {
        int c = i >> 6, m = i & 63;
        float v = x[xofs + (size_t)c * 4096 + m];
        unsigned short h = f2b(v);
        eh[m * LDE + c] = h;
        el[m * LDE + c] = f2b(v - b2f(h));
    }
    __syncthreads();

    // x at this warp's step1 fragment positions (16m x 16c tile)
    float xfrag[8];
    {
        int r0 = mB1 + (lane >> 2);
#pragma unroll
        for (int nt = 0; nt < 2; ++nt) {
            int c2 = cB1 + nt * 8 + ((lane & 3) << 1);
            xfrag[nt * 4 + 0] = x[((size_t)b * 64 + c2) * 4096 + pl + r0];
            xfrag[nt * 4 + 1] = x[((size_t)b * 64 + c2 + 1) * 4096 + pl + r0];
            xfrag[nt * 4 + 2] = x[((size_t)b * 64 + c2) * 4096 + pl + r0 + 8];
            xfrag[nt * 4 + 3] = x[((size_t)b * 64 + c2 + 1) * 4096 + pl + r0 + 8];
        }
    }

    {
        float q[32];
        run_step2(q, ehA, elA, dhA, dlA, mB2, aB2, lane);
        bool wz = (niters == 0);
#pragma unroll
        for (int blk = 0; blk < 2; ++blk)
#pragma unroll
            for (int nt = 0; nt < 4; ++nt) {
                int r = mB2 + blk * 16 + (lane >> 2);
                int a2 = aB2 + nt * 8 + ((lane & 3) << 1);
                const float* qq = &q[blk * 16 + nt * 4];
#pragma unroll
                for (int rr = 0; rr < 2; ++rr) {
                    int row = r + rr * 8;
                    float y0 = qq[rr * 2], y1 = qq[rr * 2 + 1];
                    float l0 = lam[row * LDL + a2], l1 = lam[row * LDL + a2 + 1];
                    float g0 = fmaxf(fabsf(y0) - l0, 0.f);
                    float g1 = fmaxf(fabsf(y1) - l1, 0.f);
                    float z0 = (y0 > 0.f) ? g0 : -g0;
                    float z1 = (y1 > 0.f) ? g1 : -g1;
                    unsigned short h0 = f2b(z0), h1 = f2b(z1);
                    *(unsigned*)&zh[row * LDZ + a2] =
                        (unsigned)h0 | ((unsigned)h1 << 16);
                    *(unsigned*)&zl[row * LDZ + a2] =
                        (unsigned)f2b(z0 - b2f(h0)) |
                        ((unsigned)f2b(z1 - b2f(h1)) << 16);
                    if (wz) {
                        zfp[row * LDL + a2] = z0;
                        zfp[row * LDL + a2 + 1] = z1;
                    }
                }
            }
    }
    __syncthreads();

    for (int it = 0; it < niters; ++it) {
        float R[8];
        run_step1(R, zhA, zlA, dhA, dlA, mB1, cB1, lane);
        {
            int r0 = mB1 + (lane >> 2);
#pragma unroll
            for (int nt = 0; nt < 2; ++nt) {
                int c2 = cB1 + nt * 8 + ((lane & 3) << 1);
#pragma unroll
                for (int rr = 0; rr < 2; ++rr) {
                    int row = r0 + rr * 8;
                    float e0 = xfrag[nt * 4 + rr * 2] - R[nt * 4 + rr * 2];
                    float e1 = xfrag[nt * 4 + rr * 2 + 1] - R[nt * 4 + rr * 2 + 1];
                    unsigned short h0 = f2b(e0), h1 = f2b(e1);
                    *(unsigned*)&eh[row * LDE + c2] =
                        (unsigned)h0 | ((unsigned)h1 << 16);
                    *(unsigned*)&el[row * LDE + c2] =
                        (unsigned)f2b(e0 - b2f(h0)) |
                        ((unsigned)f2b(e1 - b2f(h1)) << 16);
                }
            }
        }
        __syncthreads();
        float q[32];
        run_step2(q, ehA, elA, dhA, dlA, mB2, aB2, lane);
        bool wz = (it == niters - 1);
#pragma unroll
        for (int blk = 0; blk < 2; ++blk)
#pragma unroll
            for (int nt = 0; nt < 4; ++nt) {
                int r = mB2 + blk * 16 + (lane >> 2);
                int a2 = aB2 + nt * 8 + ((lane & 3) << 1);
                const float* qq = &q[blk * 16 + nt * 4];
#pragma unroll
                for (int rr = 0; rr < 2; ++rr) {
                    int row = r + rr * 8;
                    unsigned hz = *(unsigned*)&zh[row * LDZ + a2];
                    unsigned lz = *(unsigned*)&zl[row * LDZ + a2];
                    float zo0 = b2f(hz & 0xffffu) + b2f(lz & 0xffffu);
                    float zo1 = b2f(hz >> 16) + b2f(lz >> 16);
                    float w0 = zo0 + qq[rr * 2] * invL;
                    float w1 = zo1 + qq[rr * 2 + 1] * invL;
                    float l0 = lam[row * LDL + a2], l1 = lam[row * LDL + a2 + 1];
                    float g0 = fmaxf(fabsf(w0) - l0, 0.f);
                    float g1 = fmaxf(fabsf(w1) - l1, 0.f);
                    float z0 = (w0 > 0.f) ? g0 : -g0;
                    float z1 = (w1 > 0.f) ? g1 : -g1;
                    unsigned short h0 = f2b(z0), h1 = f2b(z1);
                    *(unsigned*)&zh[row * LDZ + a2] =
                        (unsigned)h0 | ((unsigned)h1 << 16);
                    *(unsigned*)&zl[row * LDZ + a2] =
                        (unsigned)f2b(z0 - b2f(h0)) |
                        ((unsigned)f2b(z1 - b2f(h1)) << 16);
                    if (wz) {
                        zfp[row * LDL + a2] = z0;
                        zfp[row * LDL + a2 + 1] = z1;
                    }
                }
            }
        __syncthreads();
    }

    {
        float R[8];
        run_step1(R, zhA, zlA, dhA, dlA, mB1, cB1, lane);
        __syncthreads();
        int r0 = mB1 + (lane >> 2);
#pragma unroll
        for (int nt = 0; nt < 2; ++nt) {
            int c2 = cB1 + nt * 8 + ((lane & 3) << 1);
            xrec[r0 * 65 + c2] = R[nt * 4 + 0];
            xrec[r0 * 65 + c2 + 1] = R[nt * 4 + 1];
            xrec[(r0 + 8) * 65 + c2] = R[nt * 4 + 2];
            xrec[(r0 + 8) * 65 + c2 + 1] = R[nt * 4 + 3];
        }
    }
    __syncthreads();

    size_t zofs = (size_t)b * 256 * 4096 + pl;
    for (int i = t; i < 16384; i += 512) {
        int a = i >> 6, m = i & 63;
        out_z[zofs + (size_t)a * 4096 + m] = zfp[m * LDL + a];
    }
    size_t rofs = (size_t)b * 64 * 4096 + pl;
    for (int i = t; i < 4096; i += 512) {
        int c = i >> 6, m = i & 63;
        out_r[rofs + (size_t)c * 4096 + m] = xrec[m * 65 + c];
    }
}

__global__ void copy_k(const float* __restrict__ s, float* __restrict__ d, int n) {
    int i = blockIdx.x * blockDim.x + threadIdx.x;
    if (i < n) d[i] = s[i];
}

extern "C" void kernel_launch(void* const* d_in, const int* in_sizes, int n_in,
                              void* d_out, int out_size) {
    const float* x = (const float*)d_in[0];
    const float* conv_w = (const float*)d_in[1];
    const float* conv_b = (const float*)d_in[2];
    const float* r1w1 = (const float*)d_in[3];
    const float* r1w2 = (const float*)d_in[4];
    const float* r2w1 = (const float*)d_in[5];
    const float* r2w2 = (const float*)d_in[6];
    const float* caw1 = (const float*)d_in[7];
    const float* caw2 = (const float*)d_in[8];
    const float* saw = (const float*)d_in[9];
    const float* Dict = (const float*)d_in[10];
    const float* Lp = (const float*)d_in[11];
    const int* nip = (const int*)d_in[12];
    float* out = (float*)d_out;

    float *l, *tb, *avg, *mx, *sca, *s2m, *s2x, *lam;
    cudaGetSymbolAddress((void**)&l, g_l);
    cudaGetSymbolAddress((void**)&tb, g_t);
    cudaGetSymbolAddress((void**)&avg, g_avg);
    cudaGetSymbolAddress((void**)&mx, g_mx);
    cudaGetSymbolAddress((void**)&sca, g_sca);
    cudaGetSymbolAddress((void**)&s2m, g_s2m);
    cudaGetSymbolAddress((void**)&s2x, g_s2x);
    cudaGetSymbolAddress((void**)&lam, g_lam);

    cudaFuncSetAttribute(conv3x3_mma_k<64, 256, false, true>,
                         cudaFuncAttributeMaxDynamicSharedMemorySize, CONV_SMEM);
    cudaFuncSetAttribute(conv3x3_mma_k<256, 128, true, false>,
                         cudaFuncAttributeMaxDynamicSharedMemorySize, CONV_SMEM);

    conv3x3_mma_k<64, 256, false, true>
        <<<dim3(128, 4), 256, CONV_SMEM>>>(x, conv_w, conv_b, l);
    conv3x3_mma_k<256, 128, true, false>
        <<<dim3(128, 2), 256, CONV_SMEM>>>(l, r1w1, nullptr, tb);
    conv1x1_add_k<<<dim3(64, 16), 256>>>(tb, r1w2, l);
    conv3x3_mma_k<256, 128, true, false>
        <<<dim3(128, 2), 256, CONV_SMEM>>>(l, r2w1, nullptr, tb);
    conv1x1_add_k<<<dim3(64, 16), 256>>>(tb, r2w2, l);
    pool_k<<<2048, 256>>>(l, avg, mx);
    camlp_k<<<1, 256>>>(avg, mx, caw1, caw2, sca);
    chan_k<<<128, 256>>>(l, sca, s2m, s2x);
    lamT_k<<<dim3(1024, 8), dim3(32, 8)>>>(l, s2m, s2x, saw, Lp, lam);

    cudaFuncSetAttribute(lista_mma_k, cudaFuncAttributeMaxDynamicSharedMemorySize,
                         LISTA_SMEM);
    lista_mma_k<<<512, 512, LISTA_SMEM>>>(x, Dict, Lp, nip, lam,
                                          out, out + 8 * 256 * 4096);
    copy_k<<<64, 256>>>(Dict, out + 8 * 256 * 4096 + 8 * 64 * 4096, 64 * 256);
}